// round 1
// baseline (speedup 1.0000x reference)
#include <cuda_runtime.h>
#include <cuda_bf16.h>
#include <math.h>

// ---------------------------------------------------------------------------
// Problem constants
// ---------------------------------------------------------------------------
#define BATCH     2
#define SEQ       4096
#define ROWS      (BATCH * SEQ)          // 8192 tokens
#define D_MODEL   1024
#define STATE     128
#define CONVW     4
#define HEADDIM   64
#define D_INNER   2048
#define NHEADS    32
#define CONV_DIM  (D_INNER + 2 * STATE)  // 2304
#define D_IN_PROJ (2 * D_INNER + 2 * STATE + NHEADS) // 4384
#define MLP_INNER 4096
#define EPS       1e-5f

// ---------------------------------------------------------------------------
// Scratch (static device arrays; no runtime allocation allowed)
// ---------------------------------------------------------------------------
__device__ float g_res1  [(size_t)ROWS * D_MODEL];
__device__ float g_norm  [(size_t)ROWS * D_MODEL];
__device__ float g_zx    [(size_t)ROWS * D_IN_PROJ];
__device__ float g_conv  [(size_t)ROWS * CONV_DIM];
__device__ float g_y     [(size_t)ROWS * D_INNER];
__device__ float g_h2    [(size_t)ROWS * D_MODEL];
__device__ float g_gate  [(size_t)ROWS * MLP_INNER];
__device__ float g_up    [(size_t)ROWS * MLP_INNER];

// ---------------------------------------------------------------------------
// Fused residual-add + RMSNorm (prenorm=True)
//   res_out = x + res_in ; norm_out = res_out * rsqrt(mean(res^2)+eps) * w
// One block per row of 1024, 256 threads, float4.
// ---------------------------------------------------------------------------
__global__ __launch_bounds__(256) void rmsnorm_prenorm_kernel(
    const float* __restrict__ x, const float* __restrict__ res_in,
    const float* __restrict__ w, float* __restrict__ res_out,
    float* __restrict__ norm_out)
{
    const long row = blockIdx.x;
    const int tid = threadIdx.x;
    const float4 xv = ((const float4*)(x      + row * D_MODEL))[tid];
    const float4 rv = ((const float4*)(res_in + row * D_MODEL))[tid];
    float4 s;
    s.x = xv.x + rv.x; s.y = xv.y + rv.y; s.z = xv.z + rv.z; s.w = xv.w + rv.w;
    float ss = s.x * s.x + s.y * s.y + s.z * s.z + s.w * s.w;

    #pragma unroll
    for (int o = 16; o > 0; o >>= 1) ss += __shfl_down_sync(0xffffffffu, ss, o);
    __shared__ float red[8];
    __shared__ float scale_sh;
    if ((tid & 31) == 0) red[tid >> 5] = ss;
    __syncthreads();
    if (tid == 0) {
        float t = 0.f;
        #pragma unroll
        for (int i = 0; i < 8; i++) t += red[i];
        scale_sh = rsqrtf(t / (float)D_MODEL + EPS);
    }
    __syncthreads();
    const float scale = scale_sh;

    ((float4*)(res_out + row * D_MODEL))[tid] = s;
    const float4 wv = ((const float4*)w)[tid];
    float4 o;
    o.x = s.x * scale * wv.x; o.y = s.y * scale * wv.y;
    o.z = s.z * scale * wv.z; o.w = s.w * scale * wv.w;
    ((float4*)(norm_out + row * D_MODEL))[tid] = o;
}

// ---------------------------------------------------------------------------
// SGEMM: C[M,N] = A[M,K] @ W[N,K]^T  (both operands K-contiguous, row-major)
// 128x128 block tile, BK=8, 256 threads, 8x8 per-thread micro-tile.
// M and K divisible by 128/8 respectively in every call; N guarded.
// ---------------------------------------------------------------------------
__global__ __launch_bounds__(256, 2) void sgemm_nt(
    const float* __restrict__ A, const float* __restrict__ W,
    float* __restrict__ C, int M, int N, int K)
{
    __shared__ float As[8][128];
    __shared__ float Bs[8][128];

    const int bm = blockIdx.y * 128;
    const int bn = blockIdx.x * 128;
    const int tid = threadIdx.x;
    const int tx = tid & 15;       // 0..15 -> n
    const int ty = tid >> 4;       // 0..15 -> m

    const int lr = tid >> 1;              // 0..127 row within tile
    const int lk = (tid & 1) * 4;         // 0 or 4

    const float* Aptr = A + (long)(bm + lr) * K + lk;
    const int wrow = bn + lr;
    const bool wvalid = (wrow < N);
    const float* Wptr = W + (long)(wvalid ? wrow : 0) * K + lk;

    float acc[8][8];
    #pragma unroll
    for (int i = 0; i < 8; i++)
        #pragma unroll
        for (int j = 0; j < 8; j++) acc[i][j] = 0.f;

    for (int k0 = 0; k0 < K; k0 += 8) {
        const float4 av = *(const float4*)(Aptr + k0);
        const float4 wv = wvalid ? *(const float4*)(Wptr + k0)
                                 : make_float4(0.f, 0.f, 0.f, 0.f);
        __syncthreads();
        As[lk + 0][lr] = av.x; As[lk + 1][lr] = av.y;
        As[lk + 2][lr] = av.z; As[lk + 3][lr] = av.w;
        Bs[lk + 0][lr] = wv.x; Bs[lk + 1][lr] = wv.y;
        Bs[lk + 2][lr] = wv.z; Bs[lk + 3][lr] = wv.w;
        __syncthreads();

        #pragma unroll
        for (int kk = 0; kk < 8; kk++) {
            const float4 a0 = *(const float4*)&As[kk][ty * 8];
            const float4 a1 = *(const float4*)&As[kk][ty * 8 + 4];
            const float4 b0 = *(const float4*)&Bs[kk][tx * 8];
            const float4 b1 = *(const float4*)&Bs[kk][tx * 8 + 4];
            const float ar[8] = {a0.x, a0.y, a0.z, a0.w, a1.x, a1.y, a1.z, a1.w};
            const float br[8] = {b0.x, b0.y, b0.z, b0.w, b1.x, b1.y, b1.z, b1.w};
            #pragma unroll
            for (int i = 0; i < 8; i++)
                #pragma unroll
                for (int j = 0; j < 8; j++)
                    acc[i][j] += ar[i] * br[j];
        }
    }

    #pragma unroll
    for (int i = 0; i < 8; i++) {
        const long row = bm + ty * 8 + i;
        #pragma unroll
        for (int j = 0; j < 8; j += 4) {
            const int col = bn + tx * 8 + j;
            if (col < N) {
                float4 v = make_float4(acc[i][j], acc[i][j + 1],
                                       acc[i][j + 2], acc[i][j + 3]);
                *(float4*)&C[row * N + col] = v;
            }
        }
    }
}

// ---------------------------------------------------------------------------
// Causal depthwise conv1d (width 4) + SiLU over the xBC slice of zxbcdt.
// out[r, c] = silu( sum_j x[l-3+j, c] * w[c, j] + b[c] ),  x = zx[:, 2048+c]
// ---------------------------------------------------------------------------
__global__ __launch_bounds__(256) void conv_silu_kernel(
    const float* __restrict__ zx, const float* __restrict__ cw,
    const float* __restrict__ cb, float* __restrict__ out)
{
    const long id = (long)blockIdx.x * 256 + threadIdx.x;
    if (id >= (long)ROWS * CONV_DIM) return;
    const int c = (int)(id % CONV_DIM);
    const long r = id / CONV_DIM;
    const int l = (int)(r & (SEQ - 1));
    const float* base = zx + r * D_IN_PROJ + D_INNER + c;

    const float w0 = cw[c * 4 + 0], w1 = cw[c * 4 + 1];
    const float w2 = cw[c * 4 + 2], w3 = cw[c * 4 + 3];
    float acc = cb[c];
    if (l >= 3) acc += base[-3L * D_IN_PROJ] * w0;
    if (l >= 2) acc += base[-2L * D_IN_PROJ] * w1;
    if (l >= 1) acc += base[-1L * D_IN_PROJ] * w2;
    acc += base[0] * w3;
    out[id] = acc / (1.f + expf(-acc));
}

// ---------------------------------------------------------------------------
// Selective-state scan (exact sequential recurrence) + D skip + SiLU(z) gate.
// One block per (batch, head): 64 blocks, 128 threads.
// Thread (p, half): p = tid>>1 owns output channel p; half owns 64 of 128 n.
// state[p, n] kept in registers (64 floats / thread).
// ---------------------------------------------------------------------------
#define SCAN_T 8
__global__ __launch_bounds__(128) void scan_kernel(
    const float* __restrict__ conv, const float* __restrict__ zx,
    const float* __restrict__ dt_bias, const float* __restrict__ A_log,
    const float* __restrict__ D_param, float* __restrict__ yout)
{
    const int bh = blockIdx.x;
    const int b = bh >> 5;
    const int h = bh & 31;
    const int tid = threadIdx.x;
    const int p = tid >> 1;
    const int half = tid & 1;
    const int n0 = half * 64;

    __shared__ float Bs[SCAN_T][STATE];
    __shared__ float Cs[SCAN_T][STATE];
    __shared__ float xs[SCAN_T][HEADDIM];
    __shared__ float zs[SCAN_T][HEADDIM];
    __shared__ float dts[SCAN_T];

    float state[64];
    #pragma unroll
    for (int j = 0; j < 64; j++) state[j] = 0.f;

    const float Aneg = -expf(A_log[h]);
    const float dtb  = dt_bias[h];
    const float Dp   = D_param[h];
    const long base_conv = (long)b * SEQ * CONV_DIM;
    const long base_z    = (long)b * SEQ * D_IN_PROJ;

    for (int t0 = 0; t0 < SEQ; t0 += SCAN_T) {
        __syncthreads();
        // load B and C tiles
        for (int idx = tid; idx < SCAN_T * STATE; idx += 128) {
            const int tt = idx >> 7;
            const int n  = idx & 127;
            const long rowp = base_conv + (long)(t0 + tt) * CONV_DIM;
            Bs[tt][n] = conv[rowp + D_INNER + n];
            Cs[tt][n] = conv[rowp + D_INNER + STATE + n];
        }
        // load x (post-conv) and z (pre-conv gate) for this head
        for (int idx = tid; idx < SCAN_T * HEADDIM; idx += 128) {
            const int tt = idx >> 6;
            const int pp = idx & 63;
            xs[tt][pp] = conv[base_conv + (long)(t0 + tt) * CONV_DIM + h * HEADDIM + pp];
            zs[tt][pp] = zx[base_z + (long)(t0 + tt) * D_IN_PROJ + h * HEADDIM + pp];
        }
        if (tid < SCAN_T)
            dts[tid] = zx[base_z + (long)(t0 + tid) * D_IN_PROJ + D_INNER + CONV_DIM + h];
        __syncthreads();

        #pragma unroll 1
        for (int tt = 0; tt < SCAN_T; tt++) {
            const float draw = dts[tt] + dtb;
            const float dtp = (draw > 20.f) ? draw : log1pf(expf(draw));
            const float dA = expf(dtp * Aneg);
            const float xv = xs[tt][p];
            const float k = dtp * xv;
            float y0 = 0.f, y1 = 0.f, y2 = 0.f, y3 = 0.f;
            const float4* Bv = (const float4*)&Bs[tt][n0];
            const float4* Cv = (const float4*)&Cs[tt][n0];
            #pragma unroll
            for (int jj = 0; jj < 16; jj++) {
                const float4 bv = Bv[jj];
                const float4 cv = Cv[jj];
                float* st = &state[jj * 4];
                st[0] = st[0] * dA + k * bv.x; y0 += st[0] * cv.x;
                st[1] = st[1] * dA + k * bv.y; y1 += st[1] * cv.y;
                st[2] = st[2] * dA + k * bv.z; y2 += st[2] * cv.z;
                st[3] = st[3] * dA + k * bv.w; y3 += st[3] * cv.w;
            }
            float y = (y0 + y1) + (y2 + y3);
            y += __shfl_xor_sync(0xffffffffu, y, 1);
            if (half == 0) {
                const float zv = zs[tt][p];
                const float gate = zv / (1.f + expf(-zv));
                yout[((long)(b * SEQ + t0 + tt)) * D_INNER + h * HEADDIM + p] =
                    (y + Dp * xv) * gate;
            }
        }
    }
}

// ---------------------------------------------------------------------------
// SwiGLU activation: g = silu(g) * u
// ---------------------------------------------------------------------------
__global__ __launch_bounds__(256) void silu_mul_kernel(
    float* __restrict__ g, const float* __restrict__ u, long n)
{
    const long id = (long)blockIdx.x * 256 + threadIdx.x;
    if (id >= n) return;
    const float gv = g[id];
    g[id] = (gv / (1.f + expf(-gv))) * u[id];
}

// ---------------------------------------------------------------------------
// Launch
// ---------------------------------------------------------------------------
extern "C" void kernel_launch(void* const* d_in, const int* in_sizes, int n_in,
                              void* d_out, int out_size)
{
    const float* hidden     = (const float*)d_in[0];
    const float* residual   = (const float*)d_in[1];
    const float* ssm_norm_w = (const float*)d_in[2];
    const float* mlp_norm_w = (const float*)d_in[3];
    const float* in_proj_w  = (const float*)d_in[4];
    const float* conv_w     = (const float*)d_in[5];
    const float* conv_b     = (const float*)d_in[6];
    const float* dt_bias    = (const float*)d_in[7];
    const float* A_log      = (const float*)d_in[8];
    const float* D_param    = (const float*)d_in[9];
    const float* out_proj_w = (const float*)d_in[10];
    const float* mlp_gate_w = (const float*)d_in[11];
    const float* mlp_up_w   = (const float*)d_in[12];
    const float* mlp_down_w = (const float*)d_in[13];

    float* out_h   = (float*)d_out;                       // (B,L,D_MODEL)
    float* out_res = out_h + (long)ROWS * D_MODEL;        // (B,L,D_MODEL)

    void *p_res1, *p_norm, *p_zx, *p_conv, *p_y, *p_h2, *p_gate, *p_up;
    cudaGetSymbolAddress(&p_res1, g_res1);
    cudaGetSymbolAddress(&p_norm, g_norm);
    cudaGetSymbolAddress(&p_zx,   g_zx);
    cudaGetSymbolAddress(&p_conv, g_conv);
    cudaGetSymbolAddress(&p_y,    g_y);
    cudaGetSymbolAddress(&p_h2,   g_h2);
    cudaGetSymbolAddress(&p_gate, g_gate);
    cudaGetSymbolAddress(&p_up,   g_up);

    // 1) prenorm RMSNorm #1
    rmsnorm_prenorm_kernel<<<ROWS, 256>>>(hidden, residual, ssm_norm_w,
                                          (float*)p_res1, (float*)p_norm);
    // 2) in_proj: (8192,1024) @ (4384,1024)^T
    sgemm_nt<<<dim3((D_IN_PROJ + 127) / 128, ROWS / 128), 256>>>(
        (const float*)p_norm, in_proj_w, (float*)p_zx, ROWS, D_IN_PROJ, D_MODEL);
    // 3) causal depthwise conv + SiLU on xBC
    conv_silu_kernel<<<(unsigned)(((long)ROWS * CONV_DIM + 255) / 256), 256>>>(
        (const float*)p_zx, conv_w, conv_b, (float*)p_conv);
    // 4) selective scan + D skip + SiLU(z) gate
    scan_kernel<<<BATCH * NHEADS, 128>>>(
        (const float*)p_conv, (const float*)p_zx, dt_bias, A_log, D_param,
        (float*)p_y);
    // 5) out_proj: (8192,2048) @ (1024,2048)^T
    sgemm_nt<<<dim3(D_MODEL / 128, ROWS / 128), 256>>>(
        (const float*)p_y, out_proj_w, (float*)p_h2, ROWS, D_MODEL, D_INNER);
    // 6) prenorm RMSNorm #2 (res_out is the second model output)
    rmsnorm_prenorm_kernel<<<ROWS, 256>>>((const float*)p_h2, (const float*)p_res1,
                                          mlp_norm_w, out_res, (float*)p_norm);
    // 7) MLP gate & up projections
    sgemm_nt<<<dim3(MLP_INNER / 128, ROWS / 128), 256>>>(
        (const float*)p_norm, mlp_gate_w, (float*)p_gate, ROWS, MLP_INNER, D_MODEL);
    sgemm_nt<<<dim3(MLP_INNER / 128, ROWS / 128), 256>>>(
        (const float*)p_norm, mlp_up_w, (float*)p_up, ROWS, MLP_INNER, D_MODEL);
    // 8) SwiGLU
    silu_mul_kernel<<<(unsigned)(((long)ROWS * MLP_INNER + 255) / 256), 256>>>(
        (float*)p_gate, (const float*)p_up, (long)ROWS * MLP_INNER);
    // 9) down projection -> first model output
    sgemm_nt<<<dim3(D_MODEL / 128, ROWS / 128), 256>>>(
        (const float*)p_gate, mlp_down_w, out_h, ROWS, D_MODEL, MLP_INNER);
}

// round 3
// speedup vs baseline: 1.7625x; 1.7625x over previous
#include <cuda_runtime.h>
#include <cuda_bf16.h>
#include <math.h>
#include <stdint.h>

// ---------------------------------------------------------------------------
// Problem constants
// ---------------------------------------------------------------------------
#define BATCH     2
#define SEQ       4096
#define ROWS      (BATCH * SEQ)          // 8192 tokens
#define D_MODEL   1024
#define STATE     128
#define HEADDIM   64
#define D_INNER   2048
#define NHEADS    32
#define CONV_DIM  (D_INNER + 2 * STATE)  // 2304
#define D_IN_PROJ (2 * D_INNER + 2 * STATE + NHEADS) // 4384
#define N_INPROJ_PAD 4480                // padded to multiple of 128
#define MLP_INNER 4096
#define EPS       1e-5f

// ---------------------------------------------------------------------------
// Scratch (static device arrays; no runtime allocation allowed)
// ---------------------------------------------------------------------------
__device__ float g_res1  [(size_t)ROWS * D_MODEL];
__device__ float g_zx    [(size_t)ROWS * D_IN_PROJ];
__device__ float g_conv  [(size_t)ROWS * CONV_DIM];
__device__ float g_h2    [(size_t)ROWS * D_MODEL];
__device__ float g_gate  [(size_t)ROWS * MLP_INNER];
__device__ float g_up    [(size_t)ROWS * MLP_INNER];

__device__ __nv_bfloat16 g_normh[(size_t)ROWS * D_MODEL];
__device__ __nv_bfloat16 g_norml[(size_t)ROWS * D_MODEL];
__device__ __nv_bfloat16 g_yh   [(size_t)ROWS * D_INNER];
__device__ __nv_bfloat16 g_yl   [(size_t)ROWS * D_INNER];
__device__ __nv_bfloat16 g_acth [(size_t)ROWS * MLP_INNER];
__device__ __nv_bfloat16 g_actl [(size_t)ROWS * MLP_INNER];

__device__ __nv_bfloat16 g_wih[(size_t)N_INPROJ_PAD * D_MODEL];
__device__ __nv_bfloat16 g_wil[(size_t)N_INPROJ_PAD * D_MODEL];
__device__ __nv_bfloat16 g_woh[(size_t)D_MODEL * D_INNER];
__device__ __nv_bfloat16 g_wol[(size_t)D_MODEL * D_INNER];
__device__ __nv_bfloat16 g_wgh[(size_t)MLP_INNER * D_MODEL];
__device__ __nv_bfloat16 g_wgl[(size_t)MLP_INNER * D_MODEL];
__device__ __nv_bfloat16 g_wuh[(size_t)MLP_INNER * D_MODEL];
__device__ __nv_bfloat16 g_wul[(size_t)MLP_INNER * D_MODEL];
__device__ __nv_bfloat16 g_wdh[(size_t)D_MODEL * MLP_INNER];
__device__ __nv_bfloat16 g_wdl[(size_t)D_MODEL * MLP_INNER];

// ---------------------------------------------------------------------------
// PTX helpers (baseline sm_103: cp.async + ldmatrix + mma.sync only)
// ---------------------------------------------------------------------------
__device__ __forceinline__ uint32_t smem_u32(const void* p) {
    uint32_t a;
    asm("{ .reg .u64 t; cvta.to.shared.u64 t, %1; cvt.u32.u64 %0, t; }"
        : "=r"(a) : "l"(p));
    return a;
}
__device__ __forceinline__ void cp_async16(uint32_t dst, const void* src) {
    asm volatile("cp.async.cg.shared.global [%0], [%1], 16;\n" :: "r"(dst), "l"(src));
}
__device__ __forceinline__ void cp_commit() {
    asm volatile("cp.async.commit_group;\n" ::: "memory");
}
template <int N>
__device__ __forceinline__ void cp_wait() {
    asm volatile("cp.async.wait_group %0;\n" :: "n"(N) : "memory");
}
__device__ __forceinline__ void ldmx4(uint32_t* r, uint32_t addr) {
    asm volatile("ldmatrix.sync.aligned.m8n8.x4.shared.b16 {%0,%1,%2,%3}, [%4];"
                 : "=r"(r[0]), "=r"(r[1]), "=r"(r[2]), "=r"(r[3]) : "r"(addr));
}
__device__ __forceinline__ void mma_bf16(float* c, const uint32_t* a, const uint32_t* b) {
    asm volatile(
        "mma.sync.aligned.m16n8k16.row.col.f32.bf16.bf16.f32 "
        "{%0,%1,%2,%3}, {%4,%5,%6,%7}, {%8,%9}, {%0,%1,%2,%3};"
        : "+f"(c[0]), "+f"(c[1]), "+f"(c[2]), "+f"(c[3])
        : "r"(a[0]), "r"(a[1]), "r"(a[2]), "r"(a[3]), "r"(b[0]), "r"(b[1]));
}

// ---------------------------------------------------------------------------
// Split-bf16 tensor-core GEMM: C[M,N] = A[M,K] @ W[N,K]^T
// A,W given as (hi, lo) bf16 pairs; C fp32. Error model: drop only Al*Bl.
// 128x128 CTA tile, BK=32, 3-stage cp.async pipeline, 8 warps (64x32 each).
// SMEM row stride 40 bf16 (80B) -> ldmatrix bank-conflict-free, no swizzle.
// ---------------------------------------------------------------------------
#define GSTAGE   3
#define ROWB     80                       // bytes per SMEM tile row (32 bf16 + pad)
#define TILE_B   (128 * ROWB)             // 10240 B per tile
#define STAGE_B  (4 * TILE_B)             // Ah, Al, Wh, Wl
#define GEMM_SMEM (GSTAGE * STAGE_B)      // 122880 B

__device__ __forceinline__ void load_stage_g(
    uint32_t sbase,
    const __nv_bfloat16* __restrict__ Ah, const __nv_bfloat16* __restrict__ Al,
    const __nv_bfloat16* __restrict__ Wh, const __nv_bfloat16* __restrict__ Wl,
    int bm, int bn, int K, int kc, int tid)
{
    const int koff = kc * 32;
    #pragma unroll
    for (int i = 0; i < 2; i++) {
        const int slot = tid + i * 256;   // 0..511
        const int row  = slot >> 2;       // 0..127
        const int ch   = slot & 3;        // 16B chunk within 64B row
        const uint32_t d = (uint32_t)(row * ROWB + ch * 16);
        const size_t ao = (size_t)(bm + row) * K + koff + ch * 8;
        const size_t bo = (size_t)(bn + row) * K + koff + ch * 8;
        cp_async16(sbase + 0 * TILE_B + d, Ah + ao);
        cp_async16(sbase + 1 * TILE_B + d, Al + ao);
        cp_async16(sbase + 2 * TILE_B + d, Wh + bo);
        cp_async16(sbase + 3 * TILE_B + d, Wl + bo);
    }
}

__global__ __launch_bounds__(256, 1)
void gemm_bf16x2(const __nv_bfloat16* __restrict__ Ah,
                 const __nv_bfloat16* __restrict__ Al,
                 const __nv_bfloat16* __restrict__ Wh,
                 const __nv_bfloat16* __restrict__ Wl,
                 float* __restrict__ C, int M, int N, int K)
{
    extern __shared__ __align__(128) char dynsmem[];
    const uint32_t sbase = smem_u32(dynsmem);

    const int tid  = threadIdx.x;
    const int lane = tid & 31;
    const int wid  = tid >> 5;
    const int wm   = wid & 1;             // warp row (2 x 64 rows)
    const int wn   = wid >> 1;            // warp col (4 x 32 cols)
    const int bm   = blockIdx.y * 128;
    const int bn   = blockIdx.x * 128;

    // Per-lane ldmatrix base offsets (bytes, relative to tile base)
    const uint32_t a_off = (uint32_t)((wm * 64 + (lane & 15)) * ROWB
                                      + ((lane >> 4) & 1) * 16);
    const uint32_t b_off = (uint32_t)((wn * 32 + ((lane >> 4) & 1) * 8 + (lane & 7)) * ROWB
                                      + ((lane >> 3) & 1) * 16);

    float acc[4][4][4];
    #pragma unroll
    for (int i = 0; i < 4; i++)
        #pragma unroll
        for (int j = 0; j < 4; j++)
            #pragma unroll
            for (int q = 0; q < 4; q++) acc[i][j][q] = 0.f;

    const int nk = K >> 5;

    load_stage_g(sbase + 0 * STAGE_B, Ah, Al, Wh, Wl, bm, bn, K, 0, tid);
    cp_commit();
    load_stage_g(sbase + 1 * STAGE_B, Ah, Al, Wh, Wl, bm, bn, K, 1, tid);
    cp_commit();

    for (int k = 0; k < nk; k++) {
        const uint32_t stb = sbase + (uint32_t)(k % GSTAGE) * STAGE_B;
        cp_wait<1>();
        __syncthreads();

        // prefetch next-next stage (buffer was consumed at iteration k-1)
        const int kn = k + 2;
        if (kn < nk)
            load_stage_g(sbase + (uint32_t)(kn % GSTAGE) * STAGE_B,
                         Ah, Al, Wh, Wl, bm, bn, K, kn, tid);
        cp_commit();

        const uint32_t a_h = stb + 0 * TILE_B + a_off;
        const uint32_t a_l = stb + 1 * TILE_B + a_off;
        const uint32_t b_h = stb + 2 * TILE_B + b_off;
        const uint32_t b_l = stb + 3 * TILE_B + b_off;

        #pragma unroll
        for (int s = 0; s < 2; s++) {     // two k16 steps per BK=32
            const uint32_t kb = (uint32_t)(s * 32);
            uint32_t ah[4][4], al[4][4], wh[4][2], wl[4][2];
            #pragma unroll
            for (int i = 0; i < 4; i++) {
                ldmx4(ah[i], a_h + (uint32_t)(i * 16 * ROWB) + kb);
                ldmx4(al[i], a_l + (uint32_t)(i * 16 * ROWB) + kb);
            }
            #pragma unroll
            for (int jp = 0; jp < 2; jp++) {
                uint32_t r[4];
                ldmx4(r, b_h + (uint32_t)(jp * 16 * ROWB) + kb);
                wh[jp * 2][0] = r[0]; wh[jp * 2][1] = r[1];
                wh[jp * 2 + 1][0] = r[2]; wh[jp * 2 + 1][1] = r[3];
                ldmx4(r, b_l + (uint32_t)(jp * 16 * ROWB) + kb);
                wl[jp * 2][0] = r[0]; wl[jp * 2][1] = r[1];
                wl[jp * 2 + 1][0] = r[2]; wl[jp * 2 + 1][1] = r[3];
            }
            #pragma unroll
            for (int i = 0; i < 4; i++)
                #pragma unroll
                for (int j = 0; j < 4; j++) {
                    mma_bf16(acc[i][j], ah[i], wh[j]);
                    mma_bf16(acc[i][j], ah[i], wl[j]);
                    mma_bf16(acc[i][j], al[i], wh[j]);
                }
        }
    }

    // Epilogue: write fp32 accumulators, guard N.
    #pragma unroll
    for (int i = 0; i < 4; i++) {
        const int row = bm + wm * 64 + i * 16 + (lane >> 2);
        #pragma unroll
        for (int j = 0; j < 4; j++) {
            const int col = bn + wn * 32 + j * 8 + (lane & 3) * 2;
            if (col < N) {
                float2 v0 = make_float2(acc[i][j][0], acc[i][j][1]);
                float2 v1 = make_float2(acc[i][j][2], acc[i][j][3]);
                *(float2*)&C[(size_t)row * N + col]       = v0;
                *(float2*)&C[(size_t)(row + 8) * N + col] = v1;
            }
        }
    }
}

// ---------------------------------------------------------------------------
// Weight fp32 -> (hi, lo) bf16 with zero padding at the tail.
// ---------------------------------------------------------------------------
__global__ __launch_bounds__(256) void cvt_weight_kernel(
    const float* __restrict__ w, __nv_bfloat16* __restrict__ hi,
    __nv_bfloat16* __restrict__ lo, size_t n_real, size_t n_total)
{
    const size_t i = (size_t)blockIdx.x * 256 + threadIdx.x;
    if (i >= n_total) return;
    const float v = (i < n_real) ? w[i] : 0.f;
    const __nv_bfloat16 h = __float2bfloat16(v);
    hi[i] = h;
    lo[i] = __float2bfloat16(v - __bfloat162float(h));
}

__device__ __forceinline__ void store_hilo4(
    __nv_bfloat16* __restrict__ hi, __nv_bfloat16* __restrict__ lo,
    size_t off, float4 v)
{
    __nv_bfloat16 h0 = __float2bfloat16(v.x), h1 = __float2bfloat16(v.y);
    __nv_bfloat16 h2 = __float2bfloat16(v.z), h3 = __float2bfloat16(v.w);
    __nv_bfloat162 hh0; hh0.x = h0; hh0.y = h1;
    __nv_bfloat162 hh1; hh1.x = h2; hh1.y = h3;
    *(__nv_bfloat162*)(hi + off)     = hh0;
    *(__nv_bfloat162*)(hi + off + 2) = hh1;
    __nv_bfloat162 ll0, ll1;
    ll0.x = __float2bfloat16(v.x - __bfloat162float(h0));
    ll0.y = __float2bfloat16(v.y - __bfloat162float(h1));
    ll1.x = __float2bfloat16(v.z - __bfloat162float(h2));
    ll1.y = __float2bfloat16(v.w - __bfloat162float(h3));
    *(__nv_bfloat162*)(lo + off)     = ll0;
    *(__nv_bfloat162*)(lo + off + 2) = ll1;
}

// ---------------------------------------------------------------------------
// Fused residual-add + RMSNorm; norm output as (hi, lo) bf16.
// ---------------------------------------------------------------------------
__global__ __launch_bounds__(256) void rmsnorm_prenorm_kernel(
    const float* __restrict__ x, const float* __restrict__ res_in,
    const float* __restrict__ w, float* __restrict__ res_out,
    __nv_bfloat16* __restrict__ nh, __nv_bfloat16* __restrict__ nl)
{
    const size_t row = blockIdx.x;
    const int tid = threadIdx.x;
    const float4 xv = ((const float4*)(x      + row * D_MODEL))[tid];
    const float4 rv = ((const float4*)(res_in + row * D_MODEL))[tid];
    float4 s;
    s.x = xv.x + rv.x; s.y = xv.y + rv.y; s.z = xv.z + rv.z; s.w = xv.w + rv.w;
    float ss = s.x * s.x + s.y * s.y + s.z * s.z + s.w * s.w;

    #pragma unroll
    for (int o = 16; o > 0; o >>= 1) ss += __shfl_down_sync(0xffffffffu, ss, o);
    __shared__ float red[8];
    __shared__ float scale_sh;
    if ((tid & 31) == 0) red[tid >> 5] = ss;
    __syncthreads();
    if (tid == 0) {
        float t = 0.f;
        #pragma unroll
        for (int i = 0; i < 8; i++) t += red[i];
        scale_sh = rsqrtf(t / (float)D_MODEL + EPS);
    }
    __syncthreads();
    const float scale = scale_sh;

    ((float4*)(res_out + row * D_MODEL))[tid] = s;
    const float4 wv = ((const float4*)w)[tid];
    float4 o;
    o.x = s.x * scale * wv.x; o.y = s.y * scale * wv.y;
    o.z = s.z * scale * wv.z; o.w = s.w * scale * wv.w;
    store_hilo4(nh, nl, row * D_MODEL + (size_t)tid * 4, o);
}

// ---------------------------------------------------------------------------
// Causal depthwise conv1d (width 4) + SiLU over the xBC slice of zxbcdt.
// ---------------------------------------------------------------------------
__global__ __launch_bounds__(256) void conv_silu_kernel(
    const float* __restrict__ zx, const float* __restrict__ cw,
    const float* __restrict__ cb, float* __restrict__ out)
{
    const size_t id = (size_t)blockIdx.x * 256 + threadIdx.x;
    if (id >= (size_t)ROWS * CONV_DIM) return;
    const int c = (int)(id % CONV_DIM);
    const size_t r = id / CONV_DIM;
    const int l = (int)(r & (SEQ - 1));
    const float* base = zx + r * D_IN_PROJ + D_INNER + c;

    const float w0 = cw[c * 4 + 0], w1 = cw[c * 4 + 1];
    const float w2 = cw[c * 4 + 2], w3 = cw[c * 4 + 3];
    float acc = cb[c];
    if (l >= 3) acc += base[-3L * D_IN_PROJ] * w0;
    if (l >= 2) acc += base[-2L * D_IN_PROJ] * w1;
    if (l >= 1) acc += base[-1L * D_IN_PROJ] * w2;
    acc += base[0] * w3;
    out[id] = acc / (1.f + expf(-acc));
}

// ---------------------------------------------------------------------------
// Selective-state scan + D skip + SiLU(z) gate; output as (hi, lo) bf16.
// One block per (batch, head): 64 blocks, 128 threads.
// ---------------------------------------------------------------------------
#define SCAN_T 8
__global__ __launch_bounds__(128) void scan_kernel(
    const float* __restrict__ conv, const float* __restrict__ zx,
    const float* __restrict__ dt_bias, const float* __restrict__ A_log,
    const float* __restrict__ D_param,
    __nv_bfloat16* __restrict__ yh, __nv_bfloat16* __restrict__ yl)
{
    const int bh = blockIdx.x;
    const int b = bh >> 5;
    const int h = bh & 31;
    const int tid = threadIdx.x;
    const int p = tid >> 1;
    const int half = tid & 1;
    const int n0 = half * 64;

    __shared__ float Bs[SCAN_T][STATE];
    __shared__ float Cs[SCAN_T][STATE];
    __shared__ float xs[SCAN_T][HEADDIM];
    __shared__ float zs[SCAN_T][HEADDIM];
    __shared__ float dts[SCAN_T];

    float state[64];
    #pragma unroll
    for (int j = 0; j < 64; j++) state[j] = 0.f;

    const float Aneg = -expf(A_log[h]);
    const float dtb  = dt_bias[h];
    const float Dp   = D_param[h];
    const size_t base_conv = (size_t)b * SEQ * CONV_DIM;
    const size_t base_z    = (size_t)b * SEQ * D_IN_PROJ;

    for (int t0 = 0; t0 < SEQ; t0 += SCAN_T) {
        __syncthreads();
        for (int idx = tid; idx < SCAN_T * STATE; idx += 128) {
            const int tt = idx >> 7;
            const int n  = idx & 127;
            const size_t rowp = base_conv + (size_t)(t0 + tt) * CONV_DIM;
            Bs[tt][n] = conv[rowp + D_INNER + n];
            Cs[tt][n] = conv[rowp + D_INNER + STATE + n];
        }
        for (int idx = tid; idx < SCAN_T * HEADDIM; idx += 128) {
            const int tt = idx >> 6;
            const int pp = idx & 63;
            xs[tt][pp] = conv[base_conv + (size_t)(t0 + tt) * CONV_DIM + h * HEADDIM + pp];
            zs[tt][pp] = zx[base_z + (size_t)(t0 + tt) * D_IN_PROJ + h * HEADDIM + pp];
        }
        if (tid < SCAN_T)
            dts[tid] = zx[base_z + (size_t)(t0 + tid) * D_IN_PROJ + D_INNER + CONV_DIM + h];
        __syncthreads();

        #pragma unroll 1
        for (int tt = 0; tt < SCAN_T; tt++) {
            const float draw = dts[tt] + dtb;
            const float dtp = (draw > 20.f) ? draw : log1pf(expf(draw));
            const float dA = expf(dtp * Aneg);
            const float xv = xs[tt][p];
            const float k = dtp * xv;
            float y0 = 0.f, y1 = 0.f, y2 = 0.f, y3 = 0.f;
            const float4* Bv = (const float4*)&Bs[tt][n0];
            const float4* Cv = (const float4*)&Cs[tt][n0];
            #pragma unroll
            for (int jj = 0; jj < 16; jj++) {
                const float4 bv = Bv[jj];
                const float4 cv = Cv[jj];
                float* st = &state[jj * 4];
                st[0] = st[0] * dA + k * bv.x; y0 += st[0] * cv.x;
                st[1] = st[1] * dA + k * bv.y; y1 += st[1] * cv.y;
                st[2] = st[2] * dA + k * bv.z; y2 += st[2] * cv.z;
                st[3] = st[3] * dA + k * bv.w; y3 += st[3] * cv.w;
            }
            float y = (y0 + y1) + (y2 + y3);
            y += __shfl_xor_sync(0xffffffffu, y, 1);
            if (half == 0) {
                const float zv = zs[tt][p];
                const float gate = zv / (1.f + expf(-zv));
                const float yo = (y + Dp * xv) * gate;
                const size_t oidx =
                    ((size_t)(b * SEQ + t0 + tt)) * D_INNER + h * HEADDIM + p;
                const __nv_bfloat16 hh = __float2bfloat16(yo);
                yh[oidx] = hh;
                yl[oidx] = __float2bfloat16(yo - __bfloat162float(hh));
            }
        }
    }
}

// ---------------------------------------------------------------------------
// SwiGLU: out = silu(g) * u, output as (hi, lo) bf16. 4 elems/thread.
// ---------------------------------------------------------------------------
__global__ __launch_bounds__(256) void swiglu_kernel(
    const float* __restrict__ g, const float* __restrict__ u,
    __nv_bfloat16* __restrict__ oh, __nv_bfloat16* __restrict__ ol, size_t n4)
{
    const size_t id = (size_t)blockIdx.x * 256 + threadIdx.x;
    if (id >= n4) return;
    const float4 gv = ((const float4*)g)[id];
    const float4 uv = ((const float4*)u)[id];
    float4 v;
    v.x = gv.x / (1.f + expf(-gv.x)) * uv.x;
    v.y = gv.y / (1.f + expf(-gv.y)) * uv.y;
    v.z = gv.z / (1.f + expf(-gv.z)) * uv.z;
    v.w = gv.w / (1.f + expf(-gv.w)) * uv.w;
    store_hilo4(oh, ol, id * 4, v);
}

// ---------------------------------------------------------------------------
// Launch
// ---------------------------------------------------------------------------
extern "C" void kernel_launch(void* const* d_in, const int* in_sizes, int n_in,
                              void* d_out, int out_size)
{
    const float* hidden     = (const float*)d_in[0];
    const float* residual   = (const float*)d_in[1];
    const float* ssm_norm_w = (const float*)d_in[2];
    const float* mlp_norm_w = (const float*)d_in[3];
    const float* in_proj_w  = (const float*)d_in[4];
    const float* conv_w     = (const float*)d_in[5];
    const float* conv_b     = (const float*)d_in[6];
    const float* dt_bias    = (const float*)d_in[7];
    const float* A_log      = (const float*)d_in[8];
    const float* D_param    = (const float*)d_in[9];
    const float* out_proj_w = (const float*)d_in[10];
    const float* mlp_gate_w = (const float*)d_in[11];
    const float* mlp_up_w   = (const float*)d_in[12];
    const float* mlp_down_w = (const float*)d_in[13];

    float* out_h   = (float*)d_out;
    float* out_res = out_h + (size_t)ROWS * D_MODEL;

    void *p_res1, *p_zx, *p_conv, *p_h2, *p_gate, *p_up;
    void *p_nh, *p_nl, *p_yh, *p_yl, *p_ah, *p_al;
    void *p_wih, *p_wil, *p_woh, *p_wol, *p_wgh, *p_wgl, *p_wuh, *p_wul, *p_wdh, *p_wdl;
    cudaGetSymbolAddress(&p_res1, g_res1);
    cudaGetSymbolAddress(&p_zx,   g_zx);
    cudaGetSymbolAddress(&p_conv, g_conv);
    cudaGetSymbolAddress(&p_h2,   g_h2);
    cudaGetSymbolAddress(&p_gate, g_gate);
    cudaGetSymbolAddress(&p_up,   g_up);
    cudaGetSymbolAddress(&p_nh,   g_normh);
    cudaGetSymbolAddress(&p_nl,   g_norml);
    cudaGetSymbolAddress(&p_yh,   g_yh);
    cudaGetSymbolAddress(&p_yl,   g_yl);
    cudaGetSymbolAddress(&p_ah,   g_acth);
    cudaGetSymbolAddress(&p_al,   g_actl);
    cudaGetSymbolAddress(&p_wih,  g_wih);
    cudaGetSymbolAddress(&p_wil,  g_wil);
    cudaGetSymbolAddress(&p_woh,  g_woh);
    cudaGetSymbolAddress(&p_wol,  g_wol);
    cudaGetSymbolAddress(&p_wgh,  g_wgh);
    cudaGetSymbolAddress(&p_wgl,  g_wgl);
    cudaGetSymbolAddress(&p_wuh,  g_wuh);
    cudaGetSymbolAddress(&p_wul,  g_wul);
    cudaGetSymbolAddress(&p_wdh,  g_wdh);
    cudaGetSymbolAddress(&p_wdl,  g_wdl);

    cudaFuncSetAttribute(gemm_bf16x2, cudaFuncAttributeMaxDynamicSharedMemorySize,
                         GEMM_SMEM);

    // Weight conversions (hi/lo split + padding)
    {
        size_t nr, nt;
        nr = (size_t)D_IN_PROJ * D_MODEL; nt = (size_t)N_INPROJ_PAD * D_MODEL;
        cvt_weight_kernel<<<(unsigned)((nt + 255) / 256), 256>>>(
            in_proj_w, (__nv_bfloat16*)p_wih, (__nv_bfloat16*)p_wil, nr, nt);
        nr = nt = (size_t)D_MODEL * D_INNER;
        cvt_weight_kernel<<<(unsigned)((nt + 255) / 256), 256>>>(
            out_proj_w, (__nv_bfloat16*)p_woh, (__nv_bfloat16*)p_wol, nr, nt);
        nr = nt = (size_t)MLP_INNER * D_MODEL;
        cvt_weight_kernel<<<(unsigned)((nt + 255) / 256), 256>>>(
            mlp_gate_w, (__nv_bfloat16*)p_wgh, (__nv_bfloat16*)p_wgl, nr, nt);
        cvt_weight_kernel<<<(unsigned)((nt + 255) / 256), 256>>>(
            mlp_up_w, (__nv_bfloat16*)p_wuh, (__nv_bfloat16*)p_wul, nr, nt);
        nr = nt = (size_t)D_MODEL * MLP_INNER;
        cvt_weight_kernel<<<(unsigned)((nt + 255) / 256), 256>>>(
            mlp_down_w, (__nv_bfloat16*)p_wdh, (__nv_bfloat16*)p_wdl, nr, nt);
    }

    // 1) prenorm RMSNorm #1
    rmsnorm_prenorm_kernel<<<ROWS, 256>>>(hidden, residual, ssm_norm_w,
        (float*)p_res1, (__nv_bfloat16*)p_nh, (__nv_bfloat16*)p_nl);
    // 2) in_proj
    gemm_bf16x2<<<dim3(N_INPROJ_PAD / 128, ROWS / 128), 256, GEMM_SMEM>>>(
        (const __nv_bfloat16*)p_nh, (const __nv_bfloat16*)p_nl,
        (const __nv_bfloat16*)p_wih, (const __nv_bfloat16*)p_wil,
        (float*)p_zx, ROWS, D_IN_PROJ, D_MODEL);
    // 3) causal depthwise conv + SiLU
    conv_silu_kernel<<<(unsigned)(((size_t)ROWS * CONV_DIM + 255) / 256), 256>>>(
        (const float*)p_zx, conv_w, conv_b, (float*)p_conv);
    // 4) selective scan
    scan_kernel<<<BATCH * NHEADS, 128>>>(
        (const float*)p_conv, (const float*)p_zx, dt_bias, A_log, D_param,
        (__nv_bfloat16*)p_yh, (__nv_bfloat16*)p_yl);
    // 5) out_proj
    gemm_bf16x2<<<dim3(D_MODEL / 128, ROWS / 128), 256, GEMM_SMEM>>>(
        (const __nv_bfloat16*)p_yh, (const __nv_bfloat16*)p_yl,
        (const __nv_bfloat16*)p_woh, (const __nv_bfloat16*)p_wol,
        (float*)p_h2, ROWS, D_MODEL, D_INNER);
    // 6) prenorm RMSNorm #2
    rmsnorm_prenorm_kernel<<<ROWS, 256>>>((const float*)p_h2, (const float*)p_res1,
        mlp_norm_w, out_res, (__nv_bfloat16*)p_nh, (__nv_bfloat16*)p_nl);
    // 7) MLP gate & up
    gemm_bf16x2<<<dim3(MLP_INNER / 128, ROWS / 128), 256, GEMM_SMEM>>>(
        (const __nv_bfloat16*)p_nh, (const __nv_bfloat16*)p_nl,
        (const __nv_bfloat16*)p_wgh, (const __nv_bfloat16*)p_wgl,
        (float*)p_gate, ROWS, MLP_INNER, D_MODEL);
    gemm_bf16x2<<<dim3(MLP_INNER / 128, ROWS / 128), 256, GEMM_SMEM>>>(
        (const __nv_bfloat16*)p_nh, (const __nv_bfloat16*)p_nl,
        (const __nv_bfloat16*)p_wuh, (const __nv_bfloat16*)p_wul,
        (float*)p_up, ROWS, MLP_INNER, D_MODEL);
    // 8) SwiGLU
    swiglu_kernel<<<(unsigned)(((size_t)ROWS * MLP_INNER / 4 + 255) / 256), 256>>>(
        (const float*)p_gate, (const float*)p_up,
        (__nv_bfloat16*)p_ah, (__nv_bfloat16*)p_al, (size_t)ROWS * MLP_INNER / 4);
    // 9) down projection -> first model output
    gemm_bf16x2<<<dim3(D_MODEL / 128, ROWS / 128), 256, GEMM_SMEM>>>(
        (const __nv_bfloat16*)p_ah, (const __nv_bfloat16*)p_al,
        (const __nv_bfloat16*)p_wdh, (const __nv_bfloat16*)p_wdl,
        out_h, ROWS, D_MODEL, MLP_INNER);
}

// round 6
// speedup vs baseline: 3.1358x; 1.7791x over previous
#include <cuda_runtime.h>
#include <cuda_bf16.h>
#include <math.h>
#include <stdint.h>

// ---------------------------------------------------------------------------
// Problem constants
// ---------------------------------------------------------------------------
#define BATCH     2
#define SEQ       4096
#define ROWS      (BATCH * SEQ)          // 8192 tokens
#define D_MODEL   1024
#define STATE     128
#define HEADDIM   64
#define D_INNER   2048
#define NHEADS    32
#define CONV_DIM  (D_INNER + 2 * STATE)  // 2304
#define D_IN_PROJ (2 * D_INNER + 2 * STATE + NHEADS) // 4384
#define N_INPROJ_PAD 4608                // padded to multiple of 256
#define MLP_INNER 4096
#define EPS       1e-5f
#define NCHUNK    32
#define CLEN      128                    // SEQ / NCHUNK

// ---------------------------------------------------------------------------
// Scratch (static device arrays; no runtime allocation allowed)
// ---------------------------------------------------------------------------
__device__ float g_res1  [(size_t)ROWS * D_MODEL];
__device__ float g_zx    [(size_t)ROWS * D_IN_PROJ];
__device__ float g_conv  [(size_t)ROWS * CONV_DIM];
__device__ float g_h2    [(size_t)ROWS * D_MODEL];
__device__ float g_gate  [(size_t)ROWS * MLP_INNER];
__device__ float g_up    [(size_t)ROWS * MLP_INNER];

__device__ float g_slocal[(size_t)BATCH * NHEADS * NCHUNK * HEADDIM * STATE];
__device__ float g_sin   [(size_t)BATCH * NHEADS * NCHUNK * HEADDIM * STATE];
__device__ float g_cdec  [BATCH * NHEADS * NCHUNK];

__device__ __nv_bfloat16 g_normh[(size_t)ROWS * D_MODEL];
__device__ __nv_bfloat16 g_norml[(size_t)ROWS * D_MODEL];
__device__ __nv_bfloat16 g_yh   [(size_t)ROWS * D_INNER];
__device__ __nv_bfloat16 g_yl   [(size_t)ROWS * D_INNER];
__device__ __nv_bfloat16 g_acth [(size_t)ROWS * MLP_INNER];
__device__ __nv_bfloat16 g_actl [(size_t)ROWS * MLP_INNER];

__device__ __nv_bfloat16 g_wih[(size_t)N_INPROJ_PAD * D_MODEL];
__device__ __nv_bfloat16 g_wil[(size_t)N_INPROJ_PAD * D_MODEL];
__device__ __nv_bfloat16 g_woh[(size_t)D_MODEL * D_INNER];
__device__ __nv_bfloat16 g_wol[(size_t)D_MODEL * D_INNER];
__device__ __nv_bfloat16 g_wgh[(size_t)MLP_INNER * D_MODEL];
__device__ __nv_bfloat16 g_wgl[(size_t)MLP_INNER * D_MODEL];
__device__ __nv_bfloat16 g_wuh[(size_t)MLP_INNER * D_MODEL];
__device__ __nv_bfloat16 g_wul[(size_t)MLP_INNER * D_MODEL];
__device__ __nv_bfloat16 g_wdh[(size_t)D_MODEL * MLP_INNER];
__device__ __nv_bfloat16 g_wdl[(size_t)D_MODEL * MLP_INNER];

// ---------------------------------------------------------------------------
// PTX helpers (baseline sm_103: cp.async + ldmatrix + mma.sync)
// ---------------------------------------------------------------------------
__device__ __forceinline__ uint32_t smem_u32(const void* p) {
    uint32_t a;
    asm("{ .reg .u64 t; cvta.to.shared.u64 t, %1; cvt.u32.u64 %0, t; }"
        : "=r"(a) : "l"(p));
    return a;
}
__device__ __forceinline__ void cp_async16(uint32_t dst, const void* src) {
    asm volatile("cp.async.cg.shared.global [%0], [%1], 16;\n" :: "r"(dst), "l"(src));
}
__device__ __forceinline__ void cp_commit() {
    asm volatile("cp.async.commit_group;\n" ::: "memory");
}
template <int N>
__device__ __forceinline__ void cp_wait() {
    asm volatile("cp.async.wait_group %0;\n" :: "n"(N) : "memory");
}
__device__ __forceinline__ void ldmx4(uint32_t* r, uint32_t addr) {
    asm volatile("ldmatrix.sync.aligned.m8n8.x4.shared.b16 {%0,%1,%2,%3}, [%4];"
                 : "=r"(r[0]), "=r"(r[1]), "=r"(r[2]), "=r"(r[3]) : "r"(addr));
}
__device__ __forceinline__ void mma_bf16(float* c, const uint32_t* a, const uint32_t* b) {
    asm volatile(
        "mma.sync.aligned.m16n8k16.row.col.f32.bf16.bf16.f32 "
        "{%0,%1,%2,%3}, {%4,%5,%6,%7}, {%8,%9}, {%0,%1,%2,%3};"
        : "+f"(c[0]), "+f"(c[1]), "+f"(c[2]), "+f"(c[3])
        : "r"(a[0]), "r"(a[1]), "r"(a[2]), "r"(a[3]), "r"(b[0]), "r"(b[1]));
}

// ---------------------------------------------------------------------------
// Split-bf16 tensor-core GEMM: C[M,N] = A[M,K] @ W[N,K]^T
// A,W as (hi, lo) bf16 pairs; C fp32; 3 MMAs (drop Al*Bl only).
// 128x256 CTA tile, BK=32, 512 threads (16 warps, 32x64 each), 3 stages.
// SMEM row stride 80B -> ldmatrix conflict-free without swizzle.
// ---------------------------------------------------------------------------
#define GSTAGE   3
#define ROWB     80
#define A_TILE_B (128 * ROWB)            // 10240
#define W_TILE_B (256 * ROWB)            // 20480
#define STAGE_B  (2 * A_TILE_B + 2 * W_TILE_B)  // 61440
#define GEMM_SMEM (GSTAGE * STAGE_B)     // 184320

__device__ __forceinline__ void load_stage_g(
    uint32_t sbase,
    const __nv_bfloat16* __restrict__ Ah, const __nv_bfloat16* __restrict__ Al,
    const __nv_bfloat16* __restrict__ Wh, const __nv_bfloat16* __restrict__ Wl,
    int bm, int bn, int K, int kc, int tid)
{
    const int koff = kc * 32;
    {
        const int row = tid >> 2, ch = tid & 3;
        const uint32_t d = (uint32_t)(row * ROWB + ch * 16);
        const size_t ao = (size_t)(bm + row) * K + koff + ch * 8;
        cp_async16(sbase + d, Ah + ao);
        cp_async16(sbase + A_TILE_B + d, Al + ao);
    }
    #pragma unroll
    for (int i = 0; i < 2; i++) {
        const int slot = tid + i * 512;
        const int row = slot >> 2, ch = slot & 3;
        const uint32_t d = (uint32_t)(row * ROWB + ch * 16);
        const size_t bo = (size_t)(bn + row) * K + koff + ch * 8;
        cp_async16(sbase + 2 * A_TILE_B + d, Wh + bo);
        cp_async16(sbase + 2 * A_TILE_B + W_TILE_B + d, Wl + bo);
    }
}

__global__ __launch_bounds__(512, 1)
void gemm_bf16x2(const __nv_bfloat16* __restrict__ Ah,
                 const __nv_bfloat16* __restrict__ Al,
                 const __nv_bfloat16* __restrict__ Wh,
                 const __nv_bfloat16* __restrict__ Wl,
                 float* __restrict__ C, int M, int N, int K)
{
    extern __shared__ __align__(128) char dynsmem[];
    const uint32_t sbase = smem_u32(dynsmem);

    const int tid  = threadIdx.x;
    const int lane = tid & 31;
    const int wid  = tid >> 5;
    const int wm   = wid & 3;             // 4 m-groups of 32 rows
    const int wn   = wid >> 2;            // 4 n-groups of 64 cols
    const int bm   = blockIdx.y * 128;
    const int bn   = blockIdx.x * 256;

    const uint32_t a_off = (uint32_t)((wm * 32 + (lane & 15)) * ROWB
                                      + ((lane >> 4) & 1) * 16);
    const uint32_t b_off = (uint32_t)((wn * 64 + ((lane >> 4) & 1) * 8 + (lane & 7)) * ROWB
                                      + ((lane >> 3) & 1) * 16);

    float acc[2][8][4];
    #pragma unroll
    for (int i = 0; i < 2; i++)
        #pragma unroll
        for (int j = 0; j < 8; j++)
            #pragma unroll
            for (int q = 0; q < 4; q++) acc[i][j][q] = 0.f;

    const int nk = K >> 5;

    load_stage_g(sbase + 0 * STAGE_B, Ah, Al, Wh, Wl, bm, bn, K, 0, tid);
    cp_commit();
    load_stage_g(sbase + 1 * STAGE_B, Ah, Al, Wh, Wl, bm, bn, K, 1, tid);
    cp_commit();

    for (int k = 0; k < nk; k++) {
        const uint32_t stb = sbase + (uint32_t)(k % GSTAGE) * STAGE_B;
        cp_wait<1>();
        __syncthreads();

        const int kn = k + 2;
        if (kn < nk)
            load_stage_g(sbase + (uint32_t)(kn % GSTAGE) * STAGE_B,
                         Ah, Al, Wh, Wl, bm, bn, K, kn, tid);
        cp_commit();

        const uint32_t a_h = stb + a_off;
        const uint32_t a_l = stb + A_TILE_B + a_off;
        const uint32_t b_h = stb + 2 * A_TILE_B + b_off;
        const uint32_t b_l = stb + 2 * A_TILE_B + W_TILE_B + b_off;

        #pragma unroll
        for (int s = 0; s < 2; s++) {
            const uint32_t kb = (uint32_t)(s * 32);
            uint32_t ahf[2][4], alf[2][4];
            #pragma unroll
            for (int i = 0; i < 2; i++) {
                ldmx4(ahf[i], a_h + (uint32_t)(i * 16 * ROWB) + kb);
                ldmx4(alf[i], a_l + (uint32_t)(i * 16 * ROWB) + kb);
            }
            #pragma unroll
            for (int jp = 0; jp < 4; jp++) {
                uint32_t whf[4], wlf[4];
                ldmx4(whf, b_h + (uint32_t)(jp * 16 * ROWB) + kb);
                ldmx4(wlf, b_l + (uint32_t)(jp * 16 * ROWB) + kb);
                #pragma unroll
                for (int i = 0; i < 2; i++)
                    #pragma unroll
                    for (int f = 0; f < 2; f++) {
                        mma_bf16(acc[i][jp * 2 + f], ahf[i], whf + f * 2);
                        mma_bf16(acc[i][jp * 2 + f], ahf[i], wlf + f * 2);
                        mma_bf16(acc[i][jp * 2 + f], alf[i], whf + f * 2);
                    }
            }
        }
    }

    #pragma unroll
    for (int i = 0; i < 2; i++) {
        const int row = bm + wm * 32 + i * 16 + (lane >> 2);
        #pragma unroll
        for (int j = 0; j < 8; j++) {
            const int col = bn + wn * 64 + j * 8 + (lane & 3) * 2;
            if (col < N) {
                *(float2*)&C[(size_t)row * N + col] =
                    make_float2(acc[i][j][0], acc[i][j][1]);
                *(float2*)&C[(size_t)(row + 8) * N + col] =
                    make_float2(acc[i][j][2], acc[i][j][3]);
            }
        }
    }
}

// ---------------------------------------------------------------------------
// hi/lo helpers
// ---------------------------------------------------------------------------
__device__ __forceinline__ void store_hilo4(
    __nv_bfloat16* __restrict__ hi, __nv_bfloat16* __restrict__ lo,
    size_t off, float4 v)
{
    __nv_bfloat16 h0 = __float2bfloat16(v.x), h1 = __float2bfloat16(v.y);
    __nv_bfloat16 h2 = __float2bfloat16(v.z), h3 = __float2bfloat16(v.w);
    __nv_bfloat162 hh0; hh0.x = h0; hh0.y = h1;
    __nv_bfloat162 hh1; hh1.x = h2; hh1.y = h3;
    *(__nv_bfloat162*)(hi + off)     = hh0;
    *(__nv_bfloat162*)(hi + off + 2) = hh1;
    __nv_bfloat162 ll0, ll1;
    ll0.x = __float2bfloat16(v.x - __bfloat162float(h0));
    ll0.y = __float2bfloat16(v.y - __bfloat162float(h1));
    ll1.x = __float2bfloat16(v.z - __bfloat162float(h2));
    ll1.y = __float2bfloat16(v.w - __bfloat162float(h3));
    *(__nv_bfloat162*)(lo + off)     = ll0;
    *(__nv_bfloat162*)(lo + off + 2) = ll1;
}

// Weight fp32 -> (hi, lo) bf16, float4-vectorized, zero tail padding.
__global__ __launch_bounds__(256) void cvt_weight_kernel(
    const float* __restrict__ w, __nv_bfloat16* __restrict__ hi,
    __nv_bfloat16* __restrict__ lo, size_t n_real4, size_t n_total4)
{
    const size_t i = (size_t)blockIdx.x * 256 + threadIdx.x;
    if (i >= n_total4) return;
    float4 v = (i < n_real4) ? ((const float4*)w)[i]
                             : make_float4(0.f, 0.f, 0.f, 0.f);
    store_hilo4(hi, lo, i * 4, v);
}

// ---------------------------------------------------------------------------
// Fused residual-add + RMSNorm; norm output as (hi, lo) bf16.
// ---------------------------------------------------------------------------
__global__ __launch_bounds__(256) void rmsnorm_prenorm_kernel(
    const float* __restrict__ x, const float* __restrict__ res_in,
    const float* __restrict__ w, float* __restrict__ res_out,
    __nv_bfloat16* __restrict__ nh, __nv_bfloat16* __restrict__ nl)
{
    const size_t row = blockIdx.x;
    const int tid = threadIdx.x;
    const float4 xv = ((const float4*)(x      + row * D_MODEL))[tid];
    const float4 rv = ((const float4*)(res_in + row * D_MODEL))[tid];
    float4 s;
    s.x = xv.x + rv.x; s.y = xv.y + rv.y; s.z = xv.z + rv.z; s.w = xv.w + rv.w;
    float ss = s.x * s.x + s.y * s.y + s.z * s.z + s.w * s.w;

    #pragma unroll
    for (int o = 16; o > 0; o >>= 1) ss += __shfl_down_sync(0xffffffffu, ss, o);
    __shared__ float red[8];
    __shared__ float scale_sh;
    if ((tid & 31) == 0) red[tid >> 5] = ss;
    __syncthreads();
    if (tid == 0) {
        float t = 0.f;
        #pragma unroll
        for (int i = 0; i < 8; i++) t += red[i];
        scale_sh = rsqrtf(t / (float)D_MODEL + EPS);
    }
    __syncthreads();
    const float scale = scale_sh;

    ((float4*)(res_out + row * D_MODEL))[tid] = s;
    const float4 wv = ((const float4*)w)[tid];
    float4 o;
    o.x = s.x * scale * wv.x; o.y = s.y * scale * wv.y;
    o.z = s.z * scale * wv.z; o.w = s.w * scale * wv.w;
    store_hilo4(nh, nl, row * D_MODEL + (size_t)tid * 4, o);
}

// ---------------------------------------------------------------------------
// Causal depthwise conv1d (width 4) + SiLU over the xBC slice of zxbcdt.
// ---------------------------------------------------------------------------
__global__ __launch_bounds__(256) void conv_silu_kernel(
    const float* __restrict__ zx, const float* __restrict__ cw,
    const float* __restrict__ cb, float* __restrict__ out)
{
    const size_t id = (size_t)blockIdx.x * 256 + threadIdx.x;
    if (id >= (size_t)ROWS * CONV_DIM) return;
    const int c = (int)(id % CONV_DIM);
    const size_t r = id / CONV_DIM;
    const int l = (int)(r & (SEQ - 1));
    const float* base = zx + r * D_IN_PROJ + D_INNER + c;

    const float w0 = cw[c * 4 + 0], w1 = cw[c * 4 + 1];
    const float w2 = cw[c * 4 + 2], w3 = cw[c * 4 + 3];
    float acc = cb[c];
    if (l >= 3) acc += base[-3L * D_IN_PROJ] * w0;
    if (l >= 2) acc += base[-2L * D_IN_PROJ] * w1;
    if (l >= 1) acc += base[-1L * D_IN_PROJ] * w2;
    acc += base[0] * w3;
    out[id] = acc / (1.f + expf(-acc));
}

// ---------------------------------------------------------------------------
// Chunked selective scan. Phase 1: per-chunk local scan (zero init state),
// writes final local state + chunk decay product. Grid: (NCHUNK, B*H).
// ---------------------------------------------------------------------------
#define SCAN_T 8
__global__ __launch_bounds__(128) void scan_local_kernel(
    const float* __restrict__ conv, const float* __restrict__ zx,
    const float* __restrict__ dt_bias, const float* __restrict__ A_log)
{
    const int chunk = blockIdx.x;
    const int bh = blockIdx.y;
    const int b = bh >> 5;
    const int h = bh & 31;
    const int tid = threadIdx.x;
    const int p = tid >> 1;
    const int half = tid & 1;
    const int n0 = half * 64;

    __shared__ float Bs[SCAN_T][STATE];
    __shared__ float xs[SCAN_T][HEADDIM];
    __shared__ float dts[SCAN_T];

    float state[64];
    #pragma unroll
    for (int j = 0; j < 64; j++) state[j] = 0.f;
    float cdec = 1.f;

    const float Aneg = -expf(A_log[h]);
    const float dtb  = dt_bias[h];
    const size_t base_conv = (size_t)b * SEQ * CONV_DIM;
    const size_t base_z    = (size_t)b * SEQ * D_IN_PROJ;
    const int tstart = chunk * CLEN;

    for (int t0 = tstart; t0 < tstart + CLEN; t0 += SCAN_T) {
        __syncthreads();
        for (int idx = tid; idx < SCAN_T * STATE; idx += 128) {
            const int tt = idx >> 7;
            const int n  = idx & 127;
            Bs[tt][n] = conv[base_conv + (size_t)(t0 + tt) * CONV_DIM + D_INNER + n];
        }
        for (int idx = tid; idx < SCAN_T * HEADDIM; idx += 128) {
            const int tt = idx >> 6;
            const int pp = idx & 63;
            xs[tt][pp] = conv[base_conv + (size_t)(t0 + tt) * CONV_DIM + h * HEADDIM + pp];
        }
        if (tid < SCAN_T)
            dts[tid] = zx[base_z + (size_t)(t0 + tid) * D_IN_PROJ + D_INNER + CONV_DIM + h];
        __syncthreads();

        #pragma unroll 1
        for (int tt = 0; tt < SCAN_T; tt++) {
            const float draw = dts[tt] + dtb;
            const float dtp = (draw > 20.f) ? draw : log1pf(expf(draw));
            const float dA = expf(dtp * Aneg);
            cdec *= dA;
            const float k = dtp * xs[tt][p];
            const float4* Bv = (const float4*)&Bs[tt][n0];
            #pragma unroll
            for (int jj = 0; jj < 16; jj++) {
                const float4 bv = Bv[jj];
                float* st = &state[jj * 4];
                st[0] = st[0] * dA + k * bv.x;
                st[1] = st[1] * dA + k * bv.y;
                st[2] = st[2] * dA + k * bv.z;
                st[3] = st[3] * dA + k * bv.w;
            }
        }
    }

    float* dst = g_slocal + ((size_t)(bh * NCHUNK + chunk) * HEADDIM + p) * STATE + n0;
    #pragma unroll
    for (int jj = 0; jj < 16; jj++)
        ((float4*)dst)[jj] = make_float4(state[jj * 4], state[jj * 4 + 1],
                                         state[jj * 4 + 2], state[jj * 4 + 3]);
    if (tid == 0) g_cdec[bh * NCHUNK + chunk] = cdec;
}

// Phase 2: sequential chunk combine (scalar decay per chunk). Grid: B*H.
__global__ __launch_bounds__(256) void scan_combine_kernel()
{
    const int bh = blockIdx.x;
    const int tid = threadIdx.x;
    float s[32];
    #pragma unroll
    for (int j = 0; j < 32; j++) s[j] = 0.f;

    for (int c = 0; c < NCHUNK; c++) {
        float* dst = g_sin + (size_t)(bh * NCHUNK + c) * (HEADDIM * STATE);
        if (c > 0) {
            const float D = g_cdec[bh * NCHUNK + c - 1];
            const float* src = g_slocal + (size_t)(bh * NCHUNK + c - 1) * (HEADDIM * STATE);
            #pragma unroll
            for (int j = 0; j < 32; j++)
                s[j] = D * s[j] + src[j * 256 + tid];
        }
        #pragma unroll
        for (int j = 0; j < 32; j++)
            dst[j * 256 + tid] = s[j];
    }
}

// Phase 3: per-chunk scan with proper initial state; emits gated y (hi/lo).
__global__ __launch_bounds__(128) void scan_apply_kernel(
    const float* __restrict__ conv, const float* __restrict__ zx,
    const float* __restrict__ dt_bias, const float* __restrict__ A_log,
    const float* __restrict__ D_param,
    __nv_bfloat16* __restrict__ yh, __nv_bfloat16* __restrict__ yl)
{
    const int chunk = blockIdx.x;
    const int bh = blockIdx.y;
    const int b = bh >> 5;
    const int h = bh & 31;
    const int tid = threadIdx.x;
    const int p = tid >> 1;
    const int half = tid & 1;
    const int n0 = half * 64;

    __shared__ float Bs[SCAN_T][STATE];
    __shared__ float Cs[SCAN_T][STATE];
    __shared__ float xs[SCAN_T][HEADDIM];
    __shared__ float zs[SCAN_T][HEADDIM];
    __shared__ float dts[SCAN_T];

    float state[64];
    {
        const float* src = g_sin + ((size_t)(bh * NCHUNK + chunk) * HEADDIM + p) * STATE + n0;
        #pragma unroll
        for (int jj = 0; jj < 16; jj++) {
            const float4 v = ((const float4*)src)[jj];
            state[jj * 4] = v.x; state[jj * 4 + 1] = v.y;
            state[jj * 4 + 2] = v.z; state[jj * 4 + 3] = v.w;
        }
    }

    const float Aneg = -expf(A_log[h]);
    const float dtb  = dt_bias[h];
    const float Dp   = D_param[h];
    const size_t base_conv = (size_t)b * SEQ * CONV_DIM;
    const size_t base_z    = (size_t)b * SEQ * D_IN_PROJ;
    const int tstart = chunk * CLEN;

    for (int t0 = tstart; t0 < tstart + CLEN; t0 += SCAN_T) {
        __syncthreads();
        for (int idx = tid; idx < SCAN_T * STATE; idx += 128) {
            const int tt = idx >> 7;
            const int n  = idx & 127;
            const size_t rowp = base_conv + (size_t)(t0 + tt) * CONV_DIM;
            Bs[tt][n] = conv[rowp + D_INNER + n];
            Cs[tt][n] = conv[rowp + D_INNER + STATE + n];
        }
        for (int idx = tid; idx < SCAN_T * HEADDIM; idx += 128) {
            const int tt = idx >> 6;
            const int pp = idx & 63;
            xs[tt][pp] = conv[base_conv + (size_t)(t0 + tt) * CONV_DIM + h * HEADDIM + pp];
            zs[tt][pp] = zx[base_z + (size_t)(t0 + tt) * D_IN_PROJ + h * HEADDIM + pp];
        }
        if (tid < SCAN_T)
            dts[tid] = zx[base_z + (size_t)(t0 + tid) * D_IN_PROJ + D_INNER + CONV_DIM + h];
        __syncthreads();

        #pragma unroll 1
        for (int tt = 0; tt < SCAN_T; tt++) {
            const float draw = dts[tt] + dtb;
            const float dtp = (draw > 20.f) ? draw : log1pf(expf(draw));
            const float dA = expf(dtp * Aneg);
            const float xv = xs[tt][p];
            const float k = dtp * xv;
            float y0 = 0.f, y1 = 0.f, y2 = 0.f, y3 = 0.f;
            const float4* Bv = (const float4*)&Bs[tt][n0];
            const float4* Cv = (const float4*)&Cs[tt][n0];
            #pragma unroll
            for (int jj = 0; jj < 16; jj++) {
                const float4 bv = Bv[jj];
                const float4 cv = Cv[jj];
                float* st = &state[jj * 4];
                st[0] = st[0] * dA + k * bv.x; y0 += st[0] * cv.x;
                st[1] = st[1] * dA + k * bv.y; y1 += st[1] * cv.y;
                st[2] = st[2] * dA + k * bv.z; y2 += st[2] * cv.z;
                st[3] = st[3] * dA + k * bv.w; y3 += st[3] * cv.w;
            }
            float y = (y0 + y1) + (y2 + y3);
            y += __shfl_xor_sync(0xffffffffu, y, 1);
            if (half == 0) {
                const float zv = zs[tt][p];
                const float gate = zv / (1.f + expf(-zv));
                const float yo = (y + Dp * xv) * gate;
                const size_t oidx =
                    ((size_t)(b * SEQ + t0 + tt)) * D_INNER + h * HEADDIM + p;
                const __nv_bfloat16 hh = __float2bfloat16(yo);
                yh[oidx] = hh;
                yl[oidx] = __float2bfloat16(yo - __bfloat162float(hh));
            }
        }
    }
}

// ---------------------------------------------------------------------------
// SwiGLU: out = silu(g) * u, output as (hi, lo) bf16. 4 elems/thread.
// ---------------------------------------------------------------------------
__global__ __launch_bounds__(256) void swiglu_kernel(
    const float* __restrict__ g, const float* __restrict__ u,
    __nv_bfloat16* __restrict__ oh, __nv_bfloat16* __restrict__ ol, size_t n4)
{
    const size_t id = (size_t)blockIdx.x * 256 + threadIdx.x;
    if (id >= n4) return;
    const float4 gv = ((const float4*)g)[id];
    const float4 uv = ((const float4*)u)[id];
    float4 v;
    v.x = gv.x / (1.f + expf(-gv.x)) * uv.x;
    v.y = gv.y / (1.f + expf(-gv.y)) * uv.y;
    v.z = gv.z / (1.f + expf(-gv.z)) * uv.z;
    v.w = gv.w / (1.f + expf(-gv.w)) * uv.w;
    store_hilo4(oh, ol, id * 4, v);
}

// ---------------------------------------------------------------------------
// Launch
// ---------------------------------------------------------------------------
extern "C" void kernel_launch(void* const* d_in, const int* in_sizes, int n_in,
                              void* d_out, int out_size)
{
    const float* hidden     = (const float*)d_in[0];
    const float* residual   = (const float*)d_in[1];
    const float* ssm_norm_w = (const float*)d_in[2];
    const float* mlp_norm_w = (const float*)d_in[3];
    const float* in_proj_w  = (const float*)d_in[4];
    const float* conv_w     = (const float*)d_in[5];
    const float* conv_b     = (const float*)d_in[6];
    const float* dt_bias    = (const float*)d_in[7];
    const float* A_log      = (const float*)d_in[8];
    const float* D_param    = (const float*)d_in[9];
    const float* out_proj_w = (const float*)d_in[10];
    const float* mlp_gate_w = (const float*)d_in[11];
    const float* mlp_up_w   = (const float*)d_in[12];
    const float* mlp_down_w = (const float*)d_in[13];

    float* out_h   = (float*)d_out;
    float* out_res = out_h + (size_t)ROWS * D_MODEL;

    void *p_res1, *p_zx, *p_conv, *p_h2, *p_gate, *p_up;
    void *p_nh, *p_nl, *p_yh, *p_yl, *p_ah, *p_al;
    void *p_wih, *p_wil, *p_woh, *p_wol, *p_wgh, *p_wgl, *p_wuh, *p_wul, *p_wdh, *p_wdl;
    cudaGetSymbolAddress(&p_res1, g_res1);
    cudaGetSymbolAddress(&p_zx,   g_zx);
    cudaGetSymbolAddress(&p_conv, g_conv);
    cudaGetSymbolAddress(&p_h2,   g_h2);
    cudaGetSymbolAddress(&p_gate, g_gate);
    cudaGetSymbolAddress(&p_up,   g_up);
    cudaGetSymbolAddress(&p_nh,   g_normh);
    cudaGetSymbolAddress(&p_nl,   g_norml);
    cudaGetSymbolAddress(&p_yh,   g_yh);
    cudaGetSymbolAddress(&p_yl,   g_yl);
    cudaGetSymbolAddress(&p_ah,   g_acth);
    cudaGetSymbolAddress(&p_al,   g_actl);
    cudaGetSymbolAddress(&p_wih,  g_wih);
    cudaGetSymbolAddress(&p_wil,  g_wil);
    cudaGetSymbolAddress(&p_woh,  g_woh);
    cudaGetSymbolAddress(&p_wol,  g_wol);
    cudaGetSymbolAddress(&p_wgh,  g_wgh);
    cudaGetSymbolAddress(&p_wgl,  g_wgl);
    cudaGetSymbolAddress(&p_wuh,  g_wuh);
    cudaGetSymbolAddress(&p_wul,  g_wul);
    cudaGetSymbolAddress(&p_wdh,  g_wdh);
    cudaGetSymbolAddress(&p_wdl,  g_wdl);

    cudaFuncSetAttribute(gemm_bf16x2, cudaFuncAttributeMaxDynamicSharedMemorySize,
                         GEMM_SMEM);

    // Weight conversions (hi/lo split + padding), float4-vectorized
    {
        size_t nr, nt;
        nr = (size_t)D_IN_PROJ * D_MODEL / 4; nt = (size_t)N_INPROJ_PAD * D_MODEL / 4;
        cvt_weight_kernel<<<(unsigned)((nt + 255) / 256), 256>>>(
            in_proj_w, (__nv_bfloat16*)p_wih, (__nv_bfloat16*)p_wil, nr, nt);
        nr = nt = (size_t)D_MODEL * D_INNER / 4;
        cvt_weight_kernel<<<(unsigned)((nt + 255) / 256), 256>>>(
            out_proj_w, (__nv_bfloat16*)p_woh, (__nv_bfloat16*)p_wol, nr, nt);
        nr = nt = (size_t)MLP_INNER * D_MODEL / 4;
        cvt_weight_kernel<<<(unsigned)((nt + 255) / 256), 256>>>(
            mlp_gate_w, (__nv_bfloat16*)p_wgh, (__nv_bfloat16*)p_wgl, nr, nt);
        cvt_weight_kernel<<<(unsigned)((nt + 255) / 256), 256>>>(
            mlp_up_w, (__nv_bfloat16*)p_wuh, (__nv_bfloat16*)p_wul, nr, nt);
        nr = nt = (size_t)D_MODEL * MLP_INNER / 4;
        cvt_weight_kernel<<<(unsigned)((nt + 255) / 256), 256>>>(
            mlp_down_w, (__nv_bfloat16*)p_wdh, (__nv_bfloat16*)p_wdl, nr, nt);
    }

    // 1) prenorm RMSNorm #1
    rmsnorm_prenorm_kernel<<<ROWS, 256>>>(hidden, residual, ssm_norm_w,
        (float*)p_res1, (__nv_bfloat16*)p_nh, (__nv_bfloat16*)p_nl);
    // 2) in_proj
    gemm_bf16x2<<<dim3(N_INPROJ_PAD / 256, ROWS / 128), 512, GEMM_SMEM>>>(
        (const __nv_bfloat16*)p_nh, (const __nv_bfloat16*)p_nl,
        (const __nv_bfloat16*)p_wih, (const __nv_bfloat16*)p_wil,
        (float*)p_zx, ROWS, D_IN_PROJ, D_MODEL);
    // 3) causal depthwise conv + SiLU
    conv_silu_kernel<<<(unsigned)(((size_t)ROWS * CONV_DIM + 255) / 256), 256>>>(
        (const float*)p_zx, conv_w, conv_b, (float*)p_conv);
    // 4) chunked selective scan (3 phases)
    scan_local_kernel<<<dim3(NCHUNK, BATCH * NHEADS), 128>>>(
        (const float*)p_conv, (const float*)p_zx, dt_bias, A_log);
    scan_combine_kernel<<<BATCH * NHEADS, 256>>>();
    scan_apply_kernel<<<dim3(NCHUNK, BATCH * NHEADS), 128>>>(
        (const float*)p_conv, (const float*)p_zx, dt_bias, A_log, D_param,
        (__nv_bfloat16*)p_yh, (__nv_bfloat16*)p_yl);
    // 5) out_proj
    gemm_bf16x2<<<dim3(D_MODEL / 256, ROWS / 128), 512, GEMM_SMEM>>>(
        (const __nv_bfloat16*)p_yh, (const __nv_bfloat16*)p_yl,
        (const __nv_bfloat16*)p_woh, (const __nv_bfloat16*)p_wol,
        (float*)p_h2, ROWS, D_MODEL, D_INNER);
    // 6) prenorm RMSNorm #2
    rmsnorm_prenorm_kernel<<<ROWS, 256>>>((const float*)p_h2, (const float*)p_res1,
        mlp_norm_w, out_res, (__nv_bfloat16*)p_nh, (__nv_bfloat16*)p_nl);
    // 7) MLP gate & up
    gemm_bf16x2<<<dim3(MLP_INNER / 256, ROWS / 128), 512, GEMM_SMEM>>>(
        (const __nv_bfloat16*)p_nh, (const __nv_bfloat16*)p_nl,
        (const __nv_bfloat16*)p_wgh, (const __nv_bfloat16*)p_wgl,
        (float*)p_gate, ROWS, MLP_INNER, D_MODEL);
    gemm_bf16x2<<<dim3(MLP_INNER / 256, ROWS / 128), 512, GEMM_SMEM>>>(
        (const __nv_bfloat16*)p_nh, (const __nv_bfloat16*)p_nl,
        (const __nv_bfloat16*)p_wuh, (const __nv_bfloat16*)p_wul,
        (float*)p_up, ROWS, MLP_INNER, D_MODEL);
    // 8) SwiGLU
    swiglu_kernel<<<(unsigned)(((size_t)ROWS * MLP_INNER / 4 + 255) / 256), 256>>>(
        (const float*)p_gate, (const float*)p_up,
        (__nv_bfloat16*)p_ah, (__nv_bfloat16*)p_al, (size_t)ROWS * MLP_INNER / 4);
    // 9) down projection -> first model output
    gemm_bf16x2<<<dim3(D_MODEL / 256, ROWS / 128), 512, GEMM_SMEM>>>(
        (const __nv_bfloat16*)p_ah, (const __nv_bfloat16*)p_al,
        (const __nv_bfloat16*)p_wdh, (const __nv_bfloat16*)p_wdl,
        out_h, ROWS, D_MODEL, MLP_INNER);
}

// round 7
// speedup vs baseline: 3.1927x; 1.0182x over previous
#include <cuda_runtime.h>
#include <cuda_bf16.h>
#include <math.h>
#include <stdint.h>

// ---------------------------------------------------------------------------
// Problem constants
// ---------------------------------------------------------------------------
#define BATCH     2
#define SEQ       4096
#define ROWS      (BATCH * SEQ)          // 8192 tokens
#define D_MODEL   1024
#define STATE     128
#define HEADDIM   64
#define D_INNER   2048
#define NHEADS    32
#define CONV_DIM  (D_INNER + 2 * STATE)  // 2304
#define D_IN_PROJ (2 * D_INNER + 2 * STATE + NHEADS) // 4384
#define N_INPROJ_PAD 4608                // padded to multiple of 256
#define MLP_INNER 4096
#define MLP_2X    (2 * MLP_INNER)        // interleaved gate/up
#define EPS       1e-5f
#define NCHUNK    32
#define CLEN      128                    // SEQ / NCHUNK

// ---------------------------------------------------------------------------
// Scratch (static device arrays; no runtime allocation allowed)
// ---------------------------------------------------------------------------
__device__ float g_res1  [(size_t)ROWS * D_MODEL];
__device__ float g_zx    [(size_t)ROWS * D_IN_PROJ];
__device__ float g_conv  [(size_t)ROWS * CONV_DIM];
__device__ float g_h2    [(size_t)ROWS * D_MODEL];

__device__ float g_slocal[(size_t)BATCH * NHEADS * NCHUNK * HEADDIM * STATE];
__device__ float g_sin   [(size_t)BATCH * NHEADS * NCHUNK * HEADDIM * STATE];
__device__ float g_cdec  [BATCH * NHEADS * NCHUNK];

__device__ __nv_bfloat16 g_normh[(size_t)ROWS * D_MODEL];
__device__ __nv_bfloat16 g_norml[(size_t)ROWS * D_MODEL];
__device__ __nv_bfloat16 g_yh   [(size_t)ROWS * D_INNER];
__device__ __nv_bfloat16 g_yl   [(size_t)ROWS * D_INNER];
__device__ __nv_bfloat16 g_acth [(size_t)ROWS * MLP_INNER];
__device__ __nv_bfloat16 g_actl [(size_t)ROWS * MLP_INNER];

__device__ __nv_bfloat16 g_wih[(size_t)N_INPROJ_PAD * D_MODEL];
__device__ __nv_bfloat16 g_wil[(size_t)N_INPROJ_PAD * D_MODEL];
__device__ __nv_bfloat16 g_woh[(size_t)D_MODEL * D_INNER];
__device__ __nv_bfloat16 g_wol[(size_t)D_MODEL * D_INNER];
__device__ __nv_bfloat16 g_wmh[(size_t)MLP_2X * D_MODEL];   // interleaved gate/up hi
__device__ __nv_bfloat16 g_wml[(size_t)MLP_2X * D_MODEL];   // interleaved gate/up lo
__device__ __nv_bfloat16 g_wdh[(size_t)D_MODEL * MLP_INNER];
__device__ __nv_bfloat16 g_wdl[(size_t)D_MODEL * MLP_INNER];

// ---------------------------------------------------------------------------
// PTX helpers (baseline sm_103: cp.async + ldmatrix + mma.sync)
// ---------------------------------------------------------------------------
__device__ __forceinline__ uint32_t smem_u32(const void* p) {
    uint32_t a;
    asm("{ .reg .u64 t; cvta.to.shared.u64 t, %1; cvt.u32.u64 %0, t; }"
        : "=r"(a) : "l"(p));
    return a;
}
__device__ __forceinline__ void cp_async16(uint32_t dst, const void* src) {
    asm volatile("cp.async.cg.shared.global [%0], [%1], 16;\n" :: "r"(dst), "l"(src));
}
__device__ __forceinline__ void cp_commit() {
    asm volatile("cp.async.commit_group;\n" ::: "memory");
}
template <int N>
__device__ __forceinline__ void cp_wait() {
    asm volatile("cp.async.wait_group %0;\n" :: "n"(N) : "memory");
}
__device__ __forceinline__ void ldmx4(uint32_t* r, uint32_t addr) {
    asm volatile("ldmatrix.sync.aligned.m8n8.x4.shared.b16 {%0,%1,%2,%3}, [%4];"
                 : "=r"(r[0]), "=r"(r[1]), "=r"(r[2]), "=r"(r[3]) : "r"(addr));
}
__device__ __forceinline__ void mma_bf16(float* c, const uint32_t* a, const uint32_t* b) {
    asm volatile(
        "mma.sync.aligned.m16n8k16.row.col.f32.bf16.bf16.f32 "
        "{%0,%1,%2,%3}, {%4,%5,%6,%7}, {%8,%9}, {%0,%1,%2,%3};"
        : "+f"(c[0]), "+f"(c[1]), "+f"(c[2]), "+f"(c[3])
        : "r"(a[0]), "r"(a[1]), "r"(a[2]), "r"(a[3]), "r"(b[0]), "r"(b[1]));
}

// ---------------------------------------------------------------------------
// Split-bf16 tensor-core GEMM: C[M,N] = A[M,K] @ W[N,K]^T
// A,W as (hi, lo) bf16 pairs; 3 MMAs (drop Al*Bl only).
// 128x256 CTA tile, BK=32, 512 threads (16 warps, 32x64 each), 3 stages.
// Term-major MMA ordering over jp-pairs: same-accumulator reuse distance = 8.
// SWIGLU=true: N covers interleaved (gate,up) pairs; epilogue emits
//   silu(gate)*up as (hi,lo) bf16 into OutH/OutL with N/2 columns.
// ---------------------------------------------------------------------------
#define GSTAGE   3
#define ROWB     80
#define A_TILE_B (128 * ROWB)            // 10240
#define W_TILE_B (256 * ROWB)            // 20480
#define STAGE_B  (2 * A_TILE_B + 2 * W_TILE_B)  // 61440
#define GEMM_SMEM (GSTAGE * STAGE_B)     // 184320

__device__ __forceinline__ void load_stage_g(
    uint32_t sbase,
    const __nv_bfloat16* __restrict__ Ah, const __nv_bfloat16* __restrict__ Al,
    const __nv_bfloat16* __restrict__ Wh, const __nv_bfloat16* __restrict__ Wl,
    int bm, int bn, int K, int kc, int tid)
{
    const int koff = kc * 32;
    {
        const int row = tid >> 2, ch = tid & 3;
        const uint32_t d = (uint32_t)(row * ROWB + ch * 16);
        const size_t ao = (size_t)(bm + row) * K + koff + ch * 8;
        cp_async16(sbase + d, Ah + ao);
        cp_async16(sbase + A_TILE_B + d, Al + ao);
    }
    #pragma unroll
    for (int i = 0; i < 2; i++) {
        const int slot = tid + i * 512;
        const int row = slot >> 2, ch = slot & 3;
        const uint32_t d = (uint32_t)(row * ROWB + ch * 16);
        const size_t bo = (size_t)(bn + row) * K + koff + ch * 8;
        cp_async16(sbase + 2 * A_TILE_B + d, Wh + bo);
        cp_async16(sbase + 2 * A_TILE_B + W_TILE_B + d, Wl + bo);
    }
}

template <bool SWIGLU>
__global__ __launch_bounds__(512, 1)
void gemm_bf16x2(const __nv_bfloat16* __restrict__ Ah,
                 const __nv_bfloat16* __restrict__ Al,
                 const __nv_bfloat16* __restrict__ Wh,
                 const __nv_bfloat16* __restrict__ Wl,
                 float* __restrict__ C,
                 __nv_bfloat16* __restrict__ OutH,
                 __nv_bfloat16* __restrict__ OutL,
                 int M, int N, int K)
{
    extern __shared__ __align__(128) char dynsmem[];
    const uint32_t sbase = smem_u32(dynsmem);

    const int tid  = threadIdx.x;
    const int lane = tid & 31;
    const int wid  = tid >> 5;
    const int wm   = wid & 3;             // 4 m-groups of 32 rows
    const int wn   = wid >> 2;            // 4 n-groups of 64 cols
    const int bm   = blockIdx.y * 128;
    const int bn   = blockIdx.x * 256;

    const uint32_t a_off = (uint32_t)((wm * 32 + (lane & 15)) * ROWB
                                      + ((lane >> 4) & 1) * 16);
    const uint32_t b_off = (uint32_t)((wn * 64 + ((lane >> 4) & 1) * 8 + (lane & 7)) * ROWB
                                      + ((lane >> 3) & 1) * 16);

    float acc[2][8][4];
    #pragma unroll
    for (int i = 0; i < 2; i++)
        #pragma unroll
        for (int j = 0; j < 8; j++)
            #pragma unroll
            for (int q = 0; q < 4; q++) acc[i][j][q] = 0.f;

    const int nk = K >> 5;

    load_stage_g(sbase + 0 * STAGE_B, Ah, Al, Wh, Wl, bm, bn, K, 0, tid);
    cp_commit();
    load_stage_g(sbase + 1 * STAGE_B, Ah, Al, Wh, Wl, bm, bn, K, 1, tid);
    cp_commit();

    for (int k = 0; k < nk; k++) {
        const uint32_t stb = sbase + (uint32_t)(k % GSTAGE) * STAGE_B;
        cp_wait<1>();
        __syncthreads();

        const int kn = k + 2;
        if (kn < nk)
            load_stage_g(sbase + (uint32_t)(kn % GSTAGE) * STAGE_B,
                         Ah, Al, Wh, Wl, bm, bn, K, kn, tid);
        cp_commit();

        const uint32_t a_h = stb + a_off;
        const uint32_t a_l = stb + A_TILE_B + a_off;
        const uint32_t b_h = stb + 2 * A_TILE_B + b_off;
        const uint32_t b_l = stb + 2 * A_TILE_B + W_TILE_B + b_off;

        #pragma unroll
        for (int s = 0; s < 2; s++) {
            const uint32_t kb = (uint32_t)(s * 32);
            uint32_t ahf[2][4], alf[2][4];
            #pragma unroll
            for (int i = 0; i < 2; i++) {
                ldmx4(ahf[i], a_h + (uint32_t)(i * 16 * ROWB) + kb);
                ldmx4(alf[i], a_l + (uint32_t)(i * 16 * ROWB) + kb);
            }
            // Process jp tiles in pairs; within a pair issue each split term
            // as a pass over 8 distinct accumulators (RAW distance = 8 mma).
            #pragma unroll
            for (int jph = 0; jph < 2; jph++) {
                uint32_t whf[2][4], wlf[2][4];
                #pragma unroll
                for (int q = 0; q < 2; q++) {
                    ldmx4(whf[q], b_h + (uint32_t)((jph * 2 + q) * 16 * ROWB) + kb);
                    ldmx4(wlf[q], b_l + (uint32_t)((jph * 2 + q) * 16 * ROWB) + kb);
                }
                // term hh
                #pragma unroll
                for (int q = 0; q < 2; q++)
                    #pragma unroll
                    for (int i = 0; i < 2; i++)
                        #pragma unroll
                        for (int f = 0; f < 2; f++)
                            mma_bf16(acc[i][(jph * 2 + q) * 2 + f], ahf[i], whf[q] + f * 2);
                // term hl
                #pragma unroll
                for (int q = 0; q < 2; q++)
                    #pragma unroll
                    for (int i = 0; i < 2; i++)
                        #pragma unroll
                        for (int f = 0; f < 2; f++)
                            mma_bf16(acc[i][(jph * 2 + q) * 2 + f], ahf[i], wlf[q] + f * 2);
                // term lh
                #pragma unroll
                for (int q = 0; q < 2; q++)
                    #pragma unroll
                    for (int i = 0; i < 2; i++)
                        #pragma unroll
                        for (int f = 0; f < 2; f++)
                            mma_bf16(acc[i][(jph * 2 + q) * 2 + f], alf[i], whf[q] + f * 2);
            }
        }
    }

    if (!SWIGLU) {
        #pragma unroll
        for (int i = 0; i < 2; i++) {
            const int row = bm + wm * 32 + i * 16 + (lane >> 2);
            #pragma unroll
            for (int j = 0; j < 8; j++) {
                const int col = bn + wn * 64 + j * 8 + (lane & 3) * 2;
                if (col < N) {
                    *(float2*)&C[(size_t)row * N + col] =
                        make_float2(acc[i][j][0], acc[i][j][1]);
                    *(float2*)&C[(size_t)(row + 8) * N + col] =
                        make_float2(acc[i][j][2], acc[i][j][3]);
                }
            }
        }
    } else {
        // Columns are interleaved (gate, up) pairs: acc[..][0]=gate, [1]=up
        // (and [2],[3] for row+8). Output column index = col/2, width N/2.
        const int NO = N >> 1;
        #pragma unroll
        for (int i = 0; i < 2; i++) {
            const int row = bm + wm * 32 + i * 16 + (lane >> 2);
            #pragma unroll
            for (int j = 0; j < 8; j++) {
                const int colc = (bn + wn * 64 + j * 8 + (lane & 3) * 2) >> 1;
                {
                    const float g = acc[i][j][0], u = acc[i][j][1];
                    const float v = g / (1.f + expf(-g)) * u;
                    const __nv_bfloat16 h = __float2bfloat16(v);
                    OutH[(size_t)row * NO + colc] = h;
                    OutL[(size_t)row * NO + colc] =
                        __float2bfloat16(v - __bfloat162float(h));
                }
                {
                    const float g = acc[i][j][2], u = acc[i][j][3];
                    const float v = g / (1.f + expf(-g)) * u;
                    const __nv_bfloat16 h = __float2bfloat16(v);
                    OutH[(size_t)(row + 8) * NO + colc] = h;
                    OutL[(size_t)(row + 8) * NO + colc] =
                        __float2bfloat16(v - __bfloat162float(h));
                }
            }
        }
    }
}

// ---------------------------------------------------------------------------
// hi/lo helpers
// ---------------------------------------------------------------------------
__device__ __forceinline__ void store_hilo4(
    __nv_bfloat16* __restrict__ hi, __nv_bfloat16* __restrict__ lo,
    size_t off, float4 v)
{
    __nv_bfloat16 h0 = __float2bfloat16(v.x), h1 = __float2bfloat16(v.y);
    __nv_bfloat16 h2 = __float2bfloat16(v.z), h3 = __float2bfloat16(v.w);
    __nv_bfloat162 hh0; hh0.x = h0; hh0.y = h1;
    __nv_bfloat162 hh1; hh1.x = h2; hh1.y = h3;
    *(__nv_bfloat162*)(hi + off)     = hh0;
    *(__nv_bfloat162*)(hi + off + 2) = hh1;
    __nv_bfloat162 ll0, ll1;
    ll0.x = __float2bfloat16(v.x - __bfloat162float(h0));
    ll0.y = __float2bfloat16(v.y - __bfloat162float(h1));
    ll1.x = __float2bfloat16(v.z - __bfloat162float(h2));
    ll1.y = __float2bfloat16(v.w - __bfloat162float(h3));
    *(__nv_bfloat162*)(lo + off)     = ll0;
    *(__nv_bfloat162*)(lo + off + 2) = ll1;
}

// Weight fp32 -> (hi, lo) bf16, float4-vectorized, zero tail padding.
__global__ __launch_bounds__(256) void cvt_weight_kernel(
    const float* __restrict__ w, __nv_bfloat16* __restrict__ hi,
    __nv_bfloat16* __restrict__ lo, size_t n_real4, size_t n_total4)
{
    const size_t i = (size_t)blockIdx.x * 256 + threadIdx.x;
    if (i >= n_total4) return;
    float4 v = (i < n_real4) ? ((const float4*)w)[i]
                             : make_float4(0.f, 0.f, 0.f, 0.f);
    store_hilo4(hi, lo, i * 4, v);
}

// gate/up weights -> row-interleaved combined (hi, lo): row 2j = gate_j, 2j+1 = up_j.
#define K4 (D_MODEL / 4)
__global__ __launch_bounds__(256) void cvt_weight_pair_kernel(
    const float* __restrict__ wg, const float* __restrict__ wu,
    __nv_bfloat16* __restrict__ hi, __nv_bfloat16* __restrict__ lo)
{
    const size_t i = (size_t)blockIdx.x * 256 + threadIdx.x;   // float4 index
    if (i >= (size_t)MLP_2X * K4) return;
    const size_t n = i / K4;          // interleaved row
    const size_t k4 = i % K4;
    const size_t srow = n >> 1;
    const float4 v = (n & 1) ? ((const float4*)wu)[srow * K4 + k4]
                             : ((const float4*)wg)[srow * K4 + k4];
    store_hilo4(hi, lo, i * 4, v);
}

// ---------------------------------------------------------------------------
// Fused residual-add + RMSNorm; norm output as (hi, lo) bf16.
// ---------------------------------------------------------------------------
__global__ __launch_bounds__(256) void rmsnorm_prenorm_kernel(
    const float* __restrict__ x, const float* __restrict__ res_in,
    const float* __restrict__ w, float* __restrict__ res_out,
    __nv_bfloat16* __restrict__ nh, __nv_bfloat16* __restrict__ nl)
{
    const size_t row = blockIdx.x;
    const int tid = threadIdx.x;
    const float4 xv = ((const float4*)(x      + row * D_MODEL))[tid];
    const float4 rv = ((const float4*)(res_in + row * D_MODEL))[tid];
    float4 s;
    s.x = xv.x + rv.x; s.y = xv.y + rv.y; s.z = xv.z + rv.z; s.w = xv.w + rv.w;
    float ss = s.x * s.x + s.y * s.y + s.z * s.z + s.w * s.w;

    #pragma unroll
    for (int o = 16; o > 0; o >>= 1) ss += __shfl_down_sync(0xffffffffu, ss, o);
    __shared__ float red[8];
    __shared__ float scale_sh;
    if ((tid & 31) == 0) red[tid >> 5] = ss;
    __syncthreads();
    if (tid == 0) {
        float t = 0.f;
        #pragma unroll
        for (int i = 0; i < 8; i++) t += red[i];
        scale_sh = rsqrtf(t / (float)D_MODEL + EPS);
    }
    __syncthreads();
    const float scale = scale_sh;

    ((float4*)(res_out + row * D_MODEL))[tid] = s;
    const float4 wv = ((const float4*)w)[tid];
    float4 o;
    o.x = s.x * scale * wv.x; o.y = s.y * scale * wv.y;
    o.z = s.z * scale * wv.z; o.w = s.w * scale * wv.w;
    store_hilo4(nh, nl, row * D_MODEL + (size_t)tid * 4, o);
}

// ---------------------------------------------------------------------------
// Causal depthwise conv1d (width 4) + SiLU over the xBC slice of zxbcdt.
// ---------------------------------------------------------------------------
__global__ __launch_bounds__(256) void conv_silu_kernel(
    const float* __restrict__ zx, const float* __restrict__ cw,
    const float* __restrict__ cb, float* __restrict__ out)
{
    const size_t id = (size_t)blockIdx.x * 256 + threadIdx.x;
    if (id >= (size_t)ROWS * CONV_DIM) return;
    const int c = (int)(id % CONV_DIM);
    const size_t r = id / CONV_DIM;
    const int l = (int)(r & (SEQ - 1));
    const float* base = zx + r * D_IN_PROJ + D_INNER + c;

    const float w0 = cw[c * 4 + 0], w1 = cw[c * 4 + 1];
    const float w2 = cw[c * 4 + 2], w3 = cw[c * 4 + 3];
    float acc = cb[c];
    if (l >= 3) acc += base[-3L * D_IN_PROJ] * w0;
    if (l >= 2) acc += base[-2L * D_IN_PROJ] * w1;
    if (l >= 1) acc += base[-1L * D_IN_PROJ] * w2;
    acc += base[0] * w3;
    out[id] = acc / (1.f + expf(-acc));
}

// ---------------------------------------------------------------------------
// Chunked selective scan. Phase 1: per-chunk local scan (zero init state),
// writes final local state + chunk decay product. Grid: (NCHUNK, B*H).
// ---------------------------------------------------------------------------
#define SCAN_T 8
__global__ __launch_bounds__(128) void scan_local_kernel(
    const float* __restrict__ conv, const float* __restrict__ zx,
    const float* __restrict__ dt_bias, const float* __restrict__ A_log)
{
    const int chunk = blockIdx.x;
    const int bh = blockIdx.y;
    const int b = bh >> 5;
    const int h = bh & 31;
    const int tid = threadIdx.x;
    const int p = tid >> 1;
    const int half = tid & 1;
    const int n0 = half * 64;

    __shared__ float Bs[SCAN_T][STATE];
    __shared__ float xs[SCAN_T][HEADDIM];
    __shared__ float dts[SCAN_T];

    float state[64];
    #pragma unroll
    for (int j = 0; j < 64; j++) state[j] = 0.f;
    float cdec = 1.f;

    const float Aneg = -expf(A_log[h]);
    const float dtb  = dt_bias[h];
    const size_t base_conv = (size_t)b * SEQ * CONV_DIM;
    const size_t base_z    = (size_t)b * SEQ * D_IN_PROJ;
    const int tstart = chunk * CLEN;

    for (int t0 = tstart; t0 < tstart + CLEN; t0 += SCAN_T) {
        __syncthreads();
        for (int idx = tid; idx < SCAN_T * STATE; idx += 128) {
            const int tt = idx >> 7;
            const int n  = idx & 127;
            Bs[tt][n] = conv[base_conv + (size_t)(t0 + tt) * CONV_DIM + D_INNER + n];
        }
        for (int idx = tid; idx < SCAN_T * HEADDIM; idx += 128) {
            const int tt = idx >> 6;
            const int pp = idx & 63;
            xs[tt][pp] = conv[base_conv + (size_t)(t0 + tt) * CONV_DIM + h * HEADDIM + pp];
        }
        if (tid < SCAN_T)
            dts[tid] = zx[base_z + (size_t)(t0 + tid) * D_IN_PROJ + D_INNER + CONV_DIM + h];
        __syncthreads();

        #pragma unroll 1
        for (int tt = 0; tt < SCAN_T; tt++) {
            const float draw = dts[tt] + dtb;
            const float dtp = (draw > 20.f) ? draw : log1pf(expf(draw));
            const float dA = expf(dtp * Aneg);
            cdec *= dA;
            const float k = dtp * xs[tt][p];
            const float4* Bv = (const float4*)&Bs[tt][n0];
            #pragma unroll
            for (int jj = 0; jj < 16; jj++) {
                const float4 bv = Bv[jj];
                float* st = &state[jj * 4];
                st[0] = st[0] * dA + k * bv.x;
                st[1] = st[1] * dA + k * bv.y;
                st[2] = st[2] * dA + k * bv.z;
                st[3] = st[3] * dA + k * bv.w;
            }
        }
    }

    float* dst = g_slocal + ((size_t)(bh * NCHUNK + chunk) * HEADDIM + p) * STATE + n0;
    #pragma unroll
    for (int jj = 0; jj < 16; jj++)
        ((float4*)dst)[jj] = make_float4(state[jj * 4], state[jj * 4 + 1],
                                         state[jj * 4 + 2], state[jj * 4 + 3]);
    if (tid == 0) g_cdec[bh * NCHUNK + chunk] = cdec;
}

// Phase 2: sequential chunk combine (scalar decay per chunk). Grid: B*H.
__global__ __launch_bounds__(256) void scan_combine_kernel()
{
    const int bh = blockIdx.x;
    const int tid = threadIdx.x;
    float s[32];
    #pragma unroll
    for (int j = 0; j < 32; j++) s[j] = 0.f;

    for (int c = 0; c < NCHUNK; c++) {
        float* dst = g_sin + (size_t)(bh * NCHUNK + c) * (HEADDIM * STATE);
        if (c > 0) {
            const float D = g_cdec[bh * NCHUNK + c - 1];
            const float* src = g_slocal + (size_t)(bh * NCHUNK + c - 1) * (HEADDIM * STATE);
            #pragma unroll
            for (int j = 0; j < 32; j++)
                s[j] = D * s[j] + src[j * 256 + tid];
        }
        #pragma unroll
        for (int j = 0; j < 32; j++)
            dst[j * 256 + tid] = s[j];
    }
}

// Phase 3: per-chunk scan with proper initial state; emits gated y (hi/lo).
__global__ __launch_bounds__(128) void scan_apply_kernel(
    const float* __restrict__ conv, const float* __restrict__ zx,
    const float* __restrict__ dt_bias, const float* __restrict__ A_log,
    const float* __restrict__ D_param,
    __nv_bfloat16* __restrict__ yh, __nv_bfloat16* __restrict__ yl)
{
    const int chunk = blockIdx.x;
    const int bh = blockIdx.y;
    const int b = bh >> 5;
    const int h = bh & 31;
    const int tid = threadIdx.x;
    const int p = tid >> 1;
    const int half = tid & 1;
    const int n0 = half * 64;

    __shared__ float Bs[SCAN_T][STATE];
    __shared__ float Cs[SCAN_T][STATE];
    __shared__ float xs[SCAN_T][HEADDIM];
    __shared__ float zs[SCAN_T][HEADDIM];
    __shared__ float dts[SCAN_T];

    float state[64];
    {
        const float* src = g_sin + ((size_t)(bh * NCHUNK + chunk) * HEADDIM + p) * STATE + n0;
        #pragma unroll
        for (int jj = 0; jj < 16; jj++) {
            const float4 v = ((const float4*)src)[jj];
            state[jj * 4] = v.x; state[jj * 4 + 1] = v.y;
            state[jj * 4 + 2] = v.z; state[jj * 4 + 3] = v.w;
        }
    }

    const float Aneg = -expf(A_log[h]);
    const float dtb  = dt_bias[h];
    const float Dp   = D_param[h];
    const size_t base_conv = (size_t)b * SEQ * CONV_DIM;
    const size_t base_z    = (size_t)b * SEQ * D_IN_PROJ;
    const int tstart = chunk * CLEN;

    for (int t0 = tstart; t0 < tstart + CLEN; t0 += SCAN_T) {
        __syncthreads();
        for (int idx = tid; idx < SCAN_T * STATE; idx += 128) {
            const int tt = idx >> 7;
            const int n  = idx & 127;
            const size_t rowp = base_conv + (size_t)(t0 + tt) * CONV_DIM;
            Bs[tt][n] = conv[rowp + D_INNER + n];
            Cs[tt][n] = conv[rowp + D_INNER + STATE + n];
        }
        for (int idx = tid; idx < SCAN_T * HEADDIM; idx += 128) {
            const int tt = idx >> 6;
            const int pp = idx & 63;
            xs[tt][pp] = conv[base_conv + (size_t)(t0 + tt) * CONV_DIM + h * HEADDIM + pp];
            zs[tt][pp] = zx[base_z + (size_t)(t0 + tt) * D_IN_PROJ + h * HEADDIM + pp];
        }
        if (tid < SCAN_T)
            dts[tid] = zx[base_z + (size_t)(t0 + tid) * D_IN_PROJ + D_INNER + CONV_DIM + h];
        __syncthreads();

        #pragma unroll 1
        for (int tt = 0; tt < SCAN_T; tt++) {
            const float draw = dts[tt] + dtb;
            const float dtp = (draw > 20.f) ? draw : log1pf(expf(draw));
            const float dA = expf(dtp * Aneg);
            const float xv = xs[tt][p];
            const float k = dtp * xv;
            float y0 = 0.f, y1 = 0.f, y2 = 0.f, y3 = 0.f;
            const float4* Bv = (const float4*)&Bs[tt][n0];
            const float4* Cv = (const float4*)&Cs[tt][n0];
            #pragma unroll
            for (int jj = 0; jj < 16; jj++) {
                const float4 bv = Bv[jj];
                const float4 cv = Cv[jj];
                float* st = &state[jj * 4];
                st[0] = st[0] * dA + k * bv.x; y0 += st[0] * cv.x;
                st[1] = st[1] * dA + k * bv.y; y1 += st[1] * cv.y;
                st[2] = st[2] * dA + k * bv.z; y2 += st[2] * cv.z;
                st[3] = st[3] * dA + k * bv.w; y3 += st[3] * cv.w;
            }
            float y = (y0 + y1) + (y2 + y3);
            y += __shfl_xor_sync(0xffffffffu, y, 1);
            if (half == 0) {
                const float zv = zs[tt][p];
                const float gate = zv / (1.f + expf(-zv));
                const float yo = (y + Dp * xv) * gate;
                const size_t oidx =
                    ((size_t)(b * SEQ + t0 + tt)) * D_INNER + h * HEADDIM + p;
                const __nv_bfloat16 hh = __float2bfloat16(yo);
                yh[oidx] = hh;
                yl[oidx] = __float2bfloat16(yo - __bfloat162float(hh));
            }
        }
    }
}

// ---------------------------------------------------------------------------
// Launch
// ---------------------------------------------------------------------------
extern "C" void kernel_launch(void* const* d_in, const int* in_sizes, int n_in,
                              void* d_out, int out_size)
{
    const float* hidden     = (const float*)d_in[0];
    const float* residual   = (const float*)d_in[1];
    const float* ssm_norm_w = (const float*)d_in[2];
    const float* mlp_norm_w = (const float*)d_in[3];
    const float* in_proj_w  = (const float*)d_in[4];
    const float* conv_w     = (const float*)d_in[5];
    const float* conv_b     = (const float*)d_in[6];
    const float* dt_bias    = (const float*)d_in[7];
    const float* A_log      = (const float*)d_in[8];
    const float* D_param    = (const float*)d_in[9];
    const float* out_proj_w = (const float*)d_in[10];
    const float* mlp_gate_w = (const float*)d_in[11];
    const float* mlp_up_w   = (const float*)d_in[12];
    const float* mlp_down_w = (const float*)d_in[13];

    float* out_h   = (float*)d_out;
    float* out_res = out_h + (size_t)ROWS * D_MODEL;

    void *p_res1, *p_zx, *p_conv, *p_h2;
    void *p_nh, *p_nl, *p_yh, *p_yl, *p_ah, *p_al;
    void *p_wih, *p_wil, *p_woh, *p_wol, *p_wmh, *p_wml, *p_wdh, *p_wdl;
    cudaGetSymbolAddress(&p_res1, g_res1);
    cudaGetSymbolAddress(&p_zx,   g_zx);
    cudaGetSymbolAddress(&p_conv, g_conv);
    cudaGetSymbolAddress(&p_h2,   g_h2);
    cudaGetSymbolAddress(&p_nh,   g_normh);
    cudaGetSymbolAddress(&p_nl,   g_norml);
    cudaGetSymbolAddress(&p_yh,   g_yh);
    cudaGetSymbolAddress(&p_yl,   g_yl);
    cudaGetSymbolAddress(&p_ah,   g_acth);
    cudaGetSymbolAddress(&p_al,   g_actl);
    cudaGetSymbolAddress(&p_wih,  g_wih);
    cudaGetSymbolAddress(&p_wil,  g_wil);
    cudaGetSymbolAddress(&p_woh,  g_woh);
    cudaGetSymbolAddress(&p_wol,  g_wol);
    cudaGetSymbolAddress(&p_wmh,  g_wmh);
    cudaGetSymbolAddress(&p_wml,  g_wml);
    cudaGetSymbolAddress(&p_wdh,  g_wdh);
    cudaGetSymbolAddress(&p_wdl,  g_wdl);

    cudaFuncSetAttribute(gemm_bf16x2<false>,
                         cudaFuncAttributeMaxDynamicSharedMemorySize, GEMM_SMEM);
    cudaFuncSetAttribute(gemm_bf16x2<true>,
                         cudaFuncAttributeMaxDynamicSharedMemorySize, GEMM_SMEM);

    // Weight conversions (hi/lo split + padding / interleave)
    {
        size_t nr, nt;
        nr = (size_t)D_IN_PROJ * D_MODEL / 4; nt = (size_t)N_INPROJ_PAD * D_MODEL / 4;
        cvt_weight_kernel<<<(unsigned)((nt + 255) / 256), 256>>>(
            in_proj_w, (__nv_bfloat16*)p_wih, (__nv_bfloat16*)p_wil, nr, nt);
        nr = nt = (size_t)D_MODEL * D_INNER / 4;
        cvt_weight_kernel<<<(unsigned)((nt + 255) / 256), 256>>>(
            out_proj_w, (__nv_bfloat16*)p_woh, (__nv_bfloat16*)p_wol, nr, nt);
        nt = (size_t)MLP_2X * D_MODEL / 4;
        cvt_weight_pair_kernel<<<(unsigned)((nt + 255) / 256), 256>>>(
            mlp_gate_w, mlp_up_w, (__nv_bfloat16*)p_wmh, (__nv_bfloat16*)p_wml);
        nr = nt = (size_t)D_MODEL * MLP_INNER / 4;
        cvt_weight_kernel<<<(unsigned)((nt + 255) / 256), 256>>>(
            mlp_down_w, (__nv_bfloat16*)p_wdh, (__nv_bfloat16*)p_wdl, nr, nt);
    }

    // 1) prenorm RMSNorm #1
    rmsnorm_prenorm_kernel<<<ROWS, 256>>>(hidden, residual, ssm_norm_w,
        (float*)p_res1, (__nv_bfloat16*)p_nh, (__nv_bfloat16*)p_nl);
    // 2) in_proj
    gemm_bf16x2<false><<<dim3(N_INPROJ_PAD / 256, ROWS / 128), 512, GEMM_SMEM>>>(
        (const __nv_bfloat16*)p_nh, (const __nv_bfloat16*)p_nl,
        (const __nv_bfloat16*)p_wih, (const __nv_bfloat16*)p_wil,
        (float*)p_zx, nullptr, nullptr, ROWS, D_IN_PROJ, D_MODEL);
    // 3) causal depthwise conv + SiLU
    conv_silu_kernel<<<(unsigned)(((size_t)ROWS * CONV_DIM + 255) / 256), 256>>>(
        (const float*)p_zx, conv_w, conv_b, (float*)p_conv);
    // 4) chunked selective scan (3 phases)
    scan_local_kernel<<<dim3(NCHUNK, BATCH * NHEADS), 128>>>(
        (const float*)p_conv, (const float*)p_zx, dt_bias, A_log);
    scan_combine_kernel<<<BATCH * NHEADS, 256>>>();
    scan_apply_kernel<<<dim3(NCHUNK, BATCH * NHEADS), 128>>>(
        (const float*)p_conv, (const float*)p_zx, dt_bias, A_log, D_param,
        (__nv_bfloat16*)p_yh, (__nv_bfloat16*)p_yl);
    // 5) out_proj
    gemm_bf16x2<false><<<dim3(D_MODEL / 256, ROWS / 128), 512, GEMM_SMEM>>>(
        (const __nv_bfloat16*)p_yh, (const __nv_bfloat16*)p_yl,
        (const __nv_bfloat16*)p_woh, (const __nv_bfloat16*)p_wol,
        (float*)p_h2, nullptr, nullptr, ROWS, D_MODEL, D_INNER);
    // 6) prenorm RMSNorm #2
    rmsnorm_prenorm_kernel<<<ROWS, 256>>>((const float*)p_h2, (const float*)p_res1,
        mlp_norm_w, out_res, (__nv_bfloat16*)p_nh, (__nv_bfloat16*)p_nl);
    // 7) fused MLP gate+up GEMM with SwiGLU epilogue (interleaved weights)
    gemm_bf16x2<true><<<dim3(MLP_2X / 256, ROWS / 128), 512, GEMM_SMEM>>>(
        (const __nv_bfloat16*)p_nh, (const __nv_bfloat16*)p_nl,
        (const __nv_bfloat16*)p_wmh, (const __nv_bfloat16*)p_wml,
        nullptr, (__nv_bfloat16*)p_ah, (__nv_bfloat16*)p_al,
        ROWS, MLP_2X, D_MODEL);
    // 8) down projection -> first model output
    gemm_bf16x2<false><<<dim3(D_MODEL / 256, ROWS / 128), 512, GEMM_SMEM>>>(
        (const __nv_bfloat16*)p_ah, (const __nv_bfloat16*)p_al,
        (const __nv_bfloat16*)p_wdh, (const __nv_bfloat16*)p_wdl,
        out_h, nullptr, nullptr, ROWS, D_MODEL, MLP_INNER);
}

// round 9
// speedup vs baseline: 3.8677x; 1.2114x over previous
#include <cuda_runtime.h>
#include <cuda_bf16.h>
#include <cuda_fp16.h>
#include <math.h>
#include <stdint.h>

// ---------------------------------------------------------------------------
// Problem constants
// ---------------------------------------------------------------------------
#define BATCH     2
#define SEQ       4096
#define ROWS      (BATCH * SEQ)          // 8192 tokens
#define D_MODEL   1024
#define STATE     128
#define HEADDIM   64
#define D_INNER   2048
#define NHEADS    32
#define CONV_DIM  (D_INNER + 2 * STATE)  // 2304
#define D_IN_PROJ (2 * D_INNER + 2 * STATE + NHEADS) // 4384
#define N_INPROJ_PAD 4608                // padded to multiple of 256
#define MLP_INNER 4096
#define MLP_2X    (2 * MLP_INNER)        // interleaved gate/up
#define EPS       1e-5f
#define NCHUNK    32
#define CLEN      128                    // SEQ / NCHUNK

// ---------------------------------------------------------------------------
// Scratch (static device arrays; no runtime allocation allowed)
// ---------------------------------------------------------------------------
__device__ float g_res1  [(size_t)ROWS * D_MODEL];
__device__ float g_zx    [(size_t)ROWS * D_IN_PROJ];
__device__ float g_conv  [(size_t)ROWS * CONV_DIM];
__device__ float g_h2    [(size_t)ROWS * D_MODEL];

__device__ float g_slocal[(size_t)BATCH * NHEADS * NCHUNK * HEADDIM * STATE];
__device__ float g_sin   [(size_t)BATCH * NHEADS * NCHUNK * HEADDIM * STATE];
__device__ float g_cdec  [BATCH * NHEADS * NCHUNK];

__device__ __half g_norm [(size_t)ROWS * D_MODEL];
__device__ __half g_y    [(size_t)ROWS * D_INNER];
__device__ __half g_act  [(size_t)ROWS * MLP_INNER];

__device__ __half g_wih[(size_t)N_INPROJ_PAD * D_MODEL];
__device__ __half g_wil[(size_t)N_INPROJ_PAD * D_MODEL];
__device__ __half g_woh[(size_t)D_MODEL * D_INNER];
__device__ __half g_wol[(size_t)D_MODEL * D_INNER];
__device__ __half g_wmh[(size_t)MLP_2X * D_MODEL];   // interleaved gate/up hi
__device__ __half g_wml[(size_t)MLP_2X * D_MODEL];   // interleaved gate/up lo
__device__ __half g_wdh[(size_t)D_MODEL * MLP_INNER];
__device__ __half g_wdl[(size_t)D_MODEL * MLP_INNER];

// ---------------------------------------------------------------------------
// PTX helpers (baseline sm_103: cp.async + ldmatrix + mma.sync)
// ---------------------------------------------------------------------------
__device__ __forceinline__ uint32_t smem_u32(const void* p) {
    uint32_t a;
    asm("{ .reg .u64 t; cvta.to.shared.u64 t, %1; cvt.u32.u64 %0, t; }"
        : "=r"(a) : "l"(p));
    return a;
}
__device__ __forceinline__ void cp_async16(uint32_t dst, const void* src) {
    asm volatile("cp.async.cg.shared.global [%0], [%1], 16;\n" :: "r"(dst), "l"(src));
}
__device__ __forceinline__ void cp_commit() {
    asm volatile("cp.async.commit_group;\n" ::: "memory");
}
template <int N>
__device__ __forceinline__ void cp_wait() {
    asm volatile("cp.async.wait_group %0;\n" :: "n"(N) : "memory");
}
__device__ __forceinline__ void ldmx4(uint32_t* r, uint32_t addr) {
    asm volatile("ldmatrix.sync.aligned.m8n8.x4.shared.b16 {%0,%1,%2,%3}, [%4];"
                 : "=r"(r[0]), "=r"(r[1]), "=r"(r[2]), "=r"(r[3]) : "r"(addr));
}
__device__ __forceinline__ void mma_f16(float* c, const uint32_t* a, const uint32_t* b) {
    asm volatile(
        "mma.sync.aligned.m16n8k16.row.col.f32.f16.f16.f32 "
        "{%0,%1,%2,%3}, {%4,%5,%6,%7}, {%8,%9}, {%0,%1,%2,%3};"
        : "+f"(c[0]), "+f"(c[1]), "+f"(c[2]), "+f"(c[3])
        : "r"(a[0]), "r"(a[1]), "r"(a[2]), "r"(a[3]), "r"(b[0]), "r"(b[1]));
}

// ---------------------------------------------------------------------------
// Split-fp16 tensor-core GEMM: C[M,N] = A[M,K] @ W[N,K]^T
// A single fp16; W as (hi, lo) fp16 pair; 2 MMAs: A*Wh + A*Wl.
// 128x256 CTA tile, BK=32, 512 threads (16 warps, 32x64 each), 4 stages.
// SMEM row stride 80B -> ldmatrix conflict-free without swizzle.
// SWIGLU=true: N covers interleaved (gate,up) pairs; epilogue emits
//   silu(gate)*up as fp16 into Out with N/2 columns.
// ---------------------------------------------------------------------------
#define GSTAGE   4
#define ROWB     80
#define A_TILE_B (128 * ROWB)            // 10240
#define W_TILE_B (256 * ROWB)            // 20480
#define STAGE_B  (A_TILE_B + 2 * W_TILE_B)      // 51200
#define GEMM_SMEM (GSTAGE * STAGE_B)     // 204800

__device__ __forceinline__ void load_stage_g(
    uint32_t sbase,
    const __half* __restrict__ A,
    const __half* __restrict__ Wh, const __half* __restrict__ Wl,
    int bm, int bn, int K, int kc, int tid)
{
    const int koff = kc * 32;
    {
        const int row = tid >> 2, ch = tid & 3;
        const uint32_t d = (uint32_t)(row * ROWB + ch * 16);
        cp_async16(sbase + d, A + (size_t)(bm + row) * K + koff + ch * 8);
    }
    #pragma unroll
    for (int i = 0; i < 2; i++) {
        const int slot = tid + i * 512;
        const int row = slot >> 2, ch = slot & 3;
        const uint32_t d = (uint32_t)(row * ROWB + ch * 16);
        const size_t bo = (size_t)(bn + row) * K + koff + ch * 8;
        cp_async16(sbase + A_TILE_B + d, Wh + bo);
        cp_async16(sbase + A_TILE_B + W_TILE_B + d, Wl + bo);
    }
}

template <bool SWIGLU>
__global__ __launch_bounds__(512, 1)
void gemm_f16x2(const __half* __restrict__ A,
                const __half* __restrict__ Wh,
                const __half* __restrict__ Wl,
                float* __restrict__ C,
                __half* __restrict__ Out,
                int M, int N, int K)
{
    extern __shared__ __align__(128) char dynsmem[];
    const uint32_t sbase = smem_u32(dynsmem);

    const int tid  = threadIdx.x;
    const int lane = tid & 31;
    const int wid  = tid >> 5;
    const int wm   = wid & 3;             // 4 m-groups of 32 rows
    const int wn   = wid >> 2;            // 4 n-groups of 64 cols
    const int bm   = blockIdx.y * 128;
    const int bn   = blockIdx.x * 256;

    const uint32_t a_off = (uint32_t)((wm * 32 + (lane & 15)) * ROWB
                                      + ((lane >> 4) & 1) * 16);
    const uint32_t b_off = (uint32_t)((wn * 64 + ((lane >> 4) & 1) * 8 + (lane & 7)) * ROWB
                                      + ((lane >> 3) & 1) * 16);

    float acc[2][8][4];
    #pragma unroll
    for (int i = 0; i < 2; i++)
        #pragma unroll
        for (int j = 0; j < 8; j++)
            #pragma unroll
            for (int q = 0; q < 4; q++) acc[i][j][q] = 0.f;

    const int nk = K >> 5;

    load_stage_g(sbase + 0 * STAGE_B, A, Wh, Wl, bm, bn, K, 0, tid);
    cp_commit();
    load_stage_g(sbase + 1 * STAGE_B, A, Wh, Wl, bm, bn, K, 1, tid);
    cp_commit();
    load_stage_g(sbase + 2 * STAGE_B, A, Wh, Wl, bm, bn, K, 2, tid);
    cp_commit();

    for (int k = 0; k < nk; k++) {
        const uint32_t stb = sbase + (uint32_t)(k % GSTAGE) * STAGE_B;
        cp_wait<2>();
        __syncthreads();

        const int kn = k + 3;
        if (kn < nk)
            load_stage_g(sbase + (uint32_t)(kn % GSTAGE) * STAGE_B,
                         A, Wh, Wl, bm, bn, K, kn, tid);
        cp_commit();

        const uint32_t a_b = stb + a_off;
        const uint32_t b_h = stb + A_TILE_B + b_off;
        const uint32_t b_l = stb + A_TILE_B + W_TILE_B + b_off;

        #pragma unroll
        for (int s = 0; s < 2; s++) {
            const uint32_t kb = (uint32_t)(s * 32);
            uint32_t af[2][4];
            #pragma unroll
            for (int i = 0; i < 2; i++)
                ldmx4(af[i], a_b + (uint32_t)(i * 16 * ROWB) + kb);
            #pragma unroll
            for (int jp = 0; jp < 4; jp++) {
                uint32_t whf[4], wlf[4];
                ldmx4(whf, b_h + (uint32_t)(jp * 16 * ROWB) + kb);
                ldmx4(wlf, b_l + (uint32_t)(jp * 16 * ROWB) + kb);
                #pragma unroll
                for (int i = 0; i < 2; i++)
                    #pragma unroll
                    for (int f = 0; f < 2; f++) {
                        mma_f16(acc[i][jp * 2 + f], af[i], whf + f * 2);
                        mma_f16(acc[i][jp * 2 + f], af[i], wlf + f * 2);
                    }
            }
        }
    }

    if (!SWIGLU) {
        #pragma unroll
        for (int i = 0; i < 2; i++) {
            const int row = bm + wm * 32 + i * 16 + (lane >> 2);
            #pragma unroll
            for (int j = 0; j < 8; j++) {
                const int col = bn + wn * 64 + j * 8 + (lane & 3) * 2;
                if (col < N) {
                    *(float2*)&C[(size_t)row * N + col] =
                        make_float2(acc[i][j][0], acc[i][j][1]);
                    *(float2*)&C[(size_t)(row + 8) * N + col] =
                        make_float2(acc[i][j][2], acc[i][j][3]);
                }
            }
        }
    } else {
        // Columns are interleaved (gate, up) pairs: acc[..][0]=gate, [1]=up
        // (and [2],[3] for row+8). Output column index = col/2, width N/2.
        const int NO = N >> 1;
        #pragma unroll
        for (int i = 0; i < 2; i++) {
            const int row = bm + wm * 32 + i * 16 + (lane >> 2);
            #pragma unroll
            for (int j = 0; j < 8; j++) {
                const int colc = (bn + wn * 64 + j * 8 + (lane & 3) * 2) >> 1;
                {
                    const float g = acc[i][j][0], u = acc[i][j][1];
                    const float v = g / (1.f + expf(-g)) * u;
                    Out[(size_t)row * NO + colc] = __float2half(v);
                }
                {
                    const float g = acc[i][j][2], u = acc[i][j][3];
                    const float v = g / (1.f + expf(-g)) * u;
                    Out[(size_t)(row + 8) * NO + colc] = __float2half(v);
                }
            }
        }
    }
}

// ---------------------------------------------------------------------------
// fp16 helpers
// ---------------------------------------------------------------------------
__device__ __forceinline__ void store_h4(__half* __restrict__ p, size_t off, float4 v) {
    __half2 a; a.x = __float2half(v.x); a.y = __float2half(v.y);
    __half2 b; b.x = __float2half(v.z); b.y = __float2half(v.w);
    *(__half2*)(p + off)     = a;
    *(__half2*)(p + off + 2) = b;
}
__device__ __forceinline__ void store_hilo4_h(
    __half* __restrict__ hi, __half* __restrict__ lo, size_t off, float4 v)
{
    __half h0 = __float2half(v.x), h1 = __float2half(v.y);
    __half h2 = __float2half(v.z), h3 = __float2half(v.w);
    __half2 a; a.x = h0; a.y = h1;
    __half2 b; b.x = h2; b.y = h3;
    *(__half2*)(hi + off)     = a;
    *(__half2*)(hi + off + 2) = b;
    __half2 c, d;
    c.x = __float2half(v.x - __half2float(h0));
    c.y = __float2half(v.y - __half2float(h1));
    d.x = __float2half(v.z - __half2float(h2));
    d.y = __float2half(v.w - __half2float(h3));
    *(__half2*)(lo + off)     = c;
    *(__half2*)(lo + off + 2) = d;
}

// Weight fp32 -> (hi, lo) fp16, float4-vectorized, zero tail padding.
__global__ __launch_bounds__(256) void cvt_weight_kernel(
    const float* __restrict__ w, __half* __restrict__ hi,
    __half* __restrict__ lo, size_t n_real4, size_t n_total4)
{
    const size_t i = (size_t)blockIdx.x * 256 + threadIdx.x;
    if (i >= n_total4) return;
    float4 v = (i < n_real4) ? ((const float4*)w)[i]
                             : make_float4(0.f, 0.f, 0.f, 0.f);
    store_hilo4_h(hi, lo, i * 4, v);
}

// gate/up weights -> row-interleaved combined (hi, lo): row 2j = gate_j, 2j+1 = up_j.
#define K4 (D_MODEL / 4)
__global__ __launch_bounds__(256) void cvt_weight_pair_kernel(
    const float* __restrict__ wg, const float* __restrict__ wu,
    __half* __restrict__ hi, __half* __restrict__ lo)
{
    const size_t i = (size_t)blockIdx.x * 256 + threadIdx.x;   // float4 index
    if (i >= (size_t)MLP_2X * K4) return;
    const size_t n = i / K4;          // interleaved row
    const size_t k4 = i % K4;
    const size_t srow = n >> 1;
    const float4 v = (n & 1) ? ((const float4*)wu)[srow * K4 + k4]
                             : ((const float4*)wg)[srow * K4 + k4];
    store_hilo4_h(hi, lo, i * 4, v);
}

// ---------------------------------------------------------------------------
// Fused residual-add + RMSNorm; norm output as single fp16.
// ---------------------------------------------------------------------------
__global__ __launch_bounds__(256) void rmsnorm_prenorm_kernel(
    const float* __restrict__ x, const float* __restrict__ res_in,
    const float* __restrict__ w, float* __restrict__ res_out,
    __half* __restrict__ nh)
{
    const size_t row = blockIdx.x;
    const int tid = threadIdx.x;
    const float4 xv = ((const float4*)(x      + row * D_MODEL))[tid];
    const float4 rv = ((const float4*)(res_in + row * D_MODEL))[tid];
    float4 s;
    s.x = xv.x + rv.x; s.y = xv.y + rv.y; s.z = xv.z + rv.z; s.w = xv.w + rv.w;
    float ss = s.x * s.x + s.y * s.y + s.z * s.z + s.w * s.w;

    #pragma unroll
    for (int o = 16; o > 0; o >>= 1) ss += __shfl_down_sync(0xffffffffu, ss, o);
    __shared__ float red[8];
    __shared__ float scale_sh;
    if ((tid & 31) == 0) red[tid >> 5] = ss;
    __syncthreads();
    if (tid == 0) {
        float t = 0.f;
        #pragma unroll
        for (int i = 0; i < 8; i++) t += red[i];
        scale_sh = rsqrtf(t / (float)D_MODEL + EPS);
    }
    __syncthreads();
    const float scale = scale_sh;

    ((float4*)(res_out + row * D_MODEL))[tid] = s;
    const float4 wv = ((const float4*)w)[tid];
    float4 o;
    o.x = s.x * scale * wv.x; o.y = s.y * scale * wv.y;
    o.z = s.z * scale * wv.z; o.w = s.w * scale * wv.w;
    store_h4(nh, row * D_MODEL + (size_t)tid * 4, o);
}

// ---------------------------------------------------------------------------
// Causal depthwise conv1d (width 4) + SiLU over the xBC slice of zxbcdt.
// ---------------------------------------------------------------------------
__global__ __launch_bounds__(256) void conv_silu_kernel(
    const float* __restrict__ zx, const float* __restrict__ cw,
    const float* __restrict__ cb, float* __restrict__ out)
{
    const size_t id = (size_t)blockIdx.x * 256 + threadIdx.x;
    if (id >= (size_t)ROWS * CONV_DIM) return;
    const int c = (int)(id % CONV_DIM);
    const size_t r = id / CONV_DIM;
    const int l = (int)(r & (SEQ - 1));
    const float* base = zx + r * D_IN_PROJ + D_INNER + c;

    const float w0 = cw[c * 4 + 0], w1 = cw[c * 4 + 1];
    const float w2 = cw[c * 4 + 2], w3 = cw[c * 4 + 3];
    float acc = cb[c];
    if (l >= 3) acc += base[-3L * D_IN_PROJ] * w0;
    if (l >= 2) acc += base[-2L * D_IN_PROJ] * w1;
    if (l >= 1) acc += base[-1L * D_IN_PROJ] * w2;
    acc += base[0] * w3;
    out[id] = acc / (1.f + expf(-acc));
}

// ---------------------------------------------------------------------------
// Chunked selective scan. Phase 1: per-chunk local scan (zero init state),
// writes final local state + chunk decay product. Grid: (NCHUNK, B*H).
// ---------------------------------------------------------------------------
#define SCAN_T 8
__global__ __launch_bounds__(128) void scan_local_kernel(
    const float* __restrict__ conv, const float* __restrict__ zx,
    const float* __restrict__ dt_bias, const float* __restrict__ A_log)
{
    const int chunk = blockIdx.x;
    const int bh = blockIdx.y;
    const int b = bh >> 5;
    const int h = bh & 31;
    const int tid = threadIdx.x;
    const int p = tid >> 1;
    const int half = tid & 1;
    const int n0 = half * 64;

    __shared__ float Bs[SCAN_T][STATE];
    __shared__ float xs[SCAN_T][HEADDIM];
    __shared__ float dts[SCAN_T];

    float state[64];
    #pragma unroll
    for (int j = 0; j < 64; j++) state[j] = 0.f;
    float cdec = 1.f;

    const float Aneg = -expf(A_log[h]);
    const float dtb  = dt_bias[h];
    const size_t base_conv = (size_t)b * SEQ * CONV_DIM;
    const size_t base_z    = (size_t)b * SEQ * D_IN_PROJ;
    const int tstart = chunk * CLEN;

    for (int t0 = tstart; t0 < tstart + CLEN; t0 += SCAN_T) {
        __syncthreads();
        for (int idx = tid; idx < SCAN_T * STATE; idx += 128) {
            const int tt = idx >> 7;
            const int n  = idx & 127;
            Bs[tt][n] = conv[base_conv + (size_t)(t0 + tt) * CONV_DIM + D_INNER + n];
        }
        for (int idx = tid; idx < SCAN_T * HEADDIM; idx += 128) {
            const int tt = idx >> 6;
            const int pp = idx & 63;
            xs[tt][pp] = conv[base_conv + (size_t)(t0 + tt) * CONV_DIM + h * HEADDIM + pp];
        }
        if (tid < SCAN_T)
            dts[tid] = zx[base_z + (size_t)(t0 + tid) * D_IN_PROJ + D_INNER + CONV_DIM + h];
        __syncthreads();

        #pragma unroll 1
        for (int tt = 0; tt < SCAN_T; tt++) {
            const float draw = dts[tt] + dtb;
            const float dtp = (draw > 20.f) ? draw : log1pf(expf(draw));
            const float dA = expf(dtp * Aneg);
            cdec *= dA;
            const float k = dtp * xs[tt][p];
            const float4* Bv = (const float4*)&Bs[tt][n0];
            #pragma unroll
            for (int jj = 0; jj < 16; jj++) {
                const float4 bv = Bv[jj];
                float* st = &state[jj * 4];
                st[0] = st[0] * dA + k * bv.x;
                st[1] = st[1] * dA + k * bv.y;
                st[2] = st[2] * dA + k * bv.z;
                st[3] = st[3] * dA + k * bv.w;
            }
        }
    }

    float* dst = g_slocal + ((size_t)(bh * NCHUNK + chunk) * HEADDIM + p) * STATE + n0;
    #pragma unroll
    for (int jj = 0; jj < 16; jj++)
        ((float4*)dst)[jj] = make_float4(state[jj * 4], state[jj * 4 + 1],
                                         state[jj * 4 + 2], state[jj * 4 + 3]);
    if (tid == 0) g_cdec[bh * NCHUNK + chunk] = cdec;
}

// Phase 2: sequential chunk combine (scalar decay per chunk). Grid: B*H.
__global__ __launch_bounds__(256) void scan_combine_kernel()
{
    const int bh = blockIdx.x;
    const int tid = threadIdx.x;
    float s[32];
    #pragma unroll
    for (int j = 0; j < 32; j++) s[j] = 0.f;

    for (int c = 0; c < NCHUNK; c++) {
        float* dst = g_sin + (size_t)(bh * NCHUNK + c) * (HEADDIM * STATE);
        if (c > 0) {
            const float D = g_cdec[bh * NCHUNK + c - 1];
            const float* src = g_slocal + (size_t)(bh * NCHUNK + c - 1) * (HEADDIM * STATE);
            #pragma unroll
            for (int j = 0; j < 32; j++)
                s[j] = D * s[j] + src[j * 256 + tid];
        }
        #pragma unroll
        for (int j = 0; j < 32; j++)
            dst[j * 256 + tid] = s[j];
    }
}

// Phase 3: per-chunk scan with proper initial state; emits gated y (fp16).
__global__ __launch_bounds__(128) void scan_apply_kernel(
    const float* __restrict__ conv, const float* __restrict__ zx,
    const float* __restrict__ dt_bias, const float* __restrict__ A_log,
    const float* __restrict__ D_param,
    __half* __restrict__ yh)
{
    const int chunk = blockIdx.x;
    const int bh = blockIdx.y;
    const int b = bh >> 5;
    const int h = bh & 31;
    const int tid = threadIdx.x;
    const int p = tid >> 1;
    const int half = tid & 1;
    const int n0 = half * 64;

    __shared__ float Bs[SCAN_T][STATE];
    __shared__ float Cs[SCAN_T][STATE];
    __shared__ float xs[SCAN_T][HEADDIM];
    __shared__ float zs[SCAN_T][HEADDIM];
    __shared__ float dts[SCAN_T];

    float state[64];
    {
        const float* src = g_sin + ((size_t)(bh * NCHUNK + chunk) * HEADDIM + p) * STATE + n0;
        #pragma unroll
        for (int jj = 0; jj < 16; jj++) {
            const float4 v = ((const float4*)src)[jj];
            state[jj * 4] = v.x; state[jj * 4 + 1] = v.y;
            state[jj * 4 + 2] = v.z; state[jj * 4 + 3] = v.w;
        }
    }

    const float Aneg = -expf(A_log[h]);
    const float dtb  = dt_bias[h];
    const float Dp   = D_param[h];
    const size_t base_conv = (size_t)b * SEQ * CONV_DIM;
    const size_t base_z    = (size_t)b * SEQ * D_IN_PROJ;
    const int tstart = chunk * CLEN;

    for (int t0 = tstart; t0 < tstart + CLEN; t0 += SCAN_T) {
        __syncthreads();
        for (int idx = tid; idx < SCAN_T * STATE; idx += 128) {
            const int tt = idx >> 7;
            const int n  = idx & 127;
            const size_t rowp = base_conv + (size_t)(t0 + tt) * CONV_DIM;
            Bs[tt][n] = conv[rowp + D_INNER + n];
            Cs[tt][n] = conv[rowp + D_INNER + STATE + n];
        }
        for (int idx = tid; idx < SCAN_T * HEADDIM; idx += 128) {
            const int tt = idx >> 6;
            const int pp = idx & 63;
            xs[tt][pp] = conv[base_conv + (size_t)(t0 + tt) * CONV_DIM + h * HEADDIM + pp];
            zs[tt][pp] = zx[base_z + (size_t)(t0 + tt) * D_IN_PROJ + h * HEADDIM + pp];
        }
        if (tid < SCAN_T)
            dts[tid] = zx[base_z + (size_t)(t0 + tid) * D_IN_PROJ + D_INNER + CONV_DIM + h];
        __syncthreads();

        #pragma unroll 1
        for (int tt = 0; tt < SCAN_T; tt++) {
            const float draw = dts[tt] + dtb;
            const float dtp = (draw > 20.f) ? draw : log1pf(expf(draw));
            const float dA = expf(dtp * Aneg);
            const float xv = xs[tt][p];
            const float k = dtp * xv;
            float y0 = 0.f, y1 = 0.f, y2 = 0.f, y3 = 0.f;
            const float4* Bv = (const float4*)&Bs[tt][n0];
            const float4* Cv = (const float4*)&Cs[tt][n0];
            #pragma unroll
            for (int jj = 0; jj < 16; jj++) {
                const float4 bv = Bv[jj];
                const float4 cv = Cv[jj];
                float* st = &state[jj * 4];
                st[0] = st[0] * dA + k * bv.x; y0 += st[0] * cv.x;
                st[1] = st[1] * dA + k * bv.y; y1 += st[1] * cv.y;
                st[2] = st[2] * dA + k * bv.z; y2 += st[2] * cv.z;
                st[3] = st[3] * dA + k * bv.w; y3 += st[3] * cv.w;
            }
            float y = (y0 + y1) + (y2 + y3);
            y += __shfl_xor_sync(0xffffffffu, y, 1);
            if (half == 0) {
                const float zv = zs[tt][p];
                const float gate = zv / (1.f + expf(-zv));
                const float yo = (y + Dp * xv) * gate;
                yh[((size_t)(b * SEQ + t0 + tt)) * D_INNER + h * HEADDIM + p] =
                    __float2half(yo);
            }
        }
    }
}

// ---------------------------------------------------------------------------
// Launch
// ---------------------------------------------------------------------------
extern "C" void kernel_launch(void* const* d_in, const int* in_sizes, int n_in,
                              void* d_out, int out_size)
{
    const float* hidden     = (const float*)d_in[0];
    const float* residual   = (const float*)d_in[1];
    const float* ssm_norm_w = (const float*)d_in[2];
    const float* mlp_norm_w = (const float*)d_in[3];
    const float* in_proj_w  = (const float*)d_in[4];
    const float* conv_w     = (const float*)d_in[5];
    const float* conv_b     = (const float*)d_in[6];
    const float* dt_bias    = (const float*)d_in[7];
    const float* A_log      = (const float*)d_in[8];
    const float* D_param    = (const float*)d_in[9];
    const float* out_proj_w = (const float*)d_in[10];
    const float* mlp_gate_w = (const float*)d_in[11];
    const float* mlp_up_w   = (const float*)d_in[12];
    const float* mlp_down_w = (const float*)d_in[13];

    float* out_h   = (float*)d_out;
    float* out_res = out_h + (size_t)ROWS * D_MODEL;

    void *p_res1, *p_zx, *p_conv, *p_h2;
    void *p_n, *p_y, *p_a;
    void *p_wih, *p_wil, *p_woh, *p_wol, *p_wmh, *p_wml, *p_wdh, *p_wdl;
    cudaGetSymbolAddress(&p_res1, g_res1);
    cudaGetSymbolAddress(&p_zx,   g_zx);
    cudaGetSymbolAddress(&p_conv, g_conv);
    cudaGetSymbolAddress(&p_h2,   g_h2);
    cudaGetSymbolAddress(&p_n,    g_norm);
    cudaGetSymbolAddress(&p_y,    g_y);
    cudaGetSymbolAddress(&p_a,    g_act);
    cudaGetSymbolAddress(&p_wih,  g_wih);
    cudaGetSymbolAddress(&p_wil,  g_wil);
    cudaGetSymbolAddress(&p_woh,  g_woh);
    cudaGetSymbolAddress(&p_wol,  g_wol);
    cudaGetSymbolAddress(&p_wmh,  g_wmh);
    cudaGetSymbolAddress(&p_wml,  g_wml);
    cudaGetSymbolAddress(&p_wdh,  g_wdh);
    cudaGetSymbolAddress(&p_wdl,  g_wdl);

    cudaFuncSetAttribute(gemm_f16x2<false>,
                         cudaFuncAttributeMaxDynamicSharedMemorySize, GEMM_SMEM);
    cudaFuncSetAttribute(gemm_f16x2<true>,
                         cudaFuncAttributeMaxDynamicSharedMemorySize, GEMM_SMEM);

    // Weight conversions (fp16 hi/lo split + padding / interleave)
    {
        size_t nr, nt;
        nr = (size_t)D_IN_PROJ * D_MODEL / 4; nt = (size_t)N_INPROJ_PAD * D_MODEL / 4;
        cvt_weight_kernel<<<(unsigned)((nt + 255) / 256), 256>>>(
            in_proj_w, (__half*)p_wih, (__half*)p_wil, nr, nt);
        nr = nt = (size_t)D_MODEL * D_INNER / 4;
        cvt_weight_kernel<<<(unsigned)((nt + 255) / 256), 256>>>(
            out_proj_w, (__half*)p_woh, (__half*)p_wol, nr, nt);
        nt = (size_t)MLP_2X * D_MODEL / 4;
        cvt_weight_pair_kernel<<<(unsigned)((nt + 255) / 256), 256>>>(
            mlp_gate_w, mlp_up_w, (__half*)p_wmh, (__half*)p_wml);
        nr = nt = (size_t)D_MODEL * MLP_INNER / 4;
        cvt_weight_kernel<<<(unsigned)((nt + 255) / 256), 256>>>(
            mlp_down_w, (__half*)p_wdh, (__half*)p_wdl, nr, nt);
    }

    // 1) prenorm RMSNorm #1
    rmsnorm_prenorm_kernel<<<ROWS, 256>>>(hidden, residual, ssm_norm_w,
        (float*)p_res1, (__half*)p_n);
    // 2) in_proj
    gemm_f16x2<false><<<dim3(N_INPROJ_PAD / 256, ROWS / 128), 512, GEMM_SMEM>>>(
        (const __half*)p_n, (const __half*)p_wih, (const __half*)p_wil,
        (float*)p_zx, nullptr, ROWS, D_IN_PROJ, D_MODEL);
    // 3) causal depthwise conv + SiLU
    conv_silu_kernel<<<(unsigned)(((size_t)ROWS * CONV_DIM + 255) / 256), 256>>>(
        (const float*)p_zx, conv_w, conv_b, (float*)p_conv);
    // 4) chunked selective scan (3 phases)
    scan_local_kernel<<<dim3(NCHUNK, BATCH * NHEADS), 128>>>(
        (const float*)p_conv, (const float*)p_zx, dt_bias, A_log);
    scan_combine_kernel<<<BATCH * NHEADS, 256>>>();
    scan_apply_kernel<<<dim3(NCHUNK, BATCH * NHEADS), 128>>>(
        (const float*)p_conv, (const float*)p_zx, dt_bias, A_log, D_param,
        (__half*)p_y);
    // 5) out_proj
    gemm_f16x2<false><<<dim3(D_MODEL / 256, ROWS / 128), 512, GEMM_SMEM>>>(
        (const __half*)p_y, (const __half*)p_woh, (const __half*)p_wol,
        (float*)p_h2, nullptr, ROWS, D_MODEL, D_INNER);
    // 6) prenorm RMSNorm #2
    rmsnorm_prenorm_kernel<<<ROWS, 256>>>((const float*)p_h2, (const float*)p_res1,
        mlp_norm_w, out_res, (__half*)p_n);
    // 7) fused MLP gate+up GEMM with SwiGLU epilogue (interleaved weights)
    gemm_f16x2<true><<<dim3(MLP_2X / 256, ROWS / 128), 512, GEMM_SMEM>>>(
        (const __half*)p_n, (const __half*)p_wmh, (const __half*)p_wml,
        nullptr, (__half*)p_a, ROWS, MLP_2X, D_MODEL);
    // 8) down projection -> first model output
    gemm_f16x2<false><<<dim3(D_MODEL / 256, ROWS / 128), 512, GEMM_SMEM>>>(
        (const __half*)p_a, (const __half*)p_wdh, (const __half*)p_wdl,
        out_h, nullptr, ROWS, D_MODEL, MLP_INNER);
}

// round 10
// speedup vs baseline: 5.1467x; 1.3307x over previous
#include <cuda_runtime.h>
#include <cuda_bf16.h>
#include <cuda_fp16.h>
#include <math.h>
#include <stdint.h>

// ---------------------------------------------------------------------------
// Problem constants
// ---------------------------------------------------------------------------
#define BATCH     2
#define SEQ       4096
#define ROWS      (BATCH * SEQ)          // 8192 tokens
#define D_MODEL   1024
#define STATE     128
#define HEADDIM   64
#define D_INNER   2048
#define NHEADS    32
#define CONV_DIM  (D_INNER + 2 * STATE)  // 2304
#define D_IN_PROJ (2 * D_INNER + 2 * STATE + NHEADS) // 4384
#define N_INPROJ_PAD 4608                // padded to multiple of 256
#define MLP_INNER 4096
#define MLP_2X    (2 * MLP_INNER)        // interleaved gate/up
#define EPS       1e-5f
#define NCHUNK    32
#define CLEN      128                    // SEQ / NCHUNK

// ---------------------------------------------------------------------------
// Scratch (static device arrays; no runtime allocation allowed)
// ---------------------------------------------------------------------------
__device__ float g_res1  [(size_t)ROWS * D_MODEL];
__device__ float g_zx    [(size_t)ROWS * D_IN_PROJ];
__device__ float g_conv  [(size_t)ROWS * CONV_DIM];
__device__ float g_h2    [(size_t)ROWS * D_MODEL];

__device__ float g_slocal[(size_t)BATCH * NHEADS * NCHUNK * HEADDIM * STATE];
__device__ float g_sin   [(size_t)BATCH * NHEADS * NCHUNK * HEADDIM * STATE];
__device__ float g_cdec  [BATCH * NHEADS * NCHUNK];

__device__ __half g_norm [(size_t)ROWS * D_MODEL];
__device__ __half g_y    [(size_t)ROWS * D_INNER];
__device__ __half g_act  [(size_t)ROWS * MLP_INNER];

__device__ __half g_wi[(size_t)N_INPROJ_PAD * D_MODEL];
__device__ __half g_wo[(size_t)D_MODEL * D_INNER];
__device__ __half g_wm[(size_t)MLP_2X * D_MODEL];   // interleaved gate/up
__device__ __half g_wd[(size_t)D_MODEL * MLP_INNER];

// ---------------------------------------------------------------------------
// PTX helpers (baseline sm_103: cp.async + ldmatrix + mma.sync)
// ---------------------------------------------------------------------------
__device__ __forceinline__ uint32_t smem_u32(const void* p) {
    uint32_t a;
    asm("{ .reg .u64 t; cvta.to.shared.u64 t, %1; cvt.u32.u64 %0, t; }"
        : "=r"(a) : "l"(p));
    return a;
}
__device__ __forceinline__ void cp_async16(uint32_t dst, const void* src) {
    asm volatile("cp.async.cg.shared.global [%0], [%1], 16;\n" :: "r"(dst), "l"(src));
}
__device__ __forceinline__ void cp_commit() {
    asm volatile("cp.async.commit_group;\n" ::: "memory");
}
template <int N>
__device__ __forceinline__ void cp_wait() {
    asm volatile("cp.async.wait_group %0;\n" :: "n"(N) : "memory");
}
__device__ __forceinline__ void ldmx4(uint32_t* r, uint32_t addr) {
    asm volatile("ldmatrix.sync.aligned.m8n8.x4.shared.b16 {%0,%1,%2,%3}, [%4];"
                 : "=r"(r[0]), "=r"(r[1]), "=r"(r[2]), "=r"(r[3]) : "r"(addr));
}
__device__ __forceinline__ void mma_f16(float* c, const uint32_t* a, const uint32_t* b) {
    asm volatile(
        "mma.sync.aligned.m16n8k16.row.col.f32.f16.f16.f32 "
        "{%0,%1,%2,%3}, {%4,%5,%6,%7}, {%8,%9}, {%0,%1,%2,%3};"
        : "+f"(c[0]), "+f"(c[1]), "+f"(c[2]), "+f"(c[3])
        : "r"(a[0]), "r"(a[1]), "r"(a[2]), "r"(a[3]), "r"(b[0]), "r"(b[1]));
}

// ---------------------------------------------------------------------------
// fp16 tensor-core GEMM: C[M,N] = A[M,K] @ W[N,K]^T, fp32 accumulate.
// 128x256 CTA tile, BK=32, 512 threads (16 warps, 32x64 each), 4 stages.
// SMEM row stride 80B -> ldmatrix conflict-free without swizzle.
// SWIGLU=true: N covers interleaved (gate,up) pairs; epilogue emits
//   silu(gate)*up as fp16 into Out with N/2 columns.
// ---------------------------------------------------------------------------
#define GSTAGE   4
#define ROWB     80
#define A_TILE_B (128 * ROWB)            // 10240
#define W_TILE_B (256 * ROWB)            // 20480
#define STAGE_B  (A_TILE_B + W_TILE_B)   // 30720
#define GEMM_SMEM (GSTAGE * STAGE_B)     // 122880

__device__ __forceinline__ void load_stage_g(
    uint32_t sbase,
    const __half* __restrict__ A, const __half* __restrict__ W,
    int bm, int bn, int K, int kc, int tid)
{
    const int koff = kc * 32;
    {
        const int row = tid >> 2, ch = tid & 3;
        const uint32_t d = (uint32_t)(row * ROWB + ch * 16);
        cp_async16(sbase + d, A + (size_t)(bm + row) * K + koff + ch * 8);
    }
    #pragma unroll
    for (int i = 0; i < 2; i++) {
        const int slot = tid + i * 512;
        const int row = slot >> 2, ch = slot & 3;
        const uint32_t d = (uint32_t)(row * ROWB + ch * 16);
        cp_async16(sbase + A_TILE_B + d, W + (size_t)(bn + row) * K + koff + ch * 8);
    }
}

template <bool SWIGLU>
__global__ __launch_bounds__(512, 1)
void gemm_f16(const __half* __restrict__ A,
              const __half* __restrict__ W,
              float* __restrict__ C,
              __half* __restrict__ Out,
              int M, int N, int K)
{
    extern __shared__ __align__(128) char dynsmem[];
    const uint32_t sbase = smem_u32(dynsmem);

    const int tid  = threadIdx.x;
    const int lane = tid & 31;
    const int wid  = tid >> 5;
    const int wm   = wid & 3;             // 4 m-groups of 32 rows
    const int wn   = wid >> 2;            // 4 n-groups of 64 cols
    const int bm   = blockIdx.y * 128;
    const int bn   = blockIdx.x * 256;

    const uint32_t a_off = (uint32_t)((wm * 32 + (lane & 15)) * ROWB
                                      + ((lane >> 4) & 1) * 16);
    const uint32_t b_off = (uint32_t)((wn * 64 + ((lane >> 4) & 1) * 8 + (lane & 7)) * ROWB
                                      + ((lane >> 3) & 1) * 16);

    float acc[2][8][4];
    #pragma unroll
    for (int i = 0; i < 2; i++)
        #pragma unroll
        for (int j = 0; j < 8; j++)
            #pragma unroll
            for (int q = 0; q < 4; q++) acc[i][j][q] = 0.f;

    const int nk = K >> 5;

    load_stage_g(sbase + 0 * STAGE_B, A, W, bm, bn, K, 0, tid);
    cp_commit();
    load_stage_g(sbase + 1 * STAGE_B, A, W, bm, bn, K, 1, tid);
    cp_commit();
    load_stage_g(sbase + 2 * STAGE_B, A, W, bm, bn, K, 2, tid);
    cp_commit();

    for (int k = 0; k < nk; k++) {
        const uint32_t stb = sbase + (uint32_t)(k % GSTAGE) * STAGE_B;
        cp_wait<2>();
        __syncthreads();

        const int kn = k + 3;
        if (kn < nk)
            load_stage_g(sbase + (uint32_t)(kn % GSTAGE) * STAGE_B,
                         A, W, bm, bn, K, kn, tid);
        cp_commit();

        const uint32_t a_b = stb + a_off;
        const uint32_t b_b = stb + A_TILE_B + b_off;

        #pragma unroll
        for (int s = 0; s < 2; s++) {
            const uint32_t kb = (uint32_t)(s * 32);
            uint32_t af[2][4];
            #pragma unroll
            for (int i = 0; i < 2; i++)
                ldmx4(af[i], a_b + (uint32_t)(i * 16 * ROWB) + kb);
            #pragma unroll
            for (int jp = 0; jp < 4; jp++) {
                uint32_t wf[4];
                ldmx4(wf, b_b + (uint32_t)(jp * 16 * ROWB) + kb);
                #pragma unroll
                for (int i = 0; i < 2; i++)
                    #pragma unroll
                    for (int f = 0; f < 2; f++)
                        mma_f16(acc[i][jp * 2 + f], af[i], wf + f * 2);
            }
        }
    }

    if (!SWIGLU) {
        #pragma unroll
        for (int i = 0; i < 2; i++) {
            const int row = bm + wm * 32 + i * 16 + (lane >> 2);
            #pragma unroll
            for (int j = 0; j < 8; j++) {
                const int col = bn + wn * 64 + j * 8 + (lane & 3) * 2;
                if (col < N) {
                    *(float2*)&C[(size_t)row * N + col] =
                        make_float2(acc[i][j][0], acc[i][j][1]);
                    *(float2*)&C[(size_t)(row + 8) * N + col] =
                        make_float2(acc[i][j][2], acc[i][j][3]);
                }
            }
        }
    } else {
        // Columns are interleaved (gate, up) pairs: acc[..][0]=gate, [1]=up
        // (and [2],[3] for row+8). Output column index = col/2, width N/2.
        const int NO = N >> 1;
        #pragma unroll
        for (int i = 0; i < 2; i++) {
            const int row = bm + wm * 32 + i * 16 + (lane >> 2);
            #pragma unroll
            for (int j = 0; j < 8; j++) {
                const int colc = (bn + wn * 64 + j * 8 + (lane & 3) * 2) >> 1;
                {
                    const float g = acc[i][j][0], u = acc[i][j][1];
                    const float v = g / (1.f + expf(-g)) * u;
                    Out[(size_t)row * NO + colc] = __float2half(v);
                }
                {
                    const float g = acc[i][j][2], u = acc[i][j][3];
                    const float v = g / (1.f + expf(-g)) * u;
                    Out[(size_t)(row + 8) * NO + colc] = __float2half(v);
                }
            }
        }
    }
}

// ---------------------------------------------------------------------------
// fp16 helpers
// ---------------------------------------------------------------------------
__device__ __forceinline__ void store_h4(__half* __restrict__ p, size_t off, float4 v) {
    __half2 a; a.x = __float2half(v.x); a.y = __float2half(v.y);
    __half2 b; b.x = __float2half(v.z); b.y = __float2half(v.w);
    *(__half2*)(p + off)     = a;
    *(__half2*)(p + off + 2) = b;
}

// Weight fp32 -> fp16, float4-vectorized, zero tail padding.
__global__ __launch_bounds__(256) void cvt_weight_kernel(
    const float* __restrict__ w, __half* __restrict__ out,
    size_t n_real4, size_t n_total4)
{
    const size_t i = (size_t)blockIdx.x * 256 + threadIdx.x;
    if (i >= n_total4) return;
    float4 v = (i < n_real4) ? ((const float4*)w)[i]
                             : make_float4(0.f, 0.f, 0.f, 0.f);
    store_h4(out, i * 4, v);
}

// gate/up weights -> row-interleaved fp16: row 2j = gate_j, 2j+1 = up_j.
#define K4 (D_MODEL / 4)
__global__ __launch_bounds__(256) void cvt_weight_pair_kernel(
    const float* __restrict__ wg, const float* __restrict__ wu,
    __half* __restrict__ out)
{
    const size_t i = (size_t)blockIdx.x * 256 + threadIdx.x;   // float4 index
    if (i >= (size_t)MLP_2X * K4) return;
    const size_t n = i / K4;          // interleaved row
    const size_t k4 = i % K4;
    const size_t srow = n >> 1;
    const float4 v = (n & 1) ? ((const float4*)wu)[srow * K4 + k4]
                             : ((const float4*)wg)[srow * K4 + k4];
    store_h4(out, i * 4, v);
}

// ---------------------------------------------------------------------------
// Fused residual-add + RMSNorm; norm output as fp16.
// ---------------------------------------------------------------------------
__global__ __launch_bounds__(256) void rmsnorm_prenorm_kernel(
    const float* __restrict__ x, const float* __restrict__ res_in,
    const float* __restrict__ w, float* __restrict__ res_out,
    __half* __restrict__ nh)
{
    const size_t row = blockIdx.x;
    const int tid = threadIdx.x;
    const float4 xv = ((const float4*)(x      + row * D_MODEL))[tid];
    const float4 rv = ((const float4*)(res_in + row * D_MODEL))[tid];
    float4 s;
    s.x = xv.x + rv.x; s.y = xv.y + rv.y; s.z = xv.z + rv.z; s.w = xv.w + rv.w;
    float ss = s.x * s.x + s.y * s.y + s.z * s.z + s.w * s.w;

    #pragma unroll
    for (int o = 16; o > 0; o >>= 1) ss += __shfl_down_sync(0xffffffffu, ss, o);
    __shared__ float red[8];
    __shared__ float scale_sh;
    if ((tid & 31) == 0) red[tid >> 5] = ss;
    __syncthreads();
    if (tid == 0) {
        float t = 0.f;
        #pragma unroll
        for (int i = 0; i < 8; i++) t += red[i];
        scale_sh = rsqrtf(t / (float)D_MODEL + EPS);
    }
    __syncthreads();
    const float scale = scale_sh;

    ((float4*)(res_out + row * D_MODEL))[tid] = s;
    const float4 wv = ((const float4*)w)[tid];
    float4 o;
    o.x = s.x * scale * wv.x; o.y = s.y * scale * wv.y;
    o.z = s.z * scale * wv.z; o.w = s.w * scale * wv.w;
    store_h4(nh, row * D_MODEL + (size_t)tid * 4, o);
}

// ---------------------------------------------------------------------------
// Causal depthwise conv1d (width 4) + SiLU over the xBC slice of zxbcdt.
// ---------------------------------------------------------------------------
__global__ __launch_bounds__(256) void conv_silu_kernel(
    const float* __restrict__ zx, const float* __restrict__ cw,
    const float* __restrict__ cb, float* __restrict__ out)
{
    const size_t id = (size_t)blockIdx.x * 256 + threadIdx.x;
    if (id >= (size_t)ROWS * CONV_DIM) return;
    const int c = (int)(id % CONV_DIM);
    const size_t r = id / CONV_DIM;
    const int l = (int)(r & (SEQ - 1));
    const float* base = zx + r * D_IN_PROJ + D_INNER + c;

    const float w0 = cw[c * 4 + 0], w1 = cw[c * 4 + 1];
    const float w2 = cw[c * 4 + 2], w3 = cw[c * 4 + 3];
    float acc = cb[c];
    if (l >= 3) acc += base[-3L * D_IN_PROJ] * w0;
    if (l >= 2) acc += base[-2L * D_IN_PROJ] * w1;
    if (l >= 1) acc += base[-1L * D_IN_PROJ] * w2;
    acc += base[0] * w3;
    out[id] = acc / (1.f + expf(-acc));
}

// ---------------------------------------------------------------------------
// Chunked selective scan. Phase 1: per-chunk local scan (zero init state),
// writes final local state + chunk decay product. Grid: (NCHUNK, B*H).
// ---------------------------------------------------------------------------
#define SCAN_T 8
__global__ __launch_bounds__(128) void scan_local_kernel(
    const float* __restrict__ conv, const float* __restrict__ zx,
    const float* __restrict__ dt_bias, const float* __restrict__ A_log)
{
    const int chunk = blockIdx.x;
    const int bh = blockIdx.y;
    const int b = bh >> 5;
    const int h = bh & 31;
    const int tid = threadIdx.x;
    const int p = tid >> 1;
    const int half = tid & 1;
    const int n0 = half * 64;

    __shared__ float Bs[SCAN_T][STATE];
    __shared__ float xs[SCAN_T][HEADDIM];
    __shared__ float dts[SCAN_T];

    float state[64];
    #pragma unroll
    for (int j = 0; j < 64; j++) state[j] = 0.f;
    float cdec = 1.f;

    const float Aneg = -expf(A_log[h]);
    const float dtb  = dt_bias[h];
    const size_t base_conv = (size_t)b * SEQ * CONV_DIM;
    const size_t base_z    = (size_t)b * SEQ * D_IN_PROJ;
    const int tstart = chunk * CLEN;

    for (int t0 = tstart; t0 < tstart + CLEN; t0 += SCAN_T) {
        __syncthreads();
        for (int idx = tid; idx < SCAN_T * STATE; idx += 128) {
            const int tt = idx >> 7;
            const int n  = idx & 127;
            Bs[tt][n] = conv[base_conv + (size_t)(t0 + tt) * CONV_DIM + D_INNER + n];
        }
        for (int idx = tid; idx < SCAN_T * HEADDIM; idx += 128) {
            const int tt = idx >> 6;
            const int pp = idx & 63;
            xs[tt][pp] = conv[base_conv + (size_t)(t0 + tt) * CONV_DIM + h * HEADDIM + pp];
        }
        if (tid < SCAN_T)
            dts[tid] = zx[base_z + (size_t)(t0 + tid) * D_IN_PROJ + D_INNER + CONV_DIM + h];
        __syncthreads();

        #pragma unroll 1
        for (int tt = 0; tt < SCAN_T; tt++) {
            const float draw = dts[tt] + dtb;
            const float dtp = (draw > 20.f) ? draw : log1pf(expf(draw));
            const float dA = expf(dtp * Aneg);
            cdec *= dA;
            const float k = dtp * xs[tt][p];
            const float4* Bv = (const float4*)&Bs[tt][n0];
            #pragma unroll
            for (int jj = 0; jj < 16; jj++) {
                const float4 bv = Bv[jj];
                float* st = &state[jj * 4];
                st[0] = st[0] * dA + k * bv.x;
                st[1] = st[1] * dA + k * bv.y;
                st[2] = st[2] * dA + k * bv.z;
                st[3] = st[3] * dA + k * bv.w;
            }
        }
    }

    float* dst = g_slocal + ((size_t)(bh * NCHUNK + chunk) * HEADDIM + p) * STATE + n0;
    #pragma unroll
    for (int jj = 0; jj < 16; jj++)
        ((float4*)dst)[jj] = make_float4(state[jj * 4], state[jj * 4 + 1],
                                         state[jj * 4 + 2], state[jj * 4 + 3]);
    if (tid == 0) g_cdec[bh * NCHUNK + chunk] = cdec;
}

// Phase 2: sequential chunk combine (scalar decay per chunk). Grid: B*H.
__global__ __launch_bounds__(256) void scan_combine_kernel()
{
    const int bh = blockIdx.x;
    const int tid = threadIdx.x;
    float s[32];
    #pragma unroll
    for (int j = 0; j < 32; j++) s[j] = 0.f;

    for (int c = 0; c < NCHUNK; c++) {
        float* dst = g_sin + (size_t)(bh * NCHUNK + c) * (HEADDIM * STATE);
        if (c > 0) {
            const float D = g_cdec[bh * NCHUNK + c - 1];
            const float* src = g_slocal + (size_t)(bh * NCHUNK + c - 1) * (HEADDIM * STATE);
            #pragma unroll
            for (int j = 0; j < 32; j++)
                s[j] = D * s[j] + src[j * 256 + tid];
        }
        #pragma unroll
        for (int j = 0; j < 32; j++)
            dst[j * 256 + tid] = s[j];
    }
}

// Phase 3: per-chunk scan with proper initial state; emits gated y (fp16).
__global__ __launch_bounds__(128) void scan_apply_kernel(
    const float* __restrict__ conv, const float* __restrict__ zx,
    const float* __restrict__ dt_bias, const float* __restrict__ A_log,
    const float* __restrict__ D_param,
    __half* __restrict__ yh)
{
    const int chunk = blockIdx.x;
    const int bh = blockIdx.y;
    const int b = bh >> 5;
    const int h = bh & 31;
    const int tid = threadIdx.x;
    const int p = tid >> 1;
    const int half = tid & 1;
    const int n0 = half * 64;

    __shared__ float Bs[SCAN_T][STATE];
    __shared__ float Cs[SCAN_T][STATE];
    __shared__ float xs[SCAN_T][HEADDIM];
    __shared__ float zs[SCAN_T][HEADDIM];
    __shared__ float dts[SCAN_T];

    float state[64];
    {
        const float* src = g_sin + ((size_t)(bh * NCHUNK + chunk) * HEADDIM + p) * STATE + n0;
        #pragma unroll
        for (int jj = 0; jj < 16; jj++) {
            const float4 v = ((const float4*)src)[jj];
            state[jj * 4] = v.x; state[jj * 4 + 1] = v.y;
            state[jj * 4 + 2] = v.z; state[jj * 4 + 3] = v.w;
        }
    }

    const float Aneg = -expf(A_log[h]);
    const float dtb  = dt_bias[h];
    const float Dp   = D_param[h];
    const size_t base_conv = (size_t)b * SEQ * CONV_DIM;
    const size_t base_z    = (size_t)b * SEQ * D_IN_PROJ;
    const int tstart = chunk * CLEN;

    for (int t0 = tstart; t0 < tstart + CLEN; t0 += SCAN_T) {
        __syncthreads();
        for (int idx = tid; idx < SCAN_T * STATE; idx += 128) {
            const int tt = idx >> 7;
            const int n  = idx & 127;
            const size_t rowp = base_conv + (size_t)(t0 + tt) * CONV_DIM;
            Bs[tt][n] = conv[rowp + D_INNER + n];
            Cs[tt][n] = conv[rowp + D_INNER + STATE + n];
        }
        for (int idx = tid; idx < SCAN_T * HEADDIM; idx += 128) {
            const int tt = idx >> 6;
            const int pp = idx & 63;
            xs[tt][pp] = conv[base_conv + (size_t)(t0 + tt) * CONV_DIM + h * HEADDIM + pp];
            zs[tt][pp] = zx[base_z + (size_t)(t0 + tt) * D_IN_PROJ + h * HEADDIM + pp];
        }
        if (tid < SCAN_T)
            dts[tid] = zx[base_z + (size_t)(t0 + tid) * D_IN_PROJ + D_INNER + CONV_DIM + h];
        __syncthreads();

        #pragma unroll 1
        for (int tt = 0; tt < SCAN_T; tt++) {
            const float draw = dts[tt] + dtb;
            const float dtp = (draw > 20.f) ? draw : log1pf(expf(draw));
            const float dA = expf(dtp * Aneg);
            const float xv = xs[tt][p];
            const float k = dtp * xv;
            float y0 = 0.f, y1 = 0.f, y2 = 0.f, y3 = 0.f;
            const float4* Bv = (const float4*)&Bs[tt][n0];
            const float4* Cv = (const float4*)&Cs[tt][n0];
            #pragma unroll
            for (int jj = 0; jj < 16; jj++) {
                const float4 bv = Bv[jj];
                const float4 cv = Cv[jj];
                float* st = &state[jj * 4];
                st[0] = st[0] * dA + k * bv.x; y0 += st[0] * cv.x;
                st[1] = st[1] * dA + k * bv.y; y1 += st[1] * cv.y;
                st[2] = st[2] * dA + k * bv.z; y2 += st[2] * cv.z;
                st[3] = st[3] * dA + k * bv.w; y3 += st[3] * cv.w;
            }
            float y = (y0 + y1) + (y2 + y3);
            y += __shfl_xor_sync(0xffffffffu, y, 1);
            if (half == 0) {
                const float zv = zs[tt][p];
                const float gate = zv / (1.f + expf(-zv));
                const float yo = (y + Dp * xv) * gate;
                yh[((size_t)(b * SEQ + t0 + tt)) * D_INNER + h * HEADDIM + p] =
                    __float2half(yo);
            }
        }
    }
}

// ---------------------------------------------------------------------------
// Launch
// ---------------------------------------------------------------------------
extern "C" void kernel_launch(void* const* d_in, const int* in_sizes, int n_in,
                              void* d_out, int out_size)
{
    const float* hidden     = (const float*)d_in[0];
    const float* residual   = (const float*)d_in[1];
    const float* ssm_norm_w = (const float*)d_in[2];
    const float* mlp_norm_w = (const float*)d_in[3];
    const float* in_proj_w  = (const float*)d_in[4];
    const float* conv_w     = (const float*)d_in[5];
    const float* conv_b     = (const float*)d_in[6];
    const float* dt_bias    = (const float*)d_in[7];
    const float* A_log      = (const float*)d_in[8];
    const float* D_param    = (const float*)d_in[9];
    const float* out_proj_w = (const float*)d_in[10];
    const float* mlp_gate_w = (const float*)d_in[11];
    const float* mlp_up_w   = (const float*)d_in[12];
    const float* mlp_down_w = (const float*)d_in[13];

    float* out_h   = (float*)d_out;
    float* out_res = out_h + (size_t)ROWS * D_MODEL;

    void *p_res1, *p_zx, *p_conv, *p_h2;
    void *p_n, *p_y, *p_a;
    void *p_wi, *p_wo, *p_wm, *p_wd;
    cudaGetSymbolAddress(&p_res1, g_res1);
    cudaGetSymbolAddress(&p_zx,   g_zx);
    cudaGetSymbolAddress(&p_conv, g_conv);
    cudaGetSymbolAddress(&p_h2,   g_h2);
    cudaGetSymbolAddress(&p_n,    g_norm);
    cudaGetSymbolAddress(&p_y,    g_y);
    cudaGetSymbolAddress(&p_a,    g_act);
    cudaGetSymbolAddress(&p_wi,   g_wi);
    cudaGetSymbolAddress(&p_wo,   g_wo);
    cudaGetSymbolAddress(&p_wm,   g_wm);
    cudaGetSymbolAddress(&p_wd,   g_wd);

    cudaFuncSetAttribute(gemm_f16<false>,
                         cudaFuncAttributeMaxDynamicSharedMemorySize, GEMM_SMEM);
    cudaFuncSetAttribute(gemm_f16<true>,
                         cudaFuncAttributeMaxDynamicSharedMemorySize, GEMM_SMEM);

    // Weight conversions (fp16, padding / interleave)
    {
        size_t nr, nt;
        nr = (size_t)D_IN_PROJ * D_MODEL / 4; nt = (size_t)N_INPROJ_PAD * D_MODEL / 4;
        cvt_weight_kernel<<<(unsigned)((nt + 255) / 256), 256>>>(
            in_proj_w, (__half*)p_wi, nr, nt);
        nr = nt = (size_t)D_MODEL * D_INNER / 4;
        cvt_weight_kernel<<<(unsigned)((nt + 255) / 256), 256>>>(
            out_proj_w, (__half*)p_wo, nr, nt);
        nt = (size_t)MLP_2X * D_MODEL / 4;
        cvt_weight_pair_kernel<<<(unsigned)((nt + 255) / 256), 256>>>(
            mlp_gate_w, mlp_up_w, (__half*)p_wm);
        nr = nt = (size_t)D_MODEL * MLP_INNER / 4;
        cvt_weight_kernel<<<(unsigned)((nt + 255) / 256), 256>>>(
            mlp_down_w, (__half*)p_wd, nr, nt);
    }

    // 1) prenorm RMSNorm #1
    rmsnorm_prenorm_kernel<<<ROWS, 256>>>(hidden, residual, ssm_norm_w,
        (float*)p_res1, (__half*)p_n);
    // 2) in_proj
    gemm_f16<false><<<dim3(N_INPROJ_PAD / 256, ROWS / 128), 512, GEMM_SMEM>>>(
        (const __half*)p_n, (const __half*)p_wi,
        (float*)p_zx, nullptr, ROWS, D_IN_PROJ, D_MODEL);
    // 3) causal depthwise conv + SiLU
    conv_silu_kernel<<<(unsigned)(((size_t)ROWS * CONV_DIM + 255) / 256), 256>>>(
        (const float*)p_zx, conv_w, conv_b, (float*)p_conv);
    // 4) chunked selective scan (3 phases)
    scan_local_kernel<<<dim3(NCHUNK, BATCH * NHEADS), 128>>>(
        (const float*)p_conv, (const float*)p_zx, dt_bias, A_log);
    scan_combine_kernel<<<BATCH * NHEADS, 256>>>();
    scan_apply_kernel<<<dim3(NCHUNK, BATCH * NHEADS), 128>>>(
        (const float*)p_conv, (const float*)p_zx, dt_bias, A_log, D_param,
        (__half*)p_y);
    // 5) out_proj
    gemm_f16<false><<<dim3(D_MODEL / 256, ROWS / 128), 512, GEMM_SMEM>>>(
        (const __half*)p_y, (const __half*)p_wo,
        (float*)p_h2, nullptr, ROWS, D_MODEL, D_INNER);
    // 6) prenorm RMSNorm #2
    rmsnorm_prenorm_kernel<<<ROWS, 256>>>((const float*)p_h2, (const float*)p_res1,
        mlp_norm_w, out_res, (__half*)p_n);
    // 7) fused MLP gate+up GEMM with SwiGLU epilogue (interleaved weights)
    gemm_f16<true><<<dim3(MLP_2X / 256, ROWS / 128), 512, GEMM_SMEM>>>(
        (const __half*)p_n, (const __half*)p_wm,
        nullptr, (__half*)p_a, ROWS, MLP_2X, D_MODEL);
    // 8) down projection -> first model output
    gemm_f16<false><<<dim3(D_MODEL / 256, ROWS / 128), 512, GEMM_SMEM>>>(
        (const __half*)p_a, (const __half*)p_wd,
        out_h, nullptr, ROWS, D_MODEL, MLP_INNER);
}

// round 13
// speedup vs baseline: 5.5096x; 1.0705x over previous
#include <cuda_runtime.h>
#include <cuda_bf16.h>
#include <cuda_fp16.h>
#include <math.h>
#include <stdint.h>

// ---------------------------------------------------------------------------
// Problem constants
// ---------------------------------------------------------------------------
#define BATCH     2
#define SEQ       4096
#define ROWS      (BATCH * SEQ)          // 8192 tokens
#define D_MODEL   1024
#define STATE     128
#define HEADDIM   64
#define D_INNER   2048
#define NHEADS    32
#define CONV_DIM  (D_INNER + 2 * STATE)  // 2304
#define D_IN_PROJ (2 * D_INNER + 2 * STATE + NHEADS) // 4384
#define N_INPROJ_PAD 4608                // padded to multiple of 256
#define MLP_INNER 4096
#define MLP_2X    (2 * MLP_INNER)        // interleaved gate/up
#define EPS       1e-5f
#define NCHUNK    32
#define CLEN      128                    // SEQ / NCHUNK

// ---------------------------------------------------------------------------
// Scratch (static device arrays; no runtime allocation allowed)
// ---------------------------------------------------------------------------
__device__ float g_res1  [(size_t)ROWS * D_MODEL];
__device__ float g_zx    [(size_t)ROWS * D_IN_PROJ];
__device__ float g_conv  [(size_t)ROWS * CONV_DIM];
__device__ float g_h2    [(size_t)ROWS * D_MODEL];

__device__ float g_slocal[(size_t)BATCH * NHEADS * NCHUNK * HEADDIM * STATE];
__device__ float g_sin   [(size_t)BATCH * NHEADS * NCHUNK * HEADDIM * STATE];
__device__ float g_cdec  [BATCH * NHEADS * NCHUNK];

__device__ __half g_norm [(size_t)ROWS * D_MODEL];
__device__ __half g_y    [(size_t)ROWS * D_INNER];
__device__ __half g_act  [(size_t)ROWS * MLP_INNER];

__device__ __half g_wi[(size_t)N_INPROJ_PAD * D_MODEL];
__device__ __half g_wo[(size_t)D_MODEL * D_INNER];
__device__ __half g_wm[(size_t)MLP_2X * D_MODEL];   // interleaved gate/up
__device__ __half g_wd[(size_t)D_MODEL * MLP_INNER];

// ---------------------------------------------------------------------------
// PTX helpers (baseline sm_103: cp.async + ldmatrix + mma.sync)
// ---------------------------------------------------------------------------
__device__ __forceinline__ uint32_t smem_u32(const void* p) {
    uint32_t a;
    asm("{ .reg .u64 t; cvta.to.shared.u64 t, %1; cvt.u32.u64 %0, t; }"
        : "=r"(a) : "l"(p));
    return a;
}
__device__ __forceinline__ void cp_async16(uint32_t dst, const void* src) {
    asm volatile("cp.async.cg.shared.global [%0], [%1], 16;\n" :: "r"(dst), "l"(src));
}
__device__ __forceinline__ void cp_commit() {
    asm volatile("cp.async.commit_group;\n" ::: "memory");
}
template <int N>
__device__ __forceinline__ void cp_wait() {
    asm volatile("cp.async.wait_group %0;\n" :: "n"(N) : "memory");
}
__device__ __forceinline__ void ldmx4(uint32_t* r, uint32_t addr) {
    asm volatile("ldmatrix.sync.aligned.m8n8.x4.shared.b16 {%0,%1,%2,%3}, [%4];"
                 : "=r"(r[0]), "=r"(r[1]), "=r"(r[2]), "=r"(r[3]) : "r"(addr));
}
__device__ __forceinline__ void mma_f16(float* c, const uint32_t* a, const uint32_t* b) {
    asm volatile(
        "mma.sync.aligned.m16n8k16.row.col.f32.f16.f16.f32 "
        "{%0,%1,%2,%3}, {%4,%5,%6,%7}, {%8,%9}, {%0,%1,%2,%3};"
        : "+f"(c[0]), "+f"(c[1]), "+f"(c[2]), "+f"(c[3])
        : "r"(a[0]), "r"(a[1]), "r"(a[2]), "r"(a[3]), "r"(b[0]), "r"(b[1]));
}
__device__ __forceinline__ float fast_silu(float x) {
    return __fdividef(x, 1.f + __expf(-x));
}

// ---------------------------------------------------------------------------
// fp16 tensor-core GEMM: C[M,N] = A[M,K] @ W[N,K]^T, fp32 accumulate.
// 128x256 CTA tile, BK=32, 512 threads (16 warps, 32x64 each), 4 stages.
// SMEM row stride 80B -> ldmatrix conflict-free without swizzle.
// SWIGLU=true: N covers interleaved (gate,up) pairs; epilogue emits
//   silu(gate)*up as fp16 into Out with N/2 columns.
// ---------------------------------------------------------------------------
#define GSTAGE   4
#define ROWB     80
#define A_TILE_B (128 * ROWB)            // 10240
#define W_TILE_B (256 * ROWB)            // 20480
#define STAGE_B  (A_TILE_B + W_TILE_B)   // 30720
#define GEMM_SMEM (GSTAGE * STAGE_B)     // 122880

__device__ __forceinline__ void load_stage_g(
    uint32_t sbase,
    const __half* __restrict__ A, const __half* __restrict__ W,
    int bm, int bn, int K, int kc, int tid)
{
    const int koff = kc * 32;
    {
        const int row = tid >> 2, ch = tid & 3;
        const uint32_t d = (uint32_t)(row * ROWB + ch * 16);
        cp_async16(sbase + d, A + (size_t)(bm + row) * K + koff + ch * 8);
    }
    #pragma unroll
    for (int i = 0; i < 2; i++) {
        const int slot = tid + i * 512;
        const int row = slot >> 2, ch = slot & 3;
        const uint32_t d = (uint32_t)(row * ROWB + ch * 16);
        cp_async16(sbase + A_TILE_B + d, W + (size_t)(bn + row) * K + koff + ch * 8);
    }
}

template <bool SWIGLU>
__global__ __launch_bounds__(512, 1)
void gemm_f16(const __half* __restrict__ A,
              const __half* __restrict__ W,
              float* __restrict__ C,
              __half* __restrict__ Out,
              int M, int N, int K)
{
    extern __shared__ __align__(128) char dynsmem[];
    const uint32_t sbase = smem_u32(dynsmem);

    const int tid  = threadIdx.x;
    const int lane = tid & 31;
    const int wid  = tid >> 5;
    const int wm   = wid & 3;             // 4 m-groups of 32 rows
    const int wn   = wid >> 2;            // 4 n-groups of 64 cols
    const int bm   = blockIdx.y * 128;
    const int bn   = blockIdx.x * 256;

    const uint32_t a_off = (uint32_t)((wm * 32 + (lane & 15)) * ROWB
                                      + ((lane >> 4) & 1) * 16);
    const uint32_t b_off = (uint32_t)((wn * 64 + ((lane >> 4) & 1) * 8 + (lane & 7)) * ROWB
                                      + ((lane >> 3) & 1) * 16);

    float acc[2][8][4];
    #pragma unroll
    for (int i = 0; i < 2; i++)
        #pragma unroll
        for (int j = 0; j < 8; j++)
            #pragma unroll
            for (int q = 0; q < 4; q++) acc[i][j][q] = 0.f;

    const int nk = K >> 5;

    load_stage_g(sbase + 0 * STAGE_B, A, W, bm, bn, K, 0, tid);
    cp_commit();
    load_stage_g(sbase + 1 * STAGE_B, A, W, bm, bn, K, 1, tid);
    cp_commit();
    load_stage_g(sbase + 2 * STAGE_B, A, W, bm, bn, K, 2, tid);
    cp_commit();

    for (int k = 0; k < nk; k++) {
        const uint32_t stb = sbase + (uint32_t)(k % GSTAGE) * STAGE_B;
        cp_wait<2>();
        __syncthreads();

        const int kn = k + 3;
        if (kn < nk)
            load_stage_g(sbase + (uint32_t)(kn % GSTAGE) * STAGE_B,
                         A, W, bm, bn, K, kn, tid);
        cp_commit();

        const uint32_t a_b = stb + a_off;
        const uint32_t b_b = stb + A_TILE_B + b_off;

        #pragma unroll
        for (int s = 0; s < 2; s++) {
            const uint32_t kb = (uint32_t)(s * 32);
            uint32_t af[2][4];
            #pragma unroll
            for (int i = 0; i < 2; i++)
                ldmx4(af[i], a_b + (uint32_t)(i * 16 * ROWB) + kb);
            #pragma unroll
            for (int jp = 0; jp < 4; jp++) {
                uint32_t wf[4];
                ldmx4(wf, b_b + (uint32_t)(jp * 16 * ROWB) + kb);
                #pragma unroll
                for (int i = 0; i < 2; i++)
                    #pragma unroll
                    for (int f = 0; f < 2; f++)
                        mma_f16(acc[i][jp * 2 + f], af[i], wf + f * 2);
            }
        }
    }

    if (!SWIGLU) {
        #pragma unroll
        for (int i = 0; i < 2; i++) {
            const int row = bm + wm * 32 + i * 16 + (lane >> 2);
            #pragma unroll
            for (int j = 0; j < 8; j++) {
                const int col = bn + wn * 64 + j * 8 + (lane & 3) * 2;
                if (col < N) {
                    *(float2*)&C[(size_t)row * N + col] =
                        make_float2(acc[i][j][0], acc[i][j][1]);
                    *(float2*)&C[(size_t)(row + 8) * N + col] =
                        make_float2(acc[i][j][2], acc[i][j][3]);
                }
            }
        }
    } else {
        // Columns are interleaved (gate, up) pairs: acc[..][0]=gate, [1]=up
        // (and [2],[3] for row+8). Output column index = col/2, width N/2.
        const int NO = N >> 1;
        #pragma unroll
        for (int i = 0; i < 2; i++) {
            const int row = bm + wm * 32 + i * 16 + (lane >> 2);
            #pragma unroll
            for (int j = 0; j < 8; j++) {
                const int colc = (bn + wn * 64 + j * 8 + (lane & 3) * 2) >> 1;
                {
                    const float v = fast_silu(acc[i][j][0]) * acc[i][j][1];
                    Out[(size_t)row * NO + colc] = __float2half(v);
                }
                {
                    const float v = fast_silu(acc[i][j][2]) * acc[i][j][3];
                    Out[(size_t)(row + 8) * NO + colc] = __float2half(v);
                }
            }
        }
    }
}

// ---------------------------------------------------------------------------
// fp16 helpers
// ---------------------------------------------------------------------------
__device__ __forceinline__ void store_h4(__half* __restrict__ p, size_t off, float4 v) {
    __half2 a; a.x = __float2half(v.x); a.y = __float2half(v.y);
    __half2 b; b.x = __float2half(v.z); b.y = __float2half(v.w);
    *(__half2*)(p + off)     = a;
    *(__half2*)(p + off + 2) = b;
}

// Weight fp32 -> fp16, float4-vectorized, zero tail padding.
__global__ __launch_bounds__(256) void cvt_weight_kernel(
    const float* __restrict__ w, __half* __restrict__ out,
    size_t n_real4, size_t n_total4)
{
    const size_t i = (size_t)blockIdx.x * 256 + threadIdx.x;
    if (i >= n_total4) return;
    float4 v = (i < n_real4) ? ((const float4*)w)[i]
                             : make_float4(0.f, 0.f, 0.f, 0.f);
    store_h4(out, i * 4, v);
}

// gate/up weights -> row-interleaved fp16: row 2j = gate_j, 2j+1 = up_j.
#define K4 (D_MODEL / 4)
__global__ __launch_bounds__(256) void cvt_weight_pair_kernel(
    const float* __restrict__ wg, const float* __restrict__ wu,
    __half* __restrict__ out)
{
    const size_t i = (size_t)blockIdx.x * 256 + threadIdx.x;   // float4 index
    if (i >= (size_t)MLP_2X * K4) return;
    const size_t n = i / K4;          // interleaved row
    const size_t k4 = i % K4;
    const size_t srow = n >> 1;
    const float4 v = (n & 1) ? ((const float4*)wu)[srow * K4 + k4]
                             : ((const float4*)wg)[srow * K4 + k4];
    store_h4(out, i * 4, v);
}

// ---------------------------------------------------------------------------
// Fused residual-add + RMSNorm; norm output as fp16.
// ---------------------------------------------------------------------------
__global__ __launch_bounds__(256) void rmsnorm_prenorm_kernel(
    const float* __restrict__ x, const float* __restrict__ res_in,
    const float* __restrict__ w, float* __restrict__ res_out,
    __half* __restrict__ nh)
{
    const size_t row = blockIdx.x;
    const int tid = threadIdx.x;
    const float4 xv = ((const float4*)(x      + row * D_MODEL))[tid];
    const float4 rv = ((const float4*)(res_in + row * D_MODEL))[tid];
    float4 s;
    s.x = xv.x + rv.x; s.y = xv.y + rv.y; s.z = xv.z + rv.z; s.w = xv.w + rv.w;
    float ss = s.x * s.x + s.y * s.y + s.z * s.z + s.w * s.w;

    #pragma unroll
    for (int o = 16; o > 0; o >>= 1) ss += __shfl_down_sync(0xffffffffu, ss, o);
    __shared__ float red[8];
    __shared__ float scale_sh;
    if ((tid & 31) == 0) red[tid >> 5] = ss;
    __syncthreads();
    if (tid == 0) {
        float t = 0.f;
        #pragma unroll
        for (int i = 0; i < 8; i++) t += red[i];
        scale_sh = rsqrtf(t / (float)D_MODEL + EPS);
    }
    __syncthreads();
    const float scale = scale_sh;

    ((float4*)(res_out + row * D_MODEL))[tid] = s;
    const float4 wv = ((const float4*)w)[tid];
    float4 o;
    o.x = s.x * scale * wv.x; o.y = s.y * scale * wv.y;
    o.z = s.z * scale * wv.z; o.w = s.w * scale * wv.w;
    store_h4(nh, row * D_MODEL + (size_t)tid * 4, o);
}

// ---------------------------------------------------------------------------
// Causal depthwise conv1d (width 4) + SiLU over the xBC slice of zxbcdt.
// ---------------------------------------------------------------------------
__global__ __launch_bounds__(256) void conv_silu_kernel(
    const float* __restrict__ zx, const float* __restrict__ cw,
    const float* __restrict__ cb, float* __restrict__ out)
{
    const size_t id = (size_t)blockIdx.x * 256 + threadIdx.x;
    if (id >= (size_t)ROWS * CONV_DIM) return;
    const int c = (int)(id % CONV_DIM);
    const size_t r = id / CONV_DIM;
    const int l = (int)(r & (SEQ - 1));
    const float* base = zx + r * D_IN_PROJ + D_INNER + c;

    const float w0 = cw[c * 4 + 0], w1 = cw[c * 4 + 1];
    const float w2 = cw[c * 4 + 2], w3 = cw[c * 4 + 3];
    float acc = cb[c];
    if (l >= 3) acc += base[-3L * D_IN_PROJ] * w0;
    if (l >= 2) acc += base[-2L * D_IN_PROJ] * w1;
    if (l >= 1) acc += base[-1L * D_IN_PROJ] * w2;
    acc += base[0] * w3;
    out[id] = fast_silu(acc);
}

// ---------------------------------------------------------------------------
// Chunked selective scan. Phase 1: per-chunk local scan (zero init state),
// writes final local state + chunk decay product. Grid: (NCHUNK, B*H).
// dtp/dA computed ONCE per timestep (in shared), not per thread.
// ---------------------------------------------------------------------------
#define SCAN_T 8
__global__ __launch_bounds__(128) void scan_local_kernel(
    const float* __restrict__ conv, const float* __restrict__ zx,
    const float* __restrict__ dt_bias, const float* __restrict__ A_log)
{
    const int chunk = blockIdx.x;
    const int bh = blockIdx.y;
    const int b = bh >> 5;
    const int h = bh & 31;
    const int tid = threadIdx.x;
    const int p = tid >> 1;
    const int half = tid & 1;
    const int n0 = half * 64;

    __shared__ float Bs[SCAN_T][STATE];
    __shared__ float xs[SCAN_T][HEADDIM];
    __shared__ float dtps[SCAN_T];
    __shared__ float dAs[SCAN_T];

    float state[64];
    #pragma unroll
    for (int j = 0; j < 64; j++) state[j] = 0.f;
    float cdec = 1.f;

    const float Aneg = -__expf(A_log[h]);
    const float dtb  = dt_bias[h];
    const size_t base_conv = (size_t)b * SEQ * CONV_DIM;
    const size_t base_z    = (size_t)b * SEQ * D_IN_PROJ;
    const int tstart = chunk * CLEN;

    for (int t0 = tstart; t0 < tstart + CLEN; t0 += SCAN_T) {
        __syncthreads();
        for (int idx = tid; idx < SCAN_T * STATE; idx += 128) {
            const int tt = idx >> 7;
            const int n  = idx & 127;
            Bs[tt][n] = conv[base_conv + (size_t)(t0 + tt) * CONV_DIM + D_INNER + n];
        }
        for (int idx = tid; idx < SCAN_T * HEADDIM; idx += 128) {
            const int tt = idx >> 6;
            const int pp = idx & 63;
            xs[tt][pp] = conv[base_conv + (size_t)(t0 + tt) * CONV_DIM + h * HEADDIM + pp];
        }
        if (tid < SCAN_T) {
            const float draw = zx[base_z + (size_t)(t0 + tid) * D_IN_PROJ
                                  + D_INNER + CONV_DIM + h] + dtb;
            const float dtp = (draw > 20.f) ? draw : log1pf(__expf(draw));
            dtps[tid] = dtp;
            dAs[tid]  = __expf(dtp * Aneg);
        }
        __syncthreads();

        #pragma unroll 1
        for (int tt = 0; tt < SCAN_T; tt++) {
            const float dA = dAs[tt];
            cdec *= dA;
            const float k = dtps[tt] * xs[tt][p];
            const float4* Bv = (const float4*)&Bs[tt][n0];
            #pragma unroll
            for (int jj = 0; jj < 16; jj++) {
                const float4 bv = Bv[jj];
                float* st = &state[jj * 4];
                st[0] = st[0] * dA + k * bv.x;
                st[1] = st[1] * dA + k * bv.y;
                st[2] = st[2] * dA + k * bv.z;
                st[3] = st[3] * dA + k * bv.w;
            }
        }
    }

    float* dst = g_slocal + ((size_t)(bh * NCHUNK + chunk) * HEADDIM + p) * STATE + n0;
    #pragma unroll
    for (int jj = 0; jj < 16; jj++)
        ((float4*)dst)[jj] = make_float4(state[jj * 4], state[jj * 4 + 1],
                                         state[jj * 4 + 2], state[jj * 4 + 3]);
    if (tid == 0) g_cdec[bh * NCHUNK + chunk] = cdec;
}

// Phase 2: sequential chunk combine (scalar decay per chunk).
// Grid: (B*H, 8 slices) = 512 CTAs; each thread carries 4 elements.
__global__ __launch_bounds__(256) void scan_combine_kernel()
{
    const int bh = blockIdx.x;
    const int slice = blockIdx.y;                 // 0..7
    const int tid = threadIdx.x;
    const int e0 = slice * 1024 + tid;            // element base; +256*j
    float s[4];
    #pragma unroll
    for (int j = 0; j < 4; j++) s[j] = 0.f;

    for (int c = 0; c < NCHUNK; c++) {
        float* dst = g_sin + (size_t)(bh * NCHUNK + c) * (HEADDIM * STATE);
        if (c > 0) {
            const float D = g_cdec[bh * NCHUNK + c - 1];
            const float* src = g_slocal + (size_t)(bh * NCHUNK + c - 1) * (HEADDIM * STATE);
            #pragma unroll
            for (int j = 0; j < 4; j++)
                s[j] = D * s[j] + src[e0 + j * 256];
        }
        #pragma unroll
        for (int j = 0; j < 4; j++)
            dst[e0 + j * 256] = s[j];
    }
}

// Phase 3: per-chunk scan with proper initial state; emits gated y (fp16).
__global__ __launch_bounds__(128) void scan_apply_kernel(
    const float* __restrict__ conv, const float* __restrict__ zx,
    const float* __restrict__ dt_bias, const float* __restrict__ A_log,
    const float* __restrict__ D_param,
    __half* __restrict__ yh)
{
    const int chunk = blockIdx.x;
    const int bh = blockIdx.y;
    const int b = bh >> 5;
    const int h = bh & 31;
    const int tid = threadIdx.x;
    const int p = tid >> 1;
    const int half = tid & 1;
    const int n0 = half * 64;

    __shared__ float Bs[SCAN_T][STATE];
    __shared__ float Cs[SCAN_T][STATE];
    __shared__ float xs[SCAN_T][HEADDIM];
    __shared__ float zs[SCAN_T][HEADDIM];
    __shared__ float dtps[SCAN_T];
    __shared__ float dAs[SCAN_T];

    float state[64];
    {
        const float* src = g_sin + ((size_t)(bh * NCHUNK + chunk) * HEADDIM + p) * STATE + n0;
        #pragma unroll
        for (int jj = 0; jj < 16; jj++) {
            const float4 v = ((const float4*)src)[jj];
            state[jj * 4] = v.x; state[jj * 4 + 1] = v.y;
            state[jj * 4 + 2] = v.z; state[jj * 4 + 3] = v.w;
        }
    }

    const float Aneg = -__expf(A_log[h]);
    const float dtb  = dt_bias[h];
    const float Dp   = D_param[h];
    const size_t base_conv = (size_t)b * SEQ * CONV_DIM;
    const size_t base_z    = (size_t)b * SEQ * D_IN_PROJ;
    const int tstart = chunk * CLEN;

    for (int t0 = tstart; t0 < tstart + CLEN; t0 += SCAN_T) {
        __syncthreads();
        for (int idx = tid; idx < SCAN_T * STATE; idx += 128) {
            const int tt = idx >> 7;
            const int n  = idx & 127;
            const size_t rowp = base_conv + (size_t)(t0 + tt) * CONV_DIM;
            Bs[tt][n] = conv[rowp + D_INNER + n];
            Cs[tt][n] = conv[rowp + D_INNER + STATE + n];
        }
        for (int idx = tid; idx < SCAN_T * HEADDIM; idx += 128) {
            const int tt = idx >> 6;
            const int pp = idx & 63;
            xs[tt][pp] = conv[base_conv + (size_t)(t0 + tt) * CONV_DIM + h * HEADDIM + pp];
            zs[tt][pp] = zx[base_z + (size_t)(t0 + tt) * D_IN_PROJ + h * HEADDIM + pp];
        }
        if (tid < SCAN_T) {
            const float draw = zx[base_z + (size_t)(t0 + tid) * D_IN_PROJ
                                  + D_INNER + CONV_DIM + h] + dtb;
            const float dtp = (draw > 20.f) ? draw : log1pf(__expf(draw));
            dtps[tid] = dtp;
            dAs[tid]  = __expf(dtp * Aneg);
        }
        __syncthreads();

        #pragma unroll 1
        for (int tt = 0; tt < SCAN_T; tt++) {
            const float dA = dAs[tt];
            const float xv = xs[tt][p];
            const float k = dtps[tt] * xv;
            float y0 = 0.f, y1 = 0.f, y2 = 0.f, y3 = 0.f;
            const float4* Bv = (const float4*)&Bs[tt][n0];
            const float4* Cv = (const float4*)&Cs[tt][n0];
            #pragma unroll
            for (int jj = 0; jj < 16; jj++) {
                const float4 bv = Bv[jj];
                const float4 cv = Cv[jj];
                float* st = &state[jj * 4];
                st[0] = st[0] * dA + k * bv.x; y0 += st[0] * cv.x;
                st[1] = st[1] * dA + k * bv.y; y1 += st[1] * cv.y;
                st[2] = st[2] * dA + k * bv.z; y2 += st[2] * cv.z;
                st[3] = st[3] * dA + k * bv.w; y3 += st[3] * cv.w;
            }
            float y = (y0 + y1) + (y2 + y3);
            y += __shfl_xor_sync(0xffffffffu, y, 1);
            if (half == 0) {
                const float gate = fast_silu(zs[tt][p]);
                const float yo = (y + Dp * xv) * gate;
                yh[((size_t)(b * SEQ + t0 + tt)) * D_INNER + h * HEADDIM + p] =
                    __float2half(yo);
            }
        }
    }
}

// ---------------------------------------------------------------------------
// Launch
// ---------------------------------------------------------------------------
extern "C" void kernel_launch(void* const* d_in, const int* in_sizes, int n_in,
                              void* d_out, int out_size)
{
    const float* hidden     = (const float*)d_in[0];
    const float* residual   = (const float*)d_in[1];
    const float* ssm_norm_w = (const float*)d_in[2];
    const float* mlp_norm_w = (const float*)d_in[3];
    const float* in_proj_w  = (const float*)d_in[4];
    const float* conv_w     = (const float*)d_in[5];
    const float* conv_b     = (const float*)d_in[6];
    const float* dt_bias    = (const float*)d_in[7];
    const float* A_log      = (const float*)d_in[8];
    const float* D_param    = (const float*)d_in[9];
    const float* out_proj_w = (const float*)d_in[10];
    const float* mlp_gate_w = (const float*)d_in[11];
    const float* mlp_up_w   = (const float*)d_in[12];
    const float* mlp_down_w = (const float*)d_in[13];

    float* out_h   = (float*)d_out;
    float* out_res = out_h + (size_t)ROWS * D_MODEL;

    void *p_res1, *p_zx, *p_conv, *p_h2;
    void *p_n, *p_y, *p_a;
    void *p_wi, *p_wo, *p_wm, *p_wd;
    cudaGetSymbolAddress(&p_res1, g_res1);
    cudaGetSymbolAddress(&p_zx,   g_zx);
    cudaGetSymbolAddress(&p_conv, g_conv);
    cudaGetSymbolAddress(&p_h2,   g_h2);
    cudaGetSymbolAddress(&p_n,    g_norm);
    cudaGetSymbolAddress(&p_y,    g_y);
    cudaGetSymbolAddress(&p_a,    g_act);
    cudaGetSymbolAddress(&p_wi,   g_wi);
    cudaGetSymbolAddress(&p_wo,   g_wo);
    cudaGetSymbolAddress(&p_wm,   g_wm);
    cudaGetSymbolAddress(&p_wd,   g_wd);

    cudaFuncSetAttribute(gemm_f16<false>,
                         cudaFuncAttributeMaxDynamicSharedMemorySize, GEMM_SMEM);
    cudaFuncSetAttribute(gemm_f16<true>,
                         cudaFuncAttributeMaxDynamicSharedMemorySize, GEMM_SMEM);

    // Weight conversions (fp16, padding / interleave)
    {
        size_t nr, nt;
        nr = (size_t)D_IN_PROJ * D_MODEL / 4; nt = (size_t)N_INPROJ_PAD * D_MODEL / 4;
        cvt_weight_kernel<<<(unsigned)((nt + 255) / 256), 256>>>(
            in_proj_w, (__half*)p_wi, nr, nt);
        nr = nt = (size_t)D_MODEL * D_INNER / 4;
        cvt_weight_kernel<<<(unsigned)((nt + 255) / 256), 256>>>(
            out_proj_w, (__half*)p_wo, nr, nt);
        nt = (size_t)MLP_2X * D_MODEL / 4;
        cvt_weight_pair_kernel<<<(unsigned)((nt + 255) / 256), 256>>>(
            mlp_gate_w, mlp_up_w, (__half*)p_wm);
        nr = nt = (size_t)D_MODEL * MLP_INNER / 4;
        cvt_weight_kernel<<<(unsigned)((nt + 255) / 256), 256>>>(
            mlp_down_w, (__half*)p_wd, nr, nt);
    }

    // 1) prenorm RMSNorm #1
    rmsnorm_prenorm_kernel<<<ROWS, 256>>>(hidden, residual, ssm_norm_w,
        (float*)p_res1, (__half*)p_n);
    // 2) in_proj
    gemm_f16<false><<<dim3(N_INPROJ_PAD / 256, ROWS / 128), 512, GEMM_SMEM>>>(
        (const __half*)p_n, (const __half*)p_wi,
        (float*)p_zx, nullptr, ROWS, D_IN_PROJ, D_MODEL);
    // 3) causal depthwise conv + SiLU
    conv_silu_kernel<<<(unsigned)(((size_t)ROWS * CONV_DIM + 255) / 256), 256>>>(
        (const float*)p_zx, conv_w, conv_b, (float*)p_conv);
    // 4) chunked selective scan (3 phases)
    scan_local_kernel<<<dim3(NCHUNK, BATCH * NHEADS), 128>>>(
        (const float*)p_conv, (const float*)p_zx, dt_bias, A_log);
    scan_combine_kernel<<<dim3(BATCH * NHEADS, 8), 256>>>();
    scan_apply_kernel<<<dim3(NCHUNK, BATCH * NHEADS), 128>>>(
        (const float*)p_conv, (const float*)p_zx, dt_bias, A_log, D_param,
        (__half*)p_y);
    // 5) out_proj
    gemm_f16<false><<<dim3(D_MODEL / 256, ROWS / 128), 512, GEMM_SMEM>>>(
        (const __half*)p_y, (const __half*)p_wo,
        (float*)p_h2, nullptr, ROWS, D_MODEL, D_INNER);
    // 6) prenorm RMSNorm #2
    rmsnorm_prenorm_kernel<<<ROWS, 256>>>((const float*)p_h2, (const float*)p_res1,
        mlp_norm_w, out_res, (__half*)p_n);
    // 7) fused MLP gate+up GEMM with SwiGLU epilogue (interleaved weights)
    gemm_f16<true><<<dim3(MLP_2X / 256, ROWS / 128), 512, GEMM_SMEM>>>(
        (const __half*)p_n, (const __half*)p_wm,
        nullptr, (__half*)p_a, ROWS, MLP_2X, D_MODEL);
    // 8) down projection -> first model output
    gemm_f16<false><<<dim3(D_MODEL / 256, ROWS / 128), 512, GEMM_SMEM>>>(
        (const __half*)p_a, (const __half*)p_wd,
        out_h, nullptr, ROWS, D_MODEL, MLP_INNER);
}